// round 1
// baseline (speedup 1.0000x reference)
#include <cuda_runtime.h>

// RecurrentHedgeModel: B=1048576, STEPS=30, INPUT_DIM=1, HIDDEN=32
// Strategy (round 1): 2 batch elements per thread, packed fp32x2 (Blackwell
// FFMA2 via PTX fma.rn.f32x2). Weights duplicated (w,w) in SMEM so every
// packed FMA needs no repacking; all weight reads are warp-uniform broadcasts.

#define STEPS   30
#define HID     32
#define ROWLEN  34      // x = [s, delta_prev, h(32)]
#define BTOTAL  1048576
#define TPB     128

typedef unsigned long long pk_t;   // packed (f32 lo, f32 hi)

static __device__ __forceinline__ pk_t pk_pack(float lo, float hi) {
    pk_t r; asm("mov.b64 %0, {%1, %2};" : "=l"(r) : "f"(lo), "f"(hi)); return r;
}
static __device__ __forceinline__ void pk_unpack(pk_t v, float& lo, float& hi) {
    asm("mov.b64 {%0, %1}, %2;" : "=f"(lo), "=f"(hi) : "l"(v));
}
static __device__ __forceinline__ pk_t pk_fma(pk_t a, pk_t b, pk_t c) {
    pk_t d; asm("fma.rn.f32x2 %0, %1, %2, %3;" : "=l"(d) : "l"(a), "l"(b), "l"(c)); return d;
}
static __device__ __forceinline__ pk_t pk_add(pk_t a, pk_t b) {
    pk_t d; asm("add.rn.f32x2 %0, %1, %2;" : "=l"(d) : "l"(a), "l"(b)); return d;
}

// tanh via e^{-2|x|}: u in (0,1], no overflow anywhere. EX2 + RCP (2 MUFU).
static __device__ __forceinline__ float tanh_fast(float x) {
    float ax = fabsf(x);
    float u  = __expf(-2.0f * ax);
    float t  = __fdividef(1.0f - u, 1.0f + u);
    return copysignf(t, x);
}
static __device__ __forceinline__ float sigmoid_fast(float x) {
    // sigma(x) = 0.5 * (1 + tanh(x/2))  (exact identity)
    return fmaf(tanh_fast(0.5f * x), 0.5f, 0.5f);
}

// SMEM: duplicated-pair weights + biases
//   sWx  : 128 rows x 34  (rows 0..31 = W1, rows 32..127 = Wih[r,z,n])
//   sWhh : 96 rows  x 32
static constexpr int SMEM_BYTES =
    (128 * ROWLEN + 96 * HID + 32 + 96 + 96) * 8 + 32 * 4;

__global__ __launch_bounds__(TPB, 3)
void hedge_kernel(const float* __restrict__ S,
                  const float* __restrict__ W1,  const float* __restrict__ b1,
                  const float* __restrict__ W2,  const float* __restrict__ b2,
                  const float* __restrict__ Wih, const float* __restrict__ bih,
                  const float* __restrict__ Whh, const float* __restrict__ bhh,
                  float* __restrict__ out)
{
    extern __shared__ unsigned char smem_raw[];
    pk_t*  sWx  = (pk_t*)smem_raw;              // 128*34
    pk_t*  sWhh = sWx  + 128 * ROWLEN;          // 96*32
    pk_t*  sB1  = sWhh + 96 * HID;              // 32
    pk_t*  sBih = sB1  + 32;                    // 96
    pk_t*  sBhh = sBih + 96;                    // 96
    float* sW2  = (float*)(sBhh + 96);          // 32

    const int tid = threadIdx.x;
    for (int i = tid; i < 128 * ROWLEN; i += TPB) {
        int r = i / ROWLEN, c = i - r * ROWLEN;
        float w = (r < 32) ? W1[r * ROWLEN + c] : Wih[(r - 32) * ROWLEN + c];
        sWx[i] = pk_pack(w, w);
    }
    for (int i = tid; i < 96 * HID; i += TPB) { float w = Whh[i]; sWhh[i] = pk_pack(w, w); }
    for (int i = tid; i < 32; i += TPB) { sB1[i] = pk_pack(b1[i], b1[i]); sW2[i] = W2[i]; }
    for (int i = tid; i < 96; i += TPB) {
        sBih[i] = pk_pack(bih[i], bih[i]);
        sBhh[i] = pk_pack(bhh[i], bhh[i]);
    }
    __syncthreads();

    const float b2v = __ldg(b2);
    const int g = blockIdx.x * TPB + tid;                 // 0 .. B/2-1
    const float* S0 = S + (size_t)(2 * g) * (STEPS + 1);  // rows 2g and 2g+1
    float* out0 = out + (size_t)(2 * g) * STEPS;

    pk_t h[HID];
    #pragma unroll
    for (int k = 0; k < HID; k++) h[k] = 0ull;
    pk_t delta = 0ull;
    const pk_t PKZERO = 0ull;

    float sn0 = S0[0], sn1 = S0[STEPS + 1];

    #pragma unroll 1
    for (int t = 0; t < STEPS; t++) {
        pk_t s = pk_pack(sn0, sn1);
        if (t + 1 < STEPS) { sn0 = S0[t + 1]; sn1 = S0[STEPS + 1 + t + 1]; }

        // ---------------- MLP: delta_new = relu(x@W1^T + b1)@W2^T + b2 ----
        float d0 = b2v, d1 = b2v;
        #pragma unroll 4
        for (int j = 0; j < 32; j++) {
            const pk_t* row = sWx + j * ROWLEN;
            pk_t a0 = pk_fma(row[0], s,     sB1[j]);
            pk_t a1 = pk_fma(row[1], delta, PKZERO);
            #pragma unroll
            for (int k = 0; k < HID; k += 2) {
                a0 = pk_fma(row[2 + k], h[k],     a0);
                a1 = pk_fma(row[3 + k], h[k + 1], a1);
            }
            float x0, x1; pk_unpack(pk_add(a0, a1), x0, x1);
            float w2 = sW2[j];
            d0 = fmaf(fmaxf(x0, 0.0f), w2, d0);
            d1 = fmaf(fmaxf(x1, 0.0f), w2, d1);
        }

        // ---------------- GRU (torch gate order r,z,n) --------------------
        pk_t hn[HID];
        #pragma unroll
        for (int j = 0; j < 32; j++) {
            // r gate: Wih row j (= sWx row 32+j), Whh row j
            {
            }
            const pk_t* xr = sWx  + (32 + j) * ROWLEN;
            const pk_t* hr = sWhh + j * HID;
            pk_t r0 = pk_fma(xr[0], s,     sBih[j]);
            pk_t r1 = pk_fma(xr[1], delta, sBhh[j]);
            #pragma unroll
            for (int k = 0; k < HID; k += 2) {
                r0 = pk_fma(xr[2 + k], h[k],     r0);
                r1 = pk_fma(xr[3 + k], h[k + 1], r1);
                r0 = pk_fma(hr[k],     h[k],     r0);
                r1 = pk_fma(hr[k + 1], h[k + 1], r1);
            }
            float rp0, rp1; pk_unpack(pk_add(r0, r1), rp0, rp1);

            // z gate: Wih row 32+j (= sWx row 64+j), Whh row 32+j
            const pk_t* xz = sWx  + (64 + j) * ROWLEN;
            const pk_t* hz = sWhh + (32 + j) * HID;
            pk_t z0 = pk_fma(xz[0], s,     sBih[32 + j]);
            pk_t z1 = pk_fma(xz[1], delta, sBhh[32 + j]);
            #pragma unroll
            for (int k = 0; k < HID; k += 2) {
                z0 = pk_fma(xz[2 + k], h[k],     z0);
                z1 = pk_fma(xz[3 + k], h[k + 1], z1);
                z0 = pk_fma(hz[k],     h[k],     z0);
                z1 = pk_fma(hz[k + 1], h[k + 1], z1);
            }
            float zp0, zp1; pk_unpack(pk_add(z0, z1), zp0, zp1);

            // n gate: i_n and h_n kept separate (n = tanh(i_n + r*h_n))
            const pk_t* xn  = sWx  + (96 + j) * ROWLEN;
            const pk_t* hnw = sWhh + (64 + j) * HID;
            pk_t in0 = pk_fma(xn[0], s,     sBih[64 + j]);
            pk_t in1 = pk_fma(xn[1], delta, PKZERO);
            pk_t hh0 = sBhh[64 + j];
            pk_t hh1 = PKZERO;
            #pragma unroll
            for (int k = 0; k < HID; k += 2) {
                in0 = pk_fma(xn[2 + k],  h[k],     in0);
                in1 = pk_fma(xn[3 + k],  h[k + 1], in1);
                hh0 = pk_fma(hnw[k],     h[k],     hh0);
                hh1 = pk_fma(hnw[k + 1], h[k + 1], hh1);
            }
            float inp0, inp1, hhp0, hhp1;
            pk_unpack(pk_add(in0, in1), inp0, inp1);
            pk_unpack(pk_add(hh0, hh1), hhp0, hhp1);

            float hc0, hc1; pk_unpack(h[j], hc0, hc1);
            float rg0 = sigmoid_fast(rp0), rg1 = sigmoid_fast(rp1);
            float zg0 = sigmoid_fast(zp0), zg1 = sigmoid_fast(zp1);
            float n0  = tanh_fast(fmaf(rg0, hhp0, inp0));
            float n1  = tanh_fast(fmaf(rg1, hhp1, inp1));
            // h' = (1-z)*n + z*h = n + z*(h-n)
            float o0 = fmaf(zg0, hc0 - n0, n0);
            float o1 = fmaf(zg1, hc1 - n1, n1);
            hn[j] = pk_pack(o0, o1);
        }

        #pragma unroll
        for (int k = 0; k < HID; k++) h[k] = hn[k];

        out0[t]         = d0;
        out0[STEPS + t] = d1;
        delta = pk_pack(d0, d1);
    }
}

extern "C" void kernel_launch(void* const* d_in, const int* in_sizes, int n_in,
                              void* d_out, int out_size)
{
    (void)in_sizes; (void)n_in; (void)out_size;
    const float* S   = (const float*)d_in[0];
    const float* W1  = (const float*)d_in[1];
    const float* b1  = (const float*)d_in[2];
    const float* W2  = (const float*)d_in[3];
    const float* b2  = (const float*)d_in[4];
    const float* Wih = (const float*)d_in[5];
    const float* bih = (const float*)d_in[6];
    const float* Whh = (const float*)d_in[7];
    const float* bhh = (const float*)d_in[8];
    float* out = (float*)d_out;

    cudaFuncSetAttribute(hedge_kernel,
                         cudaFuncAttributeMaxDynamicSharedMemorySize, SMEM_BYTES);

    const int nthreads = BTOTAL / 2;          // 2 elements per thread
    dim3 grid(nthreads / TPB);                // 4096 blocks
    hedge_kernel<<<grid, TPB, SMEM_BYTES>>>(S, W1, b1, W2, b2,
                                            Wih, bih, Whh, bhh, out);
}

// round 2
// speedup vs baseline: 1.2512x; 1.2512x over previous
#include <cuda_runtime.h>

// RecurrentHedgeModel: B=1048576, STEPS=30, INPUT_DIM=1, HIDDEN=32
// Round 2: LDS.128 weight fetch — each 16B broadcast shared load carries TWO
// duplicated (w,w) fp32x2 weights, feeding two FFMA2s. Halves the L1/LDS
// instruction stream that round-1 ncu showed as the binding pipe (79%).

#define STEPS   30
#define HID     32
#define ROWLEN  34      // x = [s, delta_prev, h(32)]
#define BTOTAL  1048576
#define TPB     128

typedef unsigned long long pk_t;   // packed (f32 lo, f32 hi)

static __device__ __forceinline__ pk_t pk_pack(float lo, float hi) {
    pk_t r; asm("mov.b64 %0, {%1, %2};" : "=l"(r) : "f"(lo), "f"(hi)); return r;
}
static __device__ __forceinline__ void pk_unpack(pk_t v, float& lo, float& hi) {
    asm("mov.b64 {%0, %1}, %2;" : "=f"(lo), "=f"(hi) : "l"(v));
}
static __device__ __forceinline__ pk_t pk_fma(pk_t a, pk_t b, pk_t c) {
    pk_t d; asm("fma.rn.f32x2 %0, %1, %2, %3;" : "=l"(d) : "l"(a), "l"(b), "l"(c)); return d;
}
static __device__ __forceinline__ pk_t pk_add(pk_t a, pk_t b) {
    pk_t d; asm("add.rn.f32x2 %0, %1, %2;" : "=l"(d) : "l"(a), "l"(b)); return d;
}

// tanh via e^{-2|x|}: u in (0,1], no overflow anywhere. EX2 + RCP (2 MUFU).
static __device__ __forceinline__ float tanh_fast(float x) {
    float ax = fabsf(x);
    float u  = __expf(-2.0f * ax);
    float t  = __fdividef(1.0f - u, 1.0f + u);
    return copysignf(t, x);
}
static __device__ __forceinline__ float sigmoid_fast(float x) {
    // sigma(x) = 0.5 * (1 + tanh(x/2))  (exact identity)
    return fmaf(tanh_fast(0.5f * x), 0.5f, 0.5f);
}

// SMEM: duplicated-pair weights + biases
//   sWx  : 128 rows x 34  (rows 0..31 = W1, rows 32..127 = Wih[r,z,n])
//   sWhh : 96 rows  x 32
// Row strides: 34*8=272B and 32*8=256B — both 16B-aligned, so ulonglong2
// (LDS.128) loads of consecutive weight pairs are legal everywhere.
static constexpr int SMEM_BYTES =
    (128 * ROWLEN + 96 * HID + 32 + 96 + 96) * 8 + 32 * 4;

__global__ __launch_bounds__(TPB, 3)
void hedge_kernel(const float* __restrict__ S,
                  const float* __restrict__ W1,  const float* __restrict__ b1,
                  const float* __restrict__ W2,  const float* __restrict__ b2,
                  const float* __restrict__ Wih, const float* __restrict__ bih,
                  const float* __restrict__ Whh, const float* __restrict__ bhh,
                  float* __restrict__ out)
{
    extern __shared__ __align__(16) unsigned char smem_raw[];
    pk_t*  sWx  = (pk_t*)smem_raw;              // 128*34
    pk_t*  sWhh = sWx  + 128 * ROWLEN;          // 96*32
    pk_t*  sB1  = sWhh + 96 * HID;              // 32
    pk_t*  sBih = sB1  + 32;                    // 96
    pk_t*  sBhh = sBih + 96;                    // 96
    float* sW2  = (float*)(sBhh + 96);          // 32

    const int tid = threadIdx.x;
    for (int i = tid; i < 128 * ROWLEN; i += TPB) {
        int r = i / ROWLEN, c = i - r * ROWLEN;
        float w = (r < 32) ? W1[r * ROWLEN + c] : Wih[(r - 32) * ROWLEN + c];
        sWx[i] = pk_pack(w, w);
    }
    for (int i = tid; i < 96 * HID; i += TPB) { float w = Whh[i]; sWhh[i] = pk_pack(w, w); }
    for (int i = tid; i < 32; i += TPB) { sB1[i] = pk_pack(b1[i], b1[i]); sW2[i] = W2[i]; }
    for (int i = tid; i < 96; i += TPB) {
        sBih[i] = pk_pack(bih[i], bih[i]);
        sBhh[i] = pk_pack(bhh[i], bhh[i]);
    }
    __syncthreads();

    const float b2v = __ldg(b2);
    const int g = blockIdx.x * TPB + tid;                 // 0 .. B/2-1
    const float* S0 = S + (size_t)(2 * g) * (STEPS + 1);  // rows 2g and 2g+1
    float* out0 = out + (size_t)(2 * g) * STEPS;

    pk_t h[HID];
    #pragma unroll
    for (int k = 0; k < HID; k++) h[k] = 0ull;
    pk_t delta = 0ull;
    const pk_t PKZERO = 0ull;

    float sn0 = S0[0], sn1 = S0[STEPS + 1];

    #pragma unroll 1
    for (int t = 0; t < STEPS; t++) {
        pk_t s = pk_pack(sn0, sn1);
        if (t + 1 < STEPS) { sn0 = S0[t + 1]; sn1 = S0[STEPS + 1 + t + 1]; }

        // ---------------- MLP: delta_new = relu(x@W1^T + b1)@W2^T + b2 ----
        float d0 = b2v, d1 = b2v;
        #pragma unroll 4
        for (int j = 0; j < 32; j++) {
            const ulonglong2* row = (const ulonglong2*)(sWx + j * ROWLEN);
            ulonglong2 p0 = row[0];                 // {W[j,0], W[j,1]}
            pk_t a0 = pk_fma(p0.x, s,     sB1[j]);
            pk_t a1 = pk_fma(p0.y, delta, PKZERO);
            #pragma unroll
            for (int k = 0; k < 16; k++) {
                ulonglong2 p = row[1 + k];          // {W[j,2+2k], W[j,3+2k]}
                a0 = pk_fma(p.x, h[2 * k],     a0);
                a1 = pk_fma(p.y, h[2 * k + 1], a1);
            }
            float x0, x1; pk_unpack(pk_add(a0, a1), x0, x1);
            float w2 = sW2[j];
            d0 = fmaf(fmaxf(x0, 0.0f), w2, d0);
            d1 = fmaf(fmaxf(x1, 0.0f), w2, d1);
        }

        // ---------------- GRU (torch gate order r,z,n) --------------------
        pk_t hn[HID];
        #pragma unroll 4
        for (int j = 0; j < 32; j++) {
            // r gate
            const ulonglong2* xr = (const ulonglong2*)(sWx  + (32 + j) * ROWLEN);
            const ulonglong2* hr = (const ulonglong2*)(sWhh + j * HID);
            ulonglong2 pr0 = xr[0];
            pk_t r0 = pk_fma(pr0.x, s,     sBih[j]);
            pk_t r1 = pk_fma(pr0.y, delta, sBhh[j]);
            #pragma unroll
            for (int k = 0; k < 16; k++) {
                ulonglong2 px = xr[1 + k];
                ulonglong2 ph = hr[k];
                r0 = pk_fma(px.x, h[2 * k],     r0);
                r1 = pk_fma(px.y, h[2 * k + 1], r1);
                r0 = pk_fma(ph.x, h[2 * k],     r0);
                r1 = pk_fma(ph.y, h[2 * k + 1], r1);
            }
            float rp0, rp1; pk_unpack(pk_add(r0, r1), rp0, rp1);

            // z gate
            const ulonglong2* xz = (const ulonglong2*)(sWx  + (64 + j) * ROWLEN);
            const ulonglong2* hz = (const ulonglong2*)(sWhh + (32 + j) * HID);
            ulonglong2 pz0 = xz[0];
            pk_t z0 = pk_fma(pz0.x, s,     sBih[32 + j]);
            pk_t z1 = pk_fma(pz0.y, delta, sBhh[32 + j]);
            #pragma unroll
            for (int k = 0; k < 16; k++) {
                ulonglong2 px = xz[1 + k];
                ulonglong2 ph = hz[k];
                z0 = pk_fma(px.x, h[2 * k],     z0);
                z1 = pk_fma(px.y, h[2 * k + 1], z1);
                z0 = pk_fma(ph.x, h[2 * k],     z0);
                z1 = pk_fma(ph.y, h[2 * k + 1], z1);
            }
            float zp0, zp1; pk_unpack(pk_add(z0, z1), zp0, zp1);

            // n gate: i_n and h_n kept separate (n = tanh(i_n + r*h_n))
            const ulonglong2* xn  = (const ulonglong2*)(sWx  + (96 + j) * ROWLEN);
            const ulonglong2* hnw = (const ulonglong2*)(sWhh + (64 + j) * HID);
            ulonglong2 pn0 = xn[0];
            pk_t in0 = pk_fma(pn0.x, s,     sBih[64 + j]);
            pk_t in1 = pk_fma(pn0.y, delta, PKZERO);
            pk_t hh0 = sBhh[64 + j];
            pk_t hh1 = PKZERO;
            #pragma unroll
            for (int k = 0; k < 16; k++) {
                ulonglong2 px = xn[1 + k];
                ulonglong2 ph = hnw[k];
                in0 = pk_fma(px.x, h[2 * k],     in0);
                in1 = pk_fma(px.y, h[2 * k + 1], in1);
                hh0 = pk_fma(ph.x, h[2 * k],     hh0);
                hh1 = pk_fma(ph.y, h[2 * k + 1], hh1);
            }
            float inp0, inp1, hhp0, hhp1;
            pk_unpack(pk_add(in0, in1), inp0, inp1);
            pk_unpack(pk_add(hh0, hh1), hhp0, hhp1);

            float hc0, hc1; pk_unpack(h[j], hc0, hc1);
            float rg0 = sigmoid_fast(rp0), rg1 = sigmoid_fast(rp1);
            float zg0 = sigmoid_fast(zp0), zg1 = sigmoid_fast(zp1);
            float n0  = tanh_fast(fmaf(rg0, hhp0, inp0));
            float n1  = tanh_fast(fmaf(rg1, hhp1, inp1));
            // h' = (1-z)*n + z*h = n + z*(h-n)
            float o0 = fmaf(zg0, hc0 - n0, n0);
            float o1 = fmaf(zg1, hc1 - n1, n1);
            hn[j] = pk_pack(o0, o1);
        }

        #pragma unroll
        for (int k = 0; k < HID; k++) h[k] = hn[k];

        out0[t]         = d0;
        out0[STEPS + t] = d1;
        delta = pk_pack(d0, d1);
    }
}

extern "C" void kernel_launch(void* const* d_in, const int* in_sizes, int n_in,
                              void* d_out, int out_size)
{
    (void)in_sizes; (void)n_in; (void)out_size;
    const float* S   = (const float*)d_in[0];
    const float* W1  = (const float*)d_in[1];
    const float* b1  = (const float*)d_in[2];
    const float* W2  = (const float*)d_in[3];
    const float* b2  = (const float*)d_in[4];
    const float* Wih = (const float*)d_in[5];
    const float* bih = (const float*)d_in[6];
    const float* Whh = (const float*)d_in[7];
    const float* bhh = (const float*)d_in[8];
    float* out = (float*)d_out;

    cudaFuncSetAttribute(hedge_kernel,
                         cudaFuncAttributeMaxDynamicSharedMemorySize, SMEM_BYTES);

    const int nthreads = BTOTAL / 2;          // 2 elements per thread
    dim3 grid(nthreads / TPB);                // 4096 blocks
    hedge_kernel<<<grid, TPB, SMEM_BYTES>>>(S, W1, b1, W2, b2,
                                            Wih, bih, Whh, bhh, out);
}

// round 3
// speedup vs baseline: 1.6887x; 1.3496x over previous
#include <cuda_runtime.h>

// RecurrentHedgeModel: B=1048576, STEPS=30, INPUT_DIM=1, HIDDEN=32
// Round 3: exact algebraic fold — for the r and z gates, (Wih[:,2:34] + Whh)
// multiplies the same h and the pre-activations are summed before sigmoid, so
// fold Whh into Wih's h-columns (and the biases) at init. Cuts BOTH the LDS
// byte stream (the binding pipe, L1=98.4%) and FFMA2 work by 27.6%.

#define STEPS   30
#define HID     32
#define ROWLEN  34      // x = [s, delta_prev, h(32)]
#define BTOTAL  1048576
#define TPB     128

typedef unsigned long long pk_t;   // packed (f32 lo, f32 hi)

static __device__ __forceinline__ pk_t pk_pack(float lo, float hi) {
    pk_t r; asm("mov.b64 %0, {%1, %2};" : "=l"(r) : "f"(lo), "f"(hi)); return r;
}
static __device__ __forceinline__ void pk_unpack(pk_t v, float& lo, float& hi) {
    asm("mov.b64 {%0, %1}, %2;" : "=f"(lo), "=f"(hi) : "l"(v));
}
static __device__ __forceinline__ pk_t pk_fma(pk_t a, pk_t b, pk_t c) {
    pk_t d; asm("fma.rn.f32x2 %0, %1, %2, %3;" : "=l"(d) : "l"(a), "l"(b), "l"(c)); return d;
}
static __device__ __forceinline__ pk_t pk_add(pk_t a, pk_t b) {
    pk_t d; asm("add.rn.f32x2 %0, %1, %2;" : "=l"(d) : "l"(a), "l"(b)); return d;
}

// tanh via e^{-2|x|}: u in (0,1], no overflow anywhere. EX2 + RCP (2 MUFU).
static __device__ __forceinline__ float tanh_fast(float x) {
    float ax = fabsf(x);
    float u  = __expf(-2.0f * ax);
    float t  = __fdividef(1.0f - u, 1.0f + u);
    return copysignf(t, x);
}
static __device__ __forceinline__ float sigmoid_fast(float x) {
    return fmaf(tanh_fast(0.5f * x), 0.5f, 0.5f);
}

// SMEM (duplicated-pair weights):
//   sW   : 128 rows x 34 pk
//          rows   0..31  = W1 (MLP)
//          rows  32..63  = folded R rows:  [Wih_r[:,0:2] | Wih_r[:,2:]+Whh_r]
//          rows  64..95  = folded Z rows
//          rows  96..127 = Wih_n (x-part of n gate, unfolded)
//   sWhhn: 32 rows x 32 pk (Whh n-gate rows)
//   sB1[32], sBrz[64] (folded), sBin[32], sBhn[32], sW2[32] floats
static constexpr int SMEM_BYTES =
    (128 * ROWLEN + 32 * HID + 32 + 64 + 32 + 32) * 8 + 32 * 4;

__global__ __launch_bounds__(TPB, 3)
void hedge_kernel(const float* __restrict__ S,
                  const float* __restrict__ W1,  const float* __restrict__ b1,
                  const float* __restrict__ W2,  const float* __restrict__ b2,
                  const float* __restrict__ Wih, const float* __restrict__ bih,
                  const float* __restrict__ Whh, const float* __restrict__ bhh,
                  float* __restrict__ out)
{
    extern __shared__ __align__(16) unsigned char smem_raw[];
    pk_t*  sW    = (pk_t*)smem_raw;              // 128*34
    pk_t*  sWhhn = sW    + 128 * ROWLEN;         // 32*32
    pk_t*  sB1   = sWhhn + 32 * HID;             // 32
    pk_t*  sBrz  = sB1   + 32;                   // 64
    pk_t*  sBin  = sBrz  + 64;                   // 32
    pk_t*  sBhn  = sBin  + 32;                   // 32
    float* sW2   = (float*)(sBhn + 32);          // 32

    const int tid = threadIdx.x;
    for (int i = tid; i < 128 * ROWLEN; i += TPB) {
        int r = i / ROWLEN, c = i - r * ROWLEN;
        float w;
        if (r < 32) {
            w = W1[r * ROWLEN + c];
        } else {
            int gr = r - 32;                     // Wih row index 0..95
            w = Wih[gr * ROWLEN + c];
            if (gr < 64 && c >= 2)               // fold Whh into r,z h-columns
                w += Whh[gr * HID + (c - 2)];
        }
        sW[i] = pk_pack(w, w);
    }
    for (int i = tid; i < 32 * HID; i += TPB) {  // Whh n-gate rows (64..95)
        float w = Whh[(64) * HID + i];
        sWhhn[i] = pk_pack(w, w);
    }
    for (int i = tid; i < 32; i += TPB) {
        sB1[i]  = pk_pack(b1[i], b1[i]);
        sW2[i]  = W2[i];
        float bn = bih[64 + i]; sBin[i] = pk_pack(bn, bn);
        float bh = bhh[64 + i]; sBhn[i] = pk_pack(bh, bh);
    }
    for (int i = tid; i < 64; i += TPB) {        // folded r,z biases
        float b = bih[i] + bhh[i];
        sBrz[i] = pk_pack(b, b);
    }
    __syncthreads();

    const float b2v = __ldg(b2);
    const int g = blockIdx.x * TPB + tid;                 // 0 .. B/2-1
    const float* S0 = S + (size_t)(2 * g) * (STEPS + 1);  // rows 2g and 2g+1
    float* out0 = out + (size_t)(2 * g) * STEPS;

    pk_t h[HID];
    #pragma unroll
    for (int k = 0; k < HID; k++) h[k] = 0ull;
    pk_t delta = 0ull;
    const pk_t PKZERO = 0ull;

    float sn0 = S0[0], sn1 = S0[STEPS + 1];

    #pragma unroll 1
    for (int t = 0; t < STEPS; t++) {
        pk_t s = pk_pack(sn0, sn1);
        if (t + 1 < STEPS) { sn0 = S0[t + 1]; sn1 = S0[STEPS + 1 + t + 1]; }

        // ---------------- MLP: delta_new = relu(x@W1^T + b1)@W2^T + b2 ----
        float d0 = b2v, d1 = b2v;
        #pragma unroll 4
        for (int j = 0; j < 32; j++) {
            const ulonglong2* row = (const ulonglong2*)(sW + j * ROWLEN);
            ulonglong2 p0 = row[0];
            pk_t a0 = pk_fma(p0.x, s,     sB1[j]);
            pk_t a1 = pk_fma(p0.y, delta, PKZERO);
            #pragma unroll
            for (int k = 0; k < 16; k++) {
                ulonglong2 p = row[1 + k];
                a0 = pk_fma(p.x, h[2 * k],     a0);
                a1 = pk_fma(p.y, h[2 * k + 1], a1);
            }
            float x0, x1; pk_unpack(pk_add(a0, a1), x0, x1);
            float w2 = sW2[j];
            d0 = fmaf(fmaxf(x0, 0.0f), w2, d0);
            d1 = fmaf(fmaxf(x1, 0.0f), w2, d1);
        }

        // ---------------- GRU (torch gate order r,z,n) --------------------
        pk_t hn[HID];
        #pragma unroll 4
        for (int j = 0; j < 32; j++) {
            // r gate: folded row, single pass over h
            const ulonglong2* xr = (const ulonglong2*)(sW + (32 + j) * ROWLEN);
            ulonglong2 pr0 = xr[0];
            pk_t r0 = pk_fma(pr0.x, s,     sBrz[j]);
            pk_t r1 = pk_fma(pr0.y, delta, PKZERO);
            #pragma unroll
            for (int k = 0; k < 16; k++) {
                ulonglong2 p = xr[1 + k];
                r0 = pk_fma(p.x, h[2 * k],     r0);
                r1 = pk_fma(p.y, h[2 * k + 1], r1);
            }
            float rp0, rp1; pk_unpack(pk_add(r0, r1), rp0, rp1);

            // z gate: folded row
            const ulonglong2* xz = (const ulonglong2*)(sW + (64 + j) * ROWLEN);
            ulonglong2 pz0 = xz[0];
            pk_t z0 = pk_fma(pz0.x, s,     sBrz[32 + j]);
            pk_t z1 = pk_fma(pz0.y, delta, PKZERO);
            #pragma unroll
            for (int k = 0; k < 16; k++) {
                ulonglong2 p = xz[1 + k];
                z0 = pk_fma(p.x, h[2 * k],     z0);
                z1 = pk_fma(p.y, h[2 * k + 1], z1);
            }
            float zp0, zp1; pk_unpack(pk_add(z0, z1), zp0, zp1);

            // n gate: i_n and h_n must stay separate (n = tanh(i_n + r*h_n))
            const ulonglong2* xn  = (const ulonglong2*)(sW    + (96 + j) * ROWLEN);
            const ulonglong2* hnw = (const ulonglong2*)(sWhhn + j * HID);
            ulonglong2 pn0 = xn[0];
            pk_t in0 = pk_fma(pn0.x, s,     sBin[j]);
            pk_t in1 = pk_fma(pn0.y, delta, PKZERO);
            pk_t hh0 = sBhn[j];
            pk_t hh1 = PKZERO;
            #pragma unroll
            for (int k = 0; k < 16; k++) {
                ulonglong2 px = xn[1 + k];
                ulonglong2 ph = hnw[k];
                in0 = pk_fma(px.x, h[2 * k],     in0);
                in1 = pk_fma(px.y, h[2 * k + 1], in1);
                hh0 = pk_fma(ph.x, h[2 * k],     hh0);
                hh1 = pk_fma(ph.y, h[2 * k + 1], hh1);
            }
            float inp0, inp1, hhp0, hhp1;
            pk_unpack(pk_add(in0, in1), inp0, inp1);
            pk_unpack(pk_add(hh0, hh1), hhp0, hhp1);

            float hc0, hc1; pk_unpack(h[j], hc0, hc1);
            float rg0 = sigmoid_fast(rp0), rg1 = sigmoid_fast(rp1);
            float zg0 = sigmoid_fast(zp0), zg1 = sigmoid_fast(zp1);
            float n0  = tanh_fast(fmaf(rg0, hhp0, inp0));
            float n1  = tanh_fast(fmaf(rg1, hhp1, inp1));
            // h' = (1-z)*n + z*h = n + z*(h-n)
            float o0 = fmaf(zg0, hc0 - n0, n0);
            float o1 = fmaf(zg1, hc1 - n1, n1);
            hn[j] = pk_pack(o0, o1);
        }

        #pragma unroll
        for (int k = 0; k < HID; k++) h[k] = hn[k];

        out0[t]         = d0;
        out0[STEPS + t] = d1;
        delta = pk_pack(d0, d1);
    }
}

extern "C" void kernel_launch(void* const* d_in, const int* in_sizes, int n_in,
                              void* d_out, int out_size)
{
    (void)in_sizes; (void)n_in; (void)out_size;
    const float* S   = (const float*)d_in[0];
    const float* W1  = (const float*)d_in[1];
    const float* b1  = (const float*)d_in[2];
    const float* W2  = (const float*)d_in[3];
    const float* b2  = (const float*)d_in[4];
    const float* Wih = (const float*)d_in[5];
    const float* bih = (const float*)d_in[6];
    const float* Whh = (const float*)d_in[7];
    const float* bhh = (const float*)d_in[8];
    float* out = (float*)d_out;

    cudaFuncSetAttribute(hedge_kernel,
                         cudaFuncAttributeMaxDynamicSharedMemorySize, SMEM_BYTES);

    const int nthreads = BTOTAL / 2;          // 2 elements per thread
    dim3 grid(nthreads / TPB);                // 4096 blocks
    hedge_kernel<<<grid, TPB, SMEM_BYTES>>>(S, W1, b1, W2, b2,
                                            Wih, bih, Whh, bhh, out);
}

// round 4
// speedup vs baseline: 1.9399x; 1.1488x over previous
#include <cuda_runtime.h>

// RecurrentHedgeModel: B=1048576, STEPS=30, INPUT_DIM=1, HIDDEN=32
// Round 4: 4 batch elements per thread. Each 16B broadcast weight load
// (2 L1 wavefront-cycles) now feeds 4 FFMA2s, balancing the L1 and fma
// pipes (round-3 ncu: L1=97.7% binding at exactly 2x the fma demand).
// hn double-buffer spilled to per-thread SMEM (conflict-free [slot][tid]).

#define STEPS   30
#define HID     32
#define ROWLEN  34      // x = [s, delta_prev, h(32)]
#define BTOTAL  1048576
#define TPB     128

typedef unsigned long long pk_t;   // packed (f32 lo, f32 hi)

static __device__ __forceinline__ pk_t pk_pack(float lo, float hi) {
    pk_t r; asm("mov.b64 %0, {%1, %2};" : "=l"(r) : "f"(lo), "f"(hi)); return r;
}
static __device__ __forceinline__ void pk_unpack(pk_t v, float& lo, float& hi) {
    asm("mov.b64 {%0, %1}, %2;" : "=f"(lo), "=f"(hi) : "l"(v));
}
static __device__ __forceinline__ pk_t pk_fma(pk_t a, pk_t b, pk_t c) {
    pk_t d; asm("fma.rn.f32x2 %0, %1, %2, %3;" : "=l"(d) : "l"(a), "l"(b), "l"(c)); return d;
}
static __device__ __forceinline__ pk_t pk_add(pk_t a, pk_t b) {
    pk_t d; asm("add.rn.f32x2 %0, %1, %2;" : "=l"(d) : "l"(a), "l"(b)); return d;
}

// tanh via e^{-2|x|}: u in (0,1], no overflow anywhere. EX2 + RCP (2 MUFU).
static __device__ __forceinline__ float tanh_fast(float x) {
    float ax = fabsf(x);
    float u  = __expf(-2.0f * ax);
    float t  = __fdividef(1.0f - u, 1.0f + u);
    return copysignf(t, x);
}
static __device__ __forceinline__ float sigmoid_fast(float x) {
    return fmaf(tanh_fast(0.5f * x), 0.5f, 0.5f);
}

// SMEM layout (duplicated-pair weights, identical to round 3) + hn spill:
//   sW   : 128 rows x 34 pk   (W1 | folded-R | folded-Z | Wih_n)
//   sWhhn: 32 rows x 32 pk    (Whh n-gate)
//   sB1[32], sBrz[64], sBin[32], sBhn[32] pk; sW2[32] float
//   sHn  : [64][TPB] pk  — per-thread hn double buffer, lane-contiguous
static constexpr int WPK        = 128 * ROWLEN + 32 * HID + 32 + 64 + 32 + 32; // 5536
static constexpr int HN_OFF     = WPK * 8 + 32 * 4;                            // 44416
static constexpr int SMEM_BYTES = HN_OFF + 64 * TPB * 8;                       // 109952

__global__ __launch_bounds__(TPB, 2)
void hedge_kernel(const float* __restrict__ S,
                  const float* __restrict__ W1,  const float* __restrict__ b1,
                  const float* __restrict__ W2,  const float* __restrict__ b2,
                  const float* __restrict__ Wih, const float* __restrict__ bih,
                  const float* __restrict__ Whh, const float* __restrict__ bhh,
                  float* __restrict__ out)
{
    extern __shared__ __align__(16) unsigned char smem_raw[];
    pk_t*  sW    = (pk_t*)smem_raw;              // 128*34
    pk_t*  sWhhn = sW    + 128 * ROWLEN;         // 32*32
    pk_t*  sB1   = sWhhn + 32 * HID;             // 32
    pk_t*  sBrz  = sB1   + 32;                   // 64
    pk_t*  sBin  = sBrz  + 64;                   // 32
    pk_t*  sBhn  = sBin  + 32;                   // 32
    float* sW2   = (float*)(sBhn + 32);          // 32
    pk_t*  sHn   = (pk_t*)(smem_raw + HN_OFF);   // [64][TPB]

    const int tid = threadIdx.x;
    for (int i = tid; i < 128 * ROWLEN; i += TPB) {
        int r = i / ROWLEN, c = i - r * ROWLEN;
        float w;
        if (r < 32) {
            w = W1[r * ROWLEN + c];
        } else {
            int gr = r - 32;                     // Wih row index 0..95
            w = Wih[gr * ROWLEN + c];
            if (gr < 64 && c >= 2)               // fold Whh into r,z h-columns
                w += Whh[gr * HID + (c - 2)];
        }
        sW[i] = pk_pack(w, w);
    }
    for (int i = tid; i < 32 * HID; i += TPB) {  // Whh n-gate rows (64..95)
        float w = Whh[64 * HID + i];
        sWhhn[i] = pk_pack(w, w);
    }
    for (int i = tid; i < 32; i += TPB) {
        sB1[i]  = pk_pack(b1[i], b1[i]);
        sW2[i]  = W2[i];
        float bn = bih[64 + i]; sBin[i] = pk_pack(bn, bn);
        float bh = bhh[64 + i]; sBhn[i] = pk_pack(bh, bh);
    }
    for (int i = tid; i < 64; i += TPB) {        // folded r,z biases
        float b = bih[i] + bhh[i];
        sBrz[i] = pk_pack(b, b);
    }
    __syncthreads();

    const float b2v = __ldg(b2);
    const int g = blockIdx.x * TPB + tid;                 // 0 .. B/4-1
    const float* S0 = S + (size_t)(4 * g) * (STEPS + 1);  // rows 4g..4g+3
    float* out0 = out + (size_t)(4 * g) * STEPS;

    pk_t hA[HID], hB[HID];
    #pragma unroll
    for (int k = 0; k < HID; k++) { hA[k] = 0ull; hB[k] = 0ull; }
    pk_t dA = 0ull, dB = 0ull;
    const pk_t PKZERO = 0ull;

    float s0 = S0[0], s1 = S0[STEPS + 1], s2 = S0[2 * (STEPS + 1)], s3 = S0[3 * (STEPS + 1)];

    #pragma unroll 1
    for (int t = 0; t < STEPS; t++) {
        pk_t sA = pk_pack(s0, s1);
        pk_t sB_ = pk_pack(s2, s3);
        if (t + 1 < STEPS) {
            s0 = S0[t + 1];
            s1 = S0[(STEPS + 1) + t + 1];
            s2 = S0[2 * (STEPS + 1) + t + 1];
            s3 = S0[3 * (STEPS + 1) + t + 1];
        }

        // ---------------- MLP: delta = relu(x@W1^T + b1)@W2^T + b2 --------
        float d0 = b2v, d1 = b2v, d2 = b2v, d3 = b2v;
        #pragma unroll 1
        for (int j = 0; j < 32; j++) {
            const ulonglong2* row = (const ulonglong2*)(sW + j * ROWLEN);
            ulonglong2 p0 = row[0];
            pk_t bj = sB1[j];
            pk_t aA0 = pk_fma(p0.x, sA,  bj);
            pk_t aA1 = pk_fma(p0.y, dA,  PKZERO);
            pk_t aB0 = pk_fma(p0.x, sB_, bj);
            pk_t aB1 = pk_fma(p0.y, dB,  PKZERO);
            #pragma unroll
            for (int k = 0; k < 16; k++) {
                ulonglong2 p = row[1 + k];
                aA0 = pk_fma(p.x, hA[2 * k],     aA0);
                aA1 = pk_fma(p.y, hA[2 * k + 1], aA1);
                aB0 = pk_fma(p.x, hB[2 * k],     aB0);
                aB1 = pk_fma(p.y, hB[2 * k + 1], aB1);
            }
            float x0, x1, x2, x3;
            pk_unpack(pk_add(aA0, aA1), x0, x1);
            pk_unpack(pk_add(aB0, aB1), x2, x3);
            float w2 = sW2[j];
            d0 = fmaf(fmaxf(x0, 0.0f), w2, d0);
            d1 = fmaf(fmaxf(x1, 0.0f), w2, d1);
            d2 = fmaf(fmaxf(x2, 0.0f), w2, d2);
            d3 = fmaf(fmaxf(x3, 0.0f), w2, d3);
        }

        // ---------------- GRU (torch gate order r,z,n) --------------------
        #pragma unroll 1
        for (int j = 0; j < 32; j++) {
            // r gate (folded)
            const ulonglong2* xr = (const ulonglong2*)(sW + (32 + j) * ROWLEN);
            ulonglong2 pr0 = xr[0];
            pk_t brz = sBrz[j];
            pk_t rA0 = pk_fma(pr0.x, sA,  brz);
            pk_t rA1 = pk_fma(pr0.y, dA,  PKZERO);
            pk_t rB0 = pk_fma(pr0.x, sB_, brz);
            pk_t rB1 = pk_fma(pr0.y, dB,  PKZERO);
            #pragma unroll
            for (int k = 0; k < 16; k++) {
                ulonglong2 p = xr[1 + k];
                rA0 = pk_fma(p.x, hA[2 * k],     rA0);
                rA1 = pk_fma(p.y, hA[2 * k + 1], rA1);
                rB0 = pk_fma(p.x, hB[2 * k],     rB0);
                rB1 = pk_fma(p.y, hB[2 * k + 1], rB1);
            }
            float rp0, rp1, rp2, rp3;
            pk_unpack(pk_add(rA0, rA1), rp0, rp1);
            pk_unpack(pk_add(rB0, rB1), rp2, rp3);

            // z gate (folded)
            const ulonglong2* xz = (const ulonglong2*)(sW + (64 + j) * ROWLEN);
            ulonglong2 pz0 = xz[0];
            pk_t bz = sBrz[32 + j];
            pk_t zA0 = pk_fma(pz0.x, sA,  bz);
            pk_t zA1 = pk_fma(pz0.y, dA,  PKZERO);
            pk_t zB0 = pk_fma(pz0.x, sB_, bz);
            pk_t zB1 = pk_fma(pz0.y, dB,  PKZERO);
            #pragma unroll
            for (int k = 0; k < 16; k++) {
                ulonglong2 p = xz[1 + k];
                zA0 = pk_fma(p.x, hA[2 * k],     zA0);
                zA1 = pk_fma(p.y, hA[2 * k + 1], zA1);
                zB0 = pk_fma(p.x, hB[2 * k],     zB0);
                zB1 = pk_fma(p.y, hB[2 * k + 1], zB1);
            }
            float zp0, zp1, zp2, zp3;
            pk_unpack(pk_add(zA0, zA1), zp0, zp1);
            pk_unpack(pk_add(zB0, zB1), zp2, zp3);

            // n gate: i_n and h_n separate (n = tanh(i_n + r*h_n))
            const ulonglong2* xn  = (const ulonglong2*)(sW    + (96 + j) * ROWLEN);
            const ulonglong2* hnw = (const ulonglong2*)(sWhhn + j * HID);
            ulonglong2 pn0 = xn[0];
            pk_t bin = sBin[j], bhn = sBhn[j];
            pk_t inA0 = pk_fma(pn0.x, sA,  bin);
            pk_t inA1 = pk_fma(pn0.y, dA,  PKZERO);
            pk_t inB0 = pk_fma(pn0.x, sB_, bin);
            pk_t inB1 = pk_fma(pn0.y, dB,  PKZERO);
            pk_t hhA0 = bhn, hhA1 = PKZERO;
            pk_t hhB0 = bhn, hhB1 = PKZERO;
            #pragma unroll
            for (int k = 0; k < 16; k++) {
                ulonglong2 px = xn[1 + k];
                ulonglong2 ph = hnw[k];
                inA0 = pk_fma(px.x, hA[2 * k],     inA0);
                inA1 = pk_fma(px.y, hA[2 * k + 1], inA1);
                inB0 = pk_fma(px.x, hB[2 * k],     inB0);
                inB1 = pk_fma(px.y, hB[2 * k + 1], inB1);
                hhA0 = pk_fma(ph.x, hA[2 * k],     hhA0);
                hhA1 = pk_fma(ph.y, hA[2 * k + 1], hhA1);
                hhB0 = pk_fma(ph.x, hB[2 * k],     hhB0);
                hhB1 = pk_fma(ph.y, hB[2 * k + 1], hhB1);
            }
            float in0, in1, in2, in3, hh0, hh1, hh2, hh3;
            pk_unpack(pk_add(inA0, inA1), in0, in1);
            pk_unpack(pk_add(inB0, inB1), in2, in3);
            pk_unpack(pk_add(hhA0, hhA1), hh0, hh1);
            pk_unpack(pk_add(hhB0, hhB1), hh2, hh3);

            float hc0, hc1, hc2, hc3;
            pk_unpack(hA[j], hc0, hc1);
            pk_unpack(hB[j], hc2, hc3);

            float rg0 = sigmoid_fast(rp0), rg1 = sigmoid_fast(rp1);
            float rg2 = sigmoid_fast(rp2), rg3 = sigmoid_fast(rp3);
            float zg0 = sigmoid_fast(zp0), zg1 = sigmoid_fast(zp1);
            float zg2 = sigmoid_fast(zp2), zg3 = sigmoid_fast(zp3);
            float n0 = tanh_fast(fmaf(rg0, hh0, in0));
            float n1 = tanh_fast(fmaf(rg1, hh1, in1));
            float n2 = tanh_fast(fmaf(rg2, hh2, in2));
            float n3 = tanh_fast(fmaf(rg3, hh3, in3));
            float o0 = fmaf(zg0, hc0 - n0, n0);
            float o1 = fmaf(zg1, hc1 - n1, n1);
            float o2 = fmaf(zg2, hc2 - n2, n2);
            float o3 = fmaf(zg3, hc3 - n3, n3);

            sHn[j * TPB + tid]          = pk_pack(o0, o1);
            sHn[(32 + j) * TPB + tid]   = pk_pack(o2, o3);
        }

        // copy hn back into register h (conflict-free lane-contiguous LDS)
        #pragma unroll
        for (int k = 0; k < HID; k++) {
            hA[k] = sHn[k * TPB + tid];
            hB[k] = sHn[(32 + k) * TPB + tid];
        }

        out0[t]             = d0;
        out0[STEPS + t]     = d1;
        out0[2 * STEPS + t] = d2;
        out0[3 * STEPS + t] = d3;
        dA = pk_pack(d0, d1);
        dB = pk_pack(d2, d3);
    }
}

extern "C" void kernel_launch(void* const* d_in, const int* in_sizes, int n_in,
                              void* d_out, int out_size)
{
    (void)in_sizes; (void)n_in; (void)out_size;
    const float* S   = (const float*)d_in[0];
    const float* W1  = (const float*)d_in[1];
    const float* b1  = (const float*)d_in[2];
    const float* W2  = (const float*)d_in[3];
    const float* b2  = (const float*)d_in[4];
    const float* Wih = (const float*)d_in[5];
    const float* bih = (const float*)d_in[6];
    const float* Whh = (const float*)d_in[7];
    const float* bhh = (const float*)d_in[8];
    float* out = (float*)d_out;

    cudaFuncSetAttribute(hedge_kernel,
                         cudaFuncAttributeMaxDynamicSharedMemorySize, SMEM_BYTES);

    const int nthreads = BTOTAL / 4;          // 4 elements per thread
    dim3 grid(nthreads / TPB);                // 2048 blocks
    hedge_kernel<<<grid, TPB, SMEM_BYTES>>>(S, W1, b1, W2, b2,
                                            Wih, bih, Whh, bhh, out);
}

// round 5
// speedup vs baseline: 2.0440x; 1.0536x over previous
#include <cuda_runtime.h>

// RecurrentHedgeModel: B=1048576, STEPS=30, INPUT_DIM=1, HIDDEN=32
// Round 5: same 4-elem/thread structure as round 4 (pipes balanced at ~60%),
// now attack the issue/latency bound (issue=49.6%, 2 warps/SMSP): unroll the
// j-row loops by 2 to double independent FFMA2 chains and outstanding LDS per
// warp, overlapping row epilogues (MUFU chains) with the next row's matvec.

#define STEPS   30
#define HID     32
#define ROWLEN  34      // x = [s, delta_prev, h(32)]
#define BTOTAL  1048576
#define TPB     128

typedef unsigned long long pk_t;   // packed (f32 lo, f32 hi)

static __device__ __forceinline__ pk_t pk_pack(float lo, float hi) {
    pk_t r; asm("mov.b64 %0, {%1, %2};" : "=l"(r) : "f"(lo), "f"(hi)); return r;
}
static __device__ __forceinline__ void pk_unpack(pk_t v, float& lo, float& hi) {
    asm("mov.b64 {%0, %1}, %2;" : "=f"(lo), "=f"(hi) : "l"(v));
}
static __device__ __forceinline__ pk_t pk_fma(pk_t a, pk_t b, pk_t c) {
    pk_t d; asm("fma.rn.f32x2 %0, %1, %2, %3;" : "=l"(d) : "l"(a), "l"(b), "l"(c)); return d;
}
static __device__ __forceinline__ pk_t pk_add(pk_t a, pk_t b) {
    pk_t d; asm("add.rn.f32x2 %0, %1, %2;" : "=l"(d) : "l"(a), "l"(b)); return d;
}

// tanh via e^{-2|x|}: u in (0,1], no overflow anywhere. EX2 + RCP (2 MUFU).
static __device__ __forceinline__ float tanh_fast(float x) {
    float ax = fabsf(x);
    float u  = __expf(-2.0f * ax);
    float t  = __fdividef(1.0f - u, 1.0f + u);
    return copysignf(t, x);
}
static __device__ __forceinline__ float sigmoid_fast(float x) {
    return fmaf(tanh_fast(0.5f * x), 0.5f, 0.5f);
}

// SMEM layout (duplicated-pair weights) + hn spill:
//   sW   : 128 rows x 34 pk   (W1 | folded-R | folded-Z | Wih_n)
//   sWhhn: 32 rows x 32 pk    (Whh n-gate)
//   sB1[32], sBrz[64], sBin[32], sBhn[32] pk; sW2[32] float
//   sHn  : [64][TPB] pk  — per-thread hn double buffer, lane-contiguous
static constexpr int WPK        = 128 * ROWLEN + 32 * HID + 32 + 64 + 32 + 32; // 5536
static constexpr int HN_OFF     = WPK * 8 + 32 * 4;                            // 44416
static constexpr int SMEM_BYTES = HN_OFF + 64 * TPB * 8;                       // 109952

__global__ __launch_bounds__(TPB, 2)
void hedge_kernel(const float* __restrict__ S,
                  const float* __restrict__ W1,  const float* __restrict__ b1,
                  const float* __restrict__ W2,  const float* __restrict__ b2,
                  const float* __restrict__ Wih, const float* __restrict__ bih,
                  const float* __restrict__ Whh, const float* __restrict__ bhh,
                  float* __restrict__ out)
{
    extern __shared__ __align__(16) unsigned char smem_raw[];
    pk_t*  sW    = (pk_t*)smem_raw;              // 128*34
    pk_t*  sWhhn = sW    + 128 * ROWLEN;         // 32*32
    pk_t*  sB1   = sWhhn + 32 * HID;             // 32
    pk_t*  sBrz  = sB1   + 32;                   // 64
    pk_t*  sBin  = sBrz  + 64;                   // 32
    pk_t*  sBhn  = sBin  + 32;                   // 32
    float* sW2   = (float*)(sBhn + 32);          // 32
    pk_t*  sHn   = (pk_t*)(smem_raw + HN_OFF);   // [64][TPB]

    const int tid = threadIdx.x;
    for (int i = tid; i < 128 * ROWLEN; i += TPB) {
        int r = i / ROWLEN, c = i - r * ROWLEN;
        float w;
        if (r < 32) {
            w = W1[r * ROWLEN + c];
        } else {
            int gr = r - 32;                     // Wih row index 0..95
            w = Wih[gr * ROWLEN + c];
            if (gr < 64 && c >= 2)               // fold Whh into r,z h-columns
                w += Whh[gr * HID + (c - 2)];
        }
        sW[i] = pk_pack(w, w);
    }
    for (int i = tid; i < 32 * HID; i += TPB) {  // Whh n-gate rows (64..95)
        float w = Whh[64 * HID + i];
        sWhhn[i] = pk_pack(w, w);
    }
    for (int i = tid; i < 32; i += TPB) {
        sB1[i]  = pk_pack(b1[i], b1[i]);
        sW2[i]  = W2[i];
        float bn = bih[64 + i]; sBin[i] = pk_pack(bn, bn);
        float bh = bhh[64 + i]; sBhn[i] = pk_pack(bh, bh);
    }
    for (int i = tid; i < 64; i += TPB) {        // folded r,z biases
        float b = bih[i] + bhh[i];
        sBrz[i] = pk_pack(b, b);
    }
    __syncthreads();

    const float b2v = __ldg(b2);
    const int g = blockIdx.x * TPB + tid;                 // 0 .. B/4-1
    const float* S0 = S + (size_t)(4 * g) * (STEPS + 1);  // rows 4g..4g+3
    float* out0 = out + (size_t)(4 * g) * STEPS;

    pk_t hA[HID], hB[HID];
    #pragma unroll
    for (int k = 0; k < HID; k++) { hA[k] = 0ull; hB[k] = 0ull; }
    pk_t dA = 0ull, dB = 0ull;
    const pk_t PKZERO = 0ull;

    float s0 = S0[0], s1 = S0[STEPS + 1], s2 = S0[2 * (STEPS + 1)], s3 = S0[3 * (STEPS + 1)];

    #pragma unroll 1
    for (int t = 0; t < STEPS; t++) {
        pk_t sA = pk_pack(s0, s1);
        pk_t sB_ = pk_pack(s2, s3);
        if (t + 1 < STEPS) {
            s0 = S0[t + 1];
            s1 = S0[(STEPS + 1) + t + 1];
            s2 = S0[2 * (STEPS + 1) + t + 1];
            s3 = S0[3 * (STEPS + 1) + t + 1];
        }

        // ---------------- MLP: delta = relu(x@W1^T + b1)@W2^T + b2 --------
        float d0 = b2v, d1 = b2v, d2 = b2v, d3 = b2v;
        #pragma unroll 2
        for (int j = 0; j < 32; j++) {
            const ulonglong2* row = (const ulonglong2*)(sW + j * ROWLEN);
            ulonglong2 p0 = row[0];
            pk_t bj = sB1[j];
            pk_t aA0 = pk_fma(p0.x, sA,  bj);
            pk_t aA1 = pk_fma(p0.y, dA,  PKZERO);
            pk_t aB0 = pk_fma(p0.x, sB_, bj);
            pk_t aB1 = pk_fma(p0.y, dB,  PKZERO);
            #pragma unroll
            for (int k = 0; k < 16; k++) {
                ulonglong2 p = row[1 + k];
                aA0 = pk_fma(p.x, hA[2 * k],     aA0);
                aA1 = pk_fma(p.y, hA[2 * k + 1], aA1);
                aB0 = pk_fma(p.x, hB[2 * k],     aB0);
                aB1 = pk_fma(p.y, hB[2 * k + 1], aB1);
            }
            float x0, x1, x2, x3;
            pk_unpack(pk_add(aA0, aA1), x0, x1);
            pk_unpack(pk_add(aB0, aB1), x2, x3);
            float w2 = sW2[j];
            d0 = fmaf(fmaxf(x0, 0.0f), w2, d0);
            d1 = fmaf(fmaxf(x1, 0.0f), w2, d1);
            d2 = fmaf(fmaxf(x2, 0.0f), w2, d2);
            d3 = fmaf(fmaxf(x3, 0.0f), w2, d3);
        }

        // ---------------- GRU (torch gate order r,z,n) --------------------
        #pragma unroll 2
        for (int j = 0; j < 32; j++) {
            // r gate (folded)
            const ulonglong2* xr = (const ulonglong2*)(sW + (32 + j) * ROWLEN);
            ulonglong2 pr0 = xr[0];
            pk_t brz = sBrz[j];
            pk_t rA0 = pk_fma(pr0.x, sA,  brz);
            pk_t rA1 = pk_fma(pr0.y, dA,  PKZERO);
            pk_t rB0 = pk_fma(pr0.x, sB_, brz);
            pk_t rB1 = pk_fma(pr0.y, dB,  PKZERO);
            #pragma unroll
            for (int k = 0; k < 16; k++) {
                ulonglong2 p = xr[1 + k];
                rA0 = pk_fma(p.x, hA[2 * k],     rA0);
                rA1 = pk_fma(p.y, hA[2 * k + 1], rA1);
                rB0 = pk_fma(p.x, hB[2 * k],     rB0);
                rB1 = pk_fma(p.y, hB[2 * k + 1], rB1);
            }
            float rp0, rp1, rp2, rp3;
            pk_unpack(pk_add(rA0, rA1), rp0, rp1);
            pk_unpack(pk_add(rB0, rB1), rp2, rp3);

            // z gate (folded)
            const ulonglong2* xz = (const ulonglong2*)(sW + (64 + j) * ROWLEN);
            ulonglong2 pz0 = xz[0];
            pk_t bz = sBrz[32 + j];
            pk_t zA0 = pk_fma(pz0.x, sA,  bz);
            pk_t zA1 = pk_fma(pz0.y, dA,  PKZERO);
            pk_t zB0 = pk_fma(pz0.x, sB_, bz);
            pk_t zB1 = pk_fma(pz0.y, dB,  PKZERO);
            #pragma unroll
            for (int k = 0; k < 16; k++) {
                ulonglong2 p = xz[1 + k];
                zA0 = pk_fma(p.x, hA[2 * k],     zA0);
                zA1 = pk_fma(p.y, hA[2 * k + 1], zA1);
                zB0 = pk_fma(p.x, hB[2 * k],     zB0);
                zB1 = pk_fma(p.y, hB[2 * k + 1], zB1);
            }
            float zp0, zp1, zp2, zp3;
            pk_unpack(pk_add(zA0, zA1), zp0, zp1);
            pk_unpack(pk_add(zB0, zB1), zp2, zp3);

            // n gate: i_n and h_n separate (n = tanh(i_n + r*h_n))
            const ulonglong2* xn  = (const ulonglong2*)(sW    + (96 + j) * ROWLEN);
            const ulonglong2* hnw = (const ulonglong2*)(sWhhn + j * HID);
            ulonglong2 pn0 = xn[0];
            pk_t bin = sBin[j], bhn = sBhn[j];
            pk_t inA0 = pk_fma(pn0.x, sA,  bin);
            pk_t inA1 = pk_fma(pn0.y, dA,  PKZERO);
            pk_t inB0 = pk_fma(pn0.x, sB_, bin);
            pk_t inB1 = pk_fma(pn0.y, dB,  PKZERO);
            pk_t hhA0 = bhn, hhA1 = PKZERO;
            pk_t hhB0 = bhn, hhB1 = PKZERO;
            #pragma unroll
            for (int k = 0; k < 16; k++) {
                ulonglong2 px = xn[1 + k];
                ulonglong2 ph = hnw[k];
                inA0 = pk_fma(px.x, hA[2 * k],     inA0);
                inA1 = pk_fma(px.y, hA[2 * k + 1], inA1);
                inB0 = pk_fma(px.x, hB[2 * k],     inB0);
                inB1 = pk_fma(px.y, hB[2 * k + 1], inB1);
                hhA0 = pk_fma(ph.x, hA[2 * k],     hhA0);
                hhA1 = pk_fma(ph.y, hA[2 * k + 1], hhA1);
                hhB0 = pk_fma(ph.x, hB[2 * k],     hhB0);
                hhB1 = pk_fma(ph.y, hB[2 * k + 1], hhB1);
            }
            float in0, in1, in2, in3, hh0, hh1, hh2, hh3;
            pk_unpack(pk_add(inA0, inA1), in0, in1);
            pk_unpack(pk_add(inB0, inB1), in2, in3);
            pk_unpack(pk_add(hhA0, hhA1), hh0, hh1);
            pk_unpack(pk_add(hhB0, hhB1), hh2, hh3);

            float hc0, hc1, hc2, hc3;
            pk_unpack(hA[j], hc0, hc1);
            pk_unpack(hB[j], hc2, hc3);

            float rg0 = sigmoid_fast(rp0), rg1 = sigmoid_fast(rp1);
            float rg2 = sigmoid_fast(rp2), rg3 = sigmoid_fast(rp3);
            float zg0 = sigmoid_fast(zp0), zg1 = sigmoid_fast(zp1);
            float zg2 = sigmoid_fast(zp2), zg3 = sigmoid_fast(zp3);
            float n0 = tanh_fast(fmaf(rg0, hh0, in0));
            float n1 = tanh_fast(fmaf(rg1, hh1, in1));
            float n2 = tanh_fast(fmaf(rg2, hh2, in2));
            float n3 = tanh_fast(fmaf(rg3, hh3, in3));
            float o0 = fmaf(zg0, hc0 - n0, n0);
            float o1 = fmaf(zg1, hc1 - n1, n1);
            float o2 = fmaf(zg2, hc2 - n2, n2);
            float o3 = fmaf(zg3, hc3 - n3, n3);

            sHn[j * TPB + tid]          = pk_pack(o0, o1);
            sHn[(32 + j) * TPB + tid]   = pk_pack(o2, o3);
        }

        // copy hn back into register h (conflict-free lane-contiguous LDS)
        #pragma unroll
        for (int k = 0; k < HID; k++) {
            hA[k] = sHn[k * TPB + tid];
            hB[k] = sHn[(32 + k) * TPB + tid];
        }

        out0[t]             = d0;
        out0[STEPS + t]     = d1;
        out0[2 * STEPS + t] = d2;
        out0[3 * STEPS + t] = d3;
        dA = pk_pack(d0, d1);
        dB = pk_pack(d2, d3);
    }
}

extern "C" void kernel_launch(void* const* d_in, const int* in_sizes, int n_in,
                              void* d_out, int out_size)
{
    (void)in_sizes; (void)n_in; (void)out_size;
    const float* S   = (const float*)d_in[0];
    const float* W1  = (const float*)d_in[1];
    const float* b1  = (const float*)d_in[2];
    const float* W2  = (const float*)d_in[3];
    const float* b2  = (const float*)d_in[4];
    const float* Wih = (const float*)d_in[5];
    const float* bih = (const float*)d_in[6];
    const float* Whh = (const float*)d_in[7];
    const float* bhh = (const float*)d_in[8];
    float* out = (float*)d_out;

    cudaFuncSetAttribute(hedge_kernel,
                         cudaFuncAttributeMaxDynamicSharedMemorySize, SMEM_BYTES);

    const int nthreads = BTOTAL / 4;          // 4 elements per thread
    dim3 grid(nthreads / TPB);                // 2048 blocks
    hedge_kernel<<<grid, TPB, SMEM_BYTES>>>(S, W1, b1, W2, b2,
                                            Wih, bih, Whh, bhh, out);
}

// round 7
// speedup vs baseline: 3.0177x; 1.4764x over previous
#include <cuda_runtime.h>
#include <cuda_bf16.h>
#include <cstdint>

// RecurrentHedgeModel via family-common tensor-core path (mma.sync bf16 HMMA).
// tcgen05 is rejected by this harness's PTX target (sm_103 non-'a'), so use
// mma.sync.m16n8k16 (sm_80+) + ldmatrix. Per warp: 16 batch rows, private
// X[16x48] bf16 hi/lo tile in SMEM, fused W[160x48] bf16 hi/lo shared.
// Per step: D[16x160] = X @ W^T via 20 Ntiles x 3 Kchunks x 3 hi/lo passes
// = 180 mma.sync, fp32 accum. Epilogue on C fragments in-register; delta by
// 2x shfl.bfly; h feedback via per-warp SMEM stores + __syncwarp only.
// W rows: 0-31 W1 | 32-95 folded r,z (Wih+Whh) | 96-127 Wih_n | 128-159 Whh_n
// X cols: 0-31 h | 32 s | 33 delta | 34 one | 35-47 zero

#define STEPS  30
#define SROW   31
#define BTOTAL 1048576
#define TPB    128
#define RPC    64          // rows per CTA (4 warps x 16)

// ---- smem map (bytes); row stride 96B = 48 bf16 ----
#define WHI_OFF 0
#define WLO_OFF 15360
#define W2_OFF  30720
#define X_OFF   30976      // 4 warps x (hi 1536 + lo 1536)
#define SMEM_TOTAL (30976 + 4 * 3072)

static __device__ __forceinline__ uint32_t smem_u32(const void* p) {
    uint32_t a;
    asm("{ .reg .u64 t; cvta.to.shared.u64 t, %1; cvt.u32.u64 %0, t; }"
        : "=r"(a) : "l"(p));
    return a;
}
#define STS32(addr, v) \
    asm volatile("st.shared.b32 [%0], %1;" :: "r"(addr), "r"(v) : "memory")

static __device__ __forceinline__ void ldsm4(uint32_t* r, uint32_t a) {
    asm volatile("ldmatrix.sync.aligned.m8n8.x4.shared.b16 {%0,%1,%2,%3}, [%4];"
                 : "=r"(r[0]), "=r"(r[1]), "=r"(r[2]), "=r"(r[3]) : "r"(a));
}
static __device__ __forceinline__ void ldsm2(uint32_t* r, uint32_t a) {
    asm volatile("ldmatrix.sync.aligned.m8n8.x2.shared.b16 {%0,%1}, [%2];"
                 : "=r"(r[0]), "=r"(r[1]) : "r"(a));
}
static __device__ __forceinline__ void mma_acc(float* d, const uint32_t* a,
                                               const uint32_t* b) {
    asm volatile("mma.sync.aligned.m16n8k16.row.col.f32.bf16.bf16.f32 "
                 "{%0,%1,%2,%3}, {%4,%5,%6,%7}, {%8,%9}, {%0,%1,%2,%3};"
                 : "+f"(d[0]), "+f"(d[1]), "+f"(d[2]), "+f"(d[3])
                 : "r"(a[0]), "r"(a[1]), "r"(a[2]), "r"(a[3]),
                   "r"(b[0]), "r"(b[1]));
}
static __device__ __forceinline__ void mma_zero(float* d, const uint32_t* a,
                                                const uint32_t* b) {
    asm volatile("mma.sync.aligned.m16n8k16.row.col.f32.bf16.bf16.f32 "
                 "{%0,%1,%2,%3}, {%4,%5,%6,%7}, {%8,%9}, {%10,%11,%12,%13};"
                 : "=f"(d[0]), "=f"(d[1]), "=f"(d[2]), "=f"(d[3])
                 : "r"(a[0]), "r"(a[1]), "r"(a[2]), "r"(a[3]),
                   "r"(b[0]), "r"(b[1]),
                   "f"(0.0f), "f"(0.0f), "f"(0.0f), "f"(0.0f));
}

static __device__ __forceinline__ float tanh_fast(float x) {
    float ax = fabsf(x);
    float u  = __expf(-2.0f * ax);
    float t  = __fdividef(1.0f - u, 1.0f + u);
    return copysignf(t, x);
}
static __device__ __forceinline__ float sigmoid_fast(float x) {
    return fmaf(tanh_fast(0.5f * x), 0.5f, 0.5f);
}
static __device__ __forceinline__ void split2(float x, __nv_bfloat16& hi,
                                              __nv_bfloat16& lo) {
    hi = __float2bfloat16(x);
    lo = __float2bfloat16(x - __bfloat162float(hi));
}
static __device__ __forceinline__ uint32_t packbf(__nv_bfloat16 a, __nv_bfloat16 b) {
    uint16_t ua = *(uint16_t*)&a, ub = *(uint16_t*)&b;
    return (uint32_t)ua | ((uint32_t)ub << 16);
}

__global__ __launch_bounds__(TPB, 2)
void hedge_mma(const float* __restrict__ S,
               const float* __restrict__ W1,  const float* __restrict__ b1,
               const float* __restrict__ W2,  const float* __restrict__ b2,
               const float* __restrict__ Wih, const float* __restrict__ bih,
               const float* __restrict__ Whh, const float* __restrict__ bhh,
               float* __restrict__ out)
{
    extern __shared__ __align__(128) unsigned char sm[];
    const int tid = threadIdx.x;
    const uint32_t smb = smem_u32(sm);
    __nv_bfloat16* Whi = (__nv_bfloat16*)(sm + WHI_OFF);  // [160][48]
    __nv_bfloat16* Wlo = (__nv_bfloat16*)(sm + WLO_OFF);
    float* w2f = (float*)(sm + W2_OFF);

    // ---- build fused hi/lo weight matrix ----
    for (int i = tid; i < 160 * 48; i += TPB) {
        int n = i / 48, k = i - n * 48;
        float w = 0.0f;
        if (k < 32) {
            if (n < 32)       w = W1[n * 34 + 2 + k];
            else if (n < 96)  { int g = n - 32; w = Wih[g * 34 + 2 + k] + Whh[g * 32 + k]; }
            else if (n < 128) { int g = n - 32; w = Wih[g * 34 + 2 + k]; }
            else              w = Whh[(64 + (n - 128)) * 32 + k];
        } else if (k == 32) {
            if (n < 32)       w = W1[n * 34 + 0];
            else if (n < 128) w = Wih[(n - 32) * 34 + 0];
        } else if (k == 33) {
            if (n < 32)       w = W1[n * 34 + 1];
            else if (n < 128) w = Wih[(n - 32) * 34 + 1];
        } else if (k == 34) {
            if (n < 32)       w = b1[n];
            else if (n < 96)  { int g = n - 32; w = bih[g] + bhh[g]; }
            else if (n < 128) w = bih[n - 32];
            else              w = bhh[64 + (n - 128)];
        }
        __nv_bfloat16 hi, lo; split2(w, hi, lo);
        Whi[i] = hi; Wlo[i] = lo;
    }
    if (tid < 32) w2f[tid] = W2[tid];
    if (tid == 0) w2f[32] = b2[0];
    // zero X tiles
    {
        uint32_t* xz = (uint32_t*)(sm + X_OFF);
        for (int i = tid; i < (4 * 3072) / 4; i += TPB) xz[i] = 0u;
    }
    __syncthreads();

    const int warp = tid >> 5, lane = tid & 31;
    const int c = lane & 3, rq = lane >> 2;   // column-lane, row-quad
    const uint32_t xhiB = smb + X_OFF + warp * 3072;
    const uint32_t xloB = xhiB + 1536;
    const int gbase = blockIdx.x * RPC + warp * 16;
    const int g0 = gbase + rq, g1 = g0 + 8;

    // per-lane W2 slice: cols 8q + 2c + e
    float w2r[8];
    #pragma unroll
    for (int q = 0; q < 4; q++) {
        w2r[2 * q]     = w2f[8 * q + 2 * c];
        w2r[2 * q + 1] = w2f[8 * q + 2 * c + 1];
    }
    const float b2v = w2f[32];
    const __nv_bfloat16 bf0 = __float2bfloat16(0.0f);

    // X chunk2 init: cols (32,33)=(s0,0) by c==0 lanes, (34,35)=(1,0) by c==1
    if (c == 0) {
        float s0 = S[(size_t)g0 * SROW], s1 = S[(size_t)g1 * SROW];
        __nv_bfloat16 h_, l_;
        split2(s0, h_, l_);
        STS32(xhiB + rq * 96 + 64, packbf(h_, bf0));
        STS32(xloB + rq * 96 + 64, packbf(l_, bf0));
        split2(s1, h_, l_);
        STS32(xhiB + (rq + 8) * 96 + 64, packbf(h_, bf0));
        STS32(xloB + (rq + 8) * 96 + 64, packbf(l_, bf0));
    } else if (c == 1) {
        __nv_bfloat16 one = __float2bfloat16(1.0f);
        STS32(xhiB + rq * 96 + 68, packbf(one, bf0));
        STS32(xhiB + (rq + 8) * 96 + 68, packbf(one, bf0));
    }
    __syncwarp();

    float hold[16];
    #pragma unroll
    for (int i = 0; i < 16; i++) hold[i] = 0.0f;

    const uint32_t aOffA = (uint32_t)((lane & 15) * 96 + (lane >> 4) * 16);
    const uint32_t bOff  = (uint32_t)((lane & 7) * 96 + ((lane >> 3) & 1) * 16);
    const uint32_t whiB = smb + WHI_OFF, wloB = smb + WLO_OFF;

    #pragma unroll 1
    for (int t = 0; t < STEPS; t++) {
        // A fragments: X hi and lo, 3 K-chunks
        uint32_t AH[3][4], AL[3][4];
        #pragma unroll
        for (int kc = 0; kc < 3; kc++) {
            ldsm4(AH[kc], xhiB + kc * 32 + aOffA);
            ldsm4(AL[kc], xloB + kc * 32 + aOffA);
        }

        float C[20][4];
        #pragma unroll
        for (int nt = 0; nt < 20; nt++) {
            uint32_t wrow = (uint32_t)(nt * 768) + bOff;
            uint32_t bh[2], bl[2];
            ldsm2(bh, whiB + wrow);
            ldsm2(bl, wloB + wrow);
            mma_zero(C[nt], AH[0], bh);
            mma_acc (C[nt], AH[0], bl);
            mma_acc (C[nt], AL[0], bh);
            ldsm2(bh, whiB + wrow + 32);
            ldsm2(bl, wloB + wrow + 32);
            mma_acc(C[nt], AH[1], bh);
            mma_acc(C[nt], AH[1], bl);
            mma_acc(C[nt], AL[1], bh);
            ldsm2(bh, whiB + wrow + 64);
            ldsm2(bl, wloB + wrow + 64);
            mma_acc(C[nt], AH[2], bh);
            mma_acc(C[nt], AH[2], bl);
            mma_acc(C[nt], AL[2], bh);
        }

        // ---- delta: b2 + sum_j relu(mlp_j) * w2_j  (tiles 0-3) ----
        float a0 = 0.0f, a1 = 0.0f;
        #pragma unroll
        for (int q = 0; q < 4; q++) {
            a0 = fmaf(fmaxf(C[q][0], 0.0f), w2r[2 * q],     a0);
            a0 = fmaf(fmaxf(C[q][1], 0.0f), w2r[2 * q + 1], a0);
            a1 = fmaf(fmaxf(C[q][2], 0.0f), w2r[2 * q],     a1);
            a1 = fmaf(fmaxf(C[q][3], 0.0f), w2r[2 * q + 1], a1);
        }
        a0 += __shfl_xor_sync(0xffffffffu, a0, 1);
        a0 += __shfl_xor_sync(0xffffffffu, a0, 2);
        a1 += __shfl_xor_sync(0xffffffffu, a1, 1);
        a1 += __shfl_xor_sync(0xffffffffu, a1, 2);
        float dl0 = b2v + a0, dl1 = b2v + a1;

        // ---- gates: r tiles 4-7, z 8-11, in 12-15, hh 16-19 ----
        #pragma unroll
        for (int q = 0; q < 4; q++) {
            // row half 0 (row rq): C[..][0..1]
            {
                float hv[2];
                #pragma unroll
                for (int e = 0; e < 2; e++) {
                    float rg = sigmoid_fast(C[4 + q][e]);
                    float zg = sigmoid_fast(C[8 + q][e]);
                    float nn = tanh_fast(fmaf(rg, C[16 + q][e], C[12 + q][e]));
                    float ho = hold[q * 4 + e];
                    float h2 = fmaf(zg, ho - nn, nn);
                    hold[q * 4 + e] = h2;
                    hv[e] = h2;
                }
                __nv_bfloat16 ah, al, bh_, bl_;
                split2(hv[0], ah, al); split2(hv[1], bh_, bl_);
                STS32(xhiB + rq * 96 + q * 16 + c * 4, packbf(ah, bh_));
                STS32(xloB + rq * 96 + q * 16 + c * 4, packbf(al, bl_));
            }
            // row half 1 (row rq+8): C[..][2..3]
            {
                float hv[2];
                #pragma unroll
                for (int e = 0; e < 2; e++) {
                    float rg = sigmoid_fast(C[4 + q][2 + e]);
                    float zg = sigmoid_fast(C[8 + q][2 + e]);
                    float nn = tanh_fast(fmaf(rg, C[16 + q][2 + e], C[12 + q][2 + e]));
                    float ho = hold[q * 4 + 2 + e];
                    float h2 = fmaf(zg, ho - nn, nn);
                    hold[q * 4 + 2 + e] = h2;
                    hv[e] = h2;
                }
                __nv_bfloat16 ah, al, bh_, bl_;
                split2(hv[0], ah, al); split2(hv[1], bh_, bl_);
                STS32(xhiB + (rq + 8) * 96 + q * 16 + c * 4, packbf(ah, bh_));
                STS32(xloB + (rq + 8) * 96 + q * 16 + c * 4, packbf(al, bl_));
            }
        }

        // ---- outputs + next-step (s, delta) columns ----
        if (c == 0) {
            out[(size_t)g0 * STEPS + t] = dl0;
            out[(size_t)g1 * STEPS + t] = dl1;
            float s0n = S[(size_t)g0 * SROW + t + 1];   // t+1 <= 30, valid
            float s1n = S[(size_t)g1 * SROW + t + 1];
            __nv_bfloat16 sh, sl, dh, dl_;
            split2(s0n, sh, sl); split2(dl0, dh, dl_);
            STS32(xhiB + rq * 96 + 64, packbf(sh, dh));
            STS32(xloB + rq * 96 + 64, packbf(sl, dl_));
            split2(s1n, sh, sl); split2(dl1, dh, dl_);
            STS32(xhiB + (rq + 8) * 96 + 64, packbf(sh, dh));
            STS32(xloB + (rq + 8) * 96 + 64, packbf(sl, dl_));
        }
        __syncwarp();
    }
}

extern "C" void kernel_launch(void* const* d_in, const int* in_sizes, int n_in,
                              void* d_out, int out_size)
{
    (void)in_sizes; (void)n_in; (void)out_size;
    const float* S   = (const float*)d_in[0];
    const float* W1  = (const float*)d_in[1];
    const float* b1  = (const float*)d_in[2];
    const float* W2  = (const float*)d_in[3];
    const float* b2  = (const float*)d_in[4];
    const float* Wih = (const float*)d_in[5];
    const float* bih = (const float*)d_in[6];
    const float* Whh = (const float*)d_in[7];
    const float* bhh = (const float*)d_in[8];
    float* out = (float*)d_out;

    cudaFuncSetAttribute(hedge_mma,
                         cudaFuncAttributeMaxDynamicSharedMemorySize, SMEM_TOTAL);

    dim3 grid(BTOTAL / RPC);   // 16384 CTAs, 64 rows each
    hedge_mma<<<grid, TPB, SMEM_TOTAL>>>(S, W1, b1, W2, b2, Wih, bih, Whh, bhh, out);
}

// round 8
// speedup vs baseline: 3.7655x; 1.2478x over previous
#include <cuda_runtime.h>
#include <cuda_bf16.h>
#include <cstdint>

// RecurrentHedgeModel via mma.sync bf16 HMMA (family-common path).
// Round 8: 32 batch rows per warp (2 row-blocks per mma) so the loop-invariant
// W fragments (120 ldsm2/step, the round-7 L1 bottleneck) are amortized over
// 2x rows. Register pressure controlled by q-grouped epilogue: only the 5
// column-tiles {q,q+4,q+8,q+12,q+16} (mlp/r/z/in/hh of cols 8q..8q+8) are
// live at once (40 C regs).
// W rows: 0-31 W1 | 32-95 folded r,z (Wih+Whh) | 96-127 Wih_n | 128-159 Whh_n
// X cols: 0-31 h | 32 s | 33 delta | 34 one | 35-47 zero

#define STEPS  30
#define SROW   31
#define BTOTAL 1048576
#define TPB    128
#define RPW    32          // rows per warp
#define RPC    128         // rows per CTA (4 warps x 32)

// ---- smem map (bytes); W row stride 96B = 48 bf16 ----
#define WHI_OFF 0
#define WLO_OFF 15360
#define W2_OFF  30720
#define X_OFF   30976      // 4 warps x (hi 3072 + lo 3072)
#define SMEM_TOTAL (30976 + 4 * 6144)

static __device__ __forceinline__ uint32_t smem_u32(const void* p) {
    uint32_t a;
    asm("{ .reg .u64 t; cvta.to.shared.u64 t, %1; cvt.u32.u64 %0, t; }"
        : "=r"(a) : "l"(p));
    return a;
}
#define STS32(addr, v) \
    asm volatile("st.shared.b32 [%0], %1;" :: "r"(addr), "r"(v) : "memory")

static __device__ __forceinline__ void ldsm4(uint32_t* r, uint32_t a) {
    asm volatile("ldmatrix.sync.aligned.m8n8.x4.shared.b16 {%0,%1,%2,%3}, [%4];"
                 : "=r"(r[0]), "=r"(r[1]), "=r"(r[2]), "=r"(r[3]) : "r"(a));
}
static __device__ __forceinline__ void ldsm2(uint32_t* r, uint32_t a) {
    asm volatile("ldmatrix.sync.aligned.m8n8.x2.shared.b16 {%0,%1}, [%2];"
                 : "=r"(r[0]), "=r"(r[1]) : "r"(a));
}
static __device__ __forceinline__ void mma_acc(float* d, const uint32_t* a,
                                               const uint32_t* b) {
    asm volatile("mma.sync.aligned.m16n8k16.row.col.f32.bf16.bf16.f32 "
                 "{%0,%1,%2,%3}, {%4,%5,%6,%7}, {%8,%9}, {%0,%1,%2,%3};"
                 : "+f"(d[0]), "+f"(d[1]), "+f"(d[2]), "+f"(d[3])
                 : "r"(a[0]), "r"(a[1]), "r"(a[2]), "r"(a[3]),
                   "r"(b[0]), "r"(b[1]));
}
static __device__ __forceinline__ void mma_zero(float* d, const uint32_t* a,
                                                const uint32_t* b) {
    asm volatile("mma.sync.aligned.m16n8k16.row.col.f32.bf16.bf16.f32 "
                 "{%0,%1,%2,%3}, {%4,%5,%6,%7}, {%8,%9}, {%10,%11,%12,%13};"
                 : "=f"(d[0]), "=f"(d[1]), "=f"(d[2]), "=f"(d[3])
                 : "r"(a[0]), "r"(a[1]), "r"(a[2]), "r"(a[3]),
                   "r"(b[0]), "r"(b[1]),
                   "f"(0.0f), "f"(0.0f), "f"(0.0f), "f"(0.0f));
}

static __device__ __forceinline__ float tanh_fast(float x) {
    float ax = fabsf(x);
    float u  = __expf(-2.0f * ax);
    float t  = __fdividef(1.0f - u, 1.0f + u);
    return copysignf(t, x);
}
static __device__ __forceinline__ float sigmoid_fast(float x) {
    return fmaf(tanh_fast(0.5f * x), 0.5f, 0.5f);
}
static __device__ __forceinline__ void split2(float x, __nv_bfloat16& hi,
                                              __nv_bfloat16& lo) {
    hi = __float2bfloat16(x);
    lo = __float2bfloat16(x - __bfloat162float(hi));
}
static __device__ __forceinline__ uint32_t packbf(__nv_bfloat16 a, __nv_bfloat16 b) {
    uint16_t ua = *(uint16_t*)&a, ub = *(uint16_t*)&b;
    return (uint32_t)ua | ((uint32_t)ub << 16);
}

__global__ __launch_bounds__(TPB, 2)
void hedge_mma(const float* __restrict__ S,
               const float* __restrict__ W1,  const float* __restrict__ b1,
               const float* __restrict__ W2,  const float* __restrict__ b2,
               const float* __restrict__ Wih, const float* __restrict__ bih,
               const float* __restrict__ Whh, const float* __restrict__ bhh,
               float* __restrict__ out)
{
    extern __shared__ __align__(128) unsigned char sm[];
    const int tid = threadIdx.x;
    const uint32_t smb = smem_u32(sm);
    __nv_bfloat16* Whi = (__nv_bfloat16*)(sm + WHI_OFF);  // [160][48]
    __nv_bfloat16* Wlo = (__nv_bfloat16*)(sm + WLO_OFF);
    float* w2f = (float*)(sm + W2_OFF);

    // ---- build fused hi/lo weight matrix ----
    for (int i = tid; i < 160 * 48; i += TPB) {
        int n = i / 48, k = i - n * 48;
        float w = 0.0f;
        if (k < 32) {
            if (n < 32)       w = W1[n * 34 + 2 + k];
            else if (n < 96)  { int g = n - 32; w = Wih[g * 34 + 2 + k] + Whh[g * 32 + k]; }
            else if (n < 128) { int g = n - 32; w = Wih[g * 34 + 2 + k]; }
            else              w = Whh[(64 + (n - 128)) * 32 + k];
        } else if (k == 32) {
            if (n < 32)       w = W1[n * 34 + 0];
            else if (n < 128) w = Wih[(n - 32) * 34 + 0];
        } else if (k == 33) {
            if (n < 32)       w = W1[n * 34 + 1];
            else if (n < 128) w = Wih[(n - 32) * 34 + 1];
        } else if (k == 34) {
            if (n < 32)       w = b1[n];
            else if (n < 96)  { int g = n - 32; w = bih[g] + bhh[g]; }
            else if (n < 128) w = bih[n - 32];
            else              w = bhh[64 + (n - 128)];
        }
        __nv_bfloat16 hi, lo; split2(w, hi, lo);
        Whi[i] = hi; Wlo[i] = lo;
    }
    if (tid < 32) w2f[tid] = W2[tid];
    if (tid == 0) w2f[32] = b2[0];
    // zero X tiles
    {
        uint32_t* xz = (uint32_t*)(sm + X_OFF);
        for (int i = tid; i < (4 * 6144) / 4; i += TPB) xz[i] = 0u;
    }
    __syncthreads();

    const int warp = tid >> 5, lane = tid & 31;
    const int c = lane & 3, rq = lane >> 2;   // column-lane, row-quad
    const uint32_t xhiB = smb + X_OFF + warp * 6144;   // [32][48] bf16
    const uint32_t xloB = xhiB + 3072;
    const int gbase = blockIdx.x * RPC + warp * RPW;

    // per-lane W2 slice: group q covers cols 8q+2c+{0,1}
    float w2r[8];
    #pragma unroll
    for (int q = 0; q < 4; q++) {
        w2r[2 * q]     = w2f[8 * q + 2 * c];
        w2r[2 * q + 1] = w2f[8 * q + 2 * c + 1];
    }
    const float b2v = w2f[32];
    const __nv_bfloat16 bf0 = __float2bfloat16(0.0f);
    const __nv_bfloat16 one = __float2bfloat16(1.0f);

    // X init: row = lane, cols 32..35 = [s0, 0, 1, 0]
    {
        float s0 = S[(size_t)(gbase + lane) * SROW];
        __nv_bfloat16 h_, l_; split2(s0, h_, l_);
        uint32_t ra = (uint32_t)lane * 96u;
        STS32(xhiB + ra + 64, packbf(h_, bf0));
        STS32(xhiB + ra + 68, packbf(one, bf0));
        STS32(xloB + ra + 64, packbf(l_, bf0));
    }

    float hold[32];
    #pragma unroll
    for (int i = 0; i < 32; i++) hold[i] = 0.0f;

    const uint32_t aOff = (uint32_t)((lane & 15) * 96 + (lane >> 4) * 16);
    const uint32_t bOff = (uint32_t)((lane & 7) * 96 + ((lane >> 3) & 1) * 16);
    const uint32_t whiB = smb + WHI_OFF, wloB = smb + WLO_OFF;

    #pragma unroll 1
    for (int t = 0; t < STEPS; t++) {
        __syncwarp();
        // A fragments: 2 rowblocks x 3 K-chunks, hi and lo
        uint32_t AH[2][3][4], AL[2][3][4];
        #pragma unroll
        for (int rb = 0; rb < 2; rb++) {
            #pragma unroll
            for (int kc = 0; kc < 3; kc++) {
                ldsm4(AH[rb][kc], xhiB + rb * 1536 + kc * 32 + aOff);
                ldsm4(AL[rb][kc], xloB + rb * 1536 + kc * 32 + aOff);
            }
        }

        float acc[4] = {0.0f, 0.0f, 0.0f, 0.0f};  // delta partials, 4 rows/lane

        #pragma unroll
        for (int q = 0; q < 4; q++) {
            float C[5][2][4];
            #pragma unroll
            for (int ti = 0; ti < 5; ti++) {
                uint32_t wrow = (uint32_t)((q + 4 * ti) * 768) + bOff;
                uint32_t bh[2], bl[2];
                ldsm2(bh, whiB + wrow);
                ldsm2(bl, wloB + wrow);
                #pragma unroll
                for (int rb = 0; rb < 2; rb++) {
                    mma_zero(C[ti][rb], AH[rb][0], bh);
                    mma_acc (C[ti][rb], AH[rb][0], bl);
                    mma_acc (C[ti][rb], AL[rb][0], bh);
                }
                ldsm2(bh, whiB + wrow + 32);
                ldsm2(bl, wloB + wrow + 32);
                #pragma unroll
                for (int rb = 0; rb < 2; rb++) {
                    mma_acc(C[ti][rb], AH[rb][1], bh);
                    mma_acc(C[ti][rb], AH[rb][1], bl);
                    mma_acc(C[ti][rb], AL[rb][1], bh);
                }
                ldsm2(bh, whiB + wrow + 64);
                ldsm2(bl, wloB + wrow + 64);
                #pragma unroll
                for (int rb = 0; rb < 2; rb++) {
                    mma_acc(C[ti][rb], AH[rb][2], bh);
                    mma_acc(C[ti][rb], AH[rb][2], bl);
                    mma_acc(C[ti][rb], AL[rb][2], bh);
                }
            }

            // epilogue for cols 8q+2c+{0,1}: C[0]=mlp, C[1]=r, C[2]=z,
            // C[3]=i_n, C[4]=h_n
            #pragma unroll
            for (int rb = 0; rb < 2; rb++) {
                #pragma unroll
                for (int hf = 0; hf < 2; hf++) {
                    float m0 = C[0][rb][hf * 2], m1 = C[0][rb][hf * 2 + 1];
                    acc[rb * 2 + hf] = fmaf(fmaxf(m0, 0.0f), w2r[2 * q],
                                       fmaf(fmaxf(m1, 0.0f), w2r[2 * q + 1],
                                            acc[rb * 2 + hf]));
                    float hv[2];
                    #pragma unroll
                    for (int e = 0; e < 2; e++) {
                        float rg = sigmoid_fast(C[1][rb][hf * 2 + e]);
                        float zg = sigmoid_fast(C[2][rb][hf * 2 + e]);
                        float nn = tanh_fast(fmaf(rg, C[4][rb][hf * 2 + e],
                                                  C[3][rb][hf * 2 + e]));
                        int hx = q * 8 + rb * 4 + hf * 2 + e;
                        float h2 = fmaf(zg, hold[hx] - nn, nn);
                        hold[hx] = h2;
                        hv[e] = h2;
                    }
                    __nv_bfloat16 ah, al, bh_, bl_;
                    split2(hv[0], ah, al); split2(hv[1], bh_, bl_);
                    uint32_t ra = (uint32_t)((rb * 16 + rq + hf * 8) * 96 + q * 16 + c * 4);
                    STS32(xhiB + ra, packbf(ah, bh_));
                    STS32(xloB + ra, packbf(al, bl_));
                }
            }
        }

        // delta: reduce over the 4-lane column group
        #pragma unroll
        for (int i = 0; i < 4; i++) {
            acc[i] += __shfl_xor_sync(0xffffffffu, acc[i], 1);
            acc[i] += __shfl_xor_sync(0xffffffffu, acc[i], 2);
            acc[i] += b2v;
        }

        if (c == 0) {
            #pragma unroll
            for (int rb = 0; rb < 2; rb++) {
                #pragma unroll
                for (int hf = 0; hf < 2; hf++) {
                    int r = rb * 16 + rq + hf * 8;
                    int grow = gbase + r;
                    float dl = acc[rb * 2 + hf];
                    out[(size_t)grow * STEPS + t] = dl;
                    float sn = S[(size_t)grow * SROW + t + 1];
                    __nv_bfloat16 sh, sl, dh, dl_;
                    split2(sn, sh, sl); split2(dl, dh, dl_);
                    uint32_t ra = (uint32_t)(r * 96 + 64);
                    STS32(xhiB + ra, packbf(sh, dh));
                    STS32(xloB + ra, packbf(sl, dl_));
                }
            }
        }
    }
}

extern "C" void kernel_launch(void* const* d_in, const int* in_sizes, int n_in,
                              void* d_out, int out_size)
{
    (void)in_sizes; (void)n_in; (void)out_size;
    const float* S   = (const float*)d_in[0];
    const float* W1  = (const float*)d_in[1];
    const float* b1  = (const float*)d_in[2];
    const float* W2  = (const float*)d_in[3];
    const float* b2  = (const float*)d_in[4];
    const float* Wih = (const float*)d_in[5];
    const float* bih = (const float*)d_in[6];
    const float* Whh = (const float*)d_in[7];
    const float* bhh = (const float*)d_in[8];
    float* out = (float*)d_out;

    cudaFuncSetAttribute(hedge_mma,
                         cudaFuncAttributeMaxDynamicSharedMemorySize, SMEM_TOTAL);

    dim3 grid(BTOTAL / RPC);   // 8192 CTAs, 128 rows each
    hedge_mma<<<grid, TPB, SMEM_TOTAL>>>(S, W1, b1, W2, b2, Wih, bih, Whh, bhh, out);
}

// round 9
// speedup vs baseline: 3.8835x; 1.0313x over previous
#include <cuda_runtime.h>
#include <cuda_bf16.h>
#include <cstdint>

// RecurrentHedgeModel via mma.sync bf16 HMMA (family-common path).
// Round 9: same 32-rows/warp scheme as round 8 (tensor=56%, issue=45%,
// 2 CTAs/SM). Buy a 3rd CTA/SM: drop the 32-reg hold[] (re-read h_old from
// the X SMEM tile, hi+lo reconstruct) + __launch_bounds__(128,3) -> ~170 regs,
// 12 warps/SM, covering the HMMA/LDS latency that capped issue at 45%.
// W rows: 0-31 W1 | 32-95 folded r,z (Wih+Whh) | 96-127 Wih_n | 128-159 Whh_n
// X cols: 0-31 h | 32 s | 33 delta | 34 one | 35-47 zero

#define STEPS  30
#define SROW   31
#define BTOTAL 1048576
#define TPB    128
#define RPW    32          // rows per warp
#define RPC    128         // rows per CTA (4 warps x 32)

// ---- smem map (bytes); W row stride 96B = 48 bf16 ----
#define WHI_OFF 0
#define WLO_OFF 15360
#define W2_OFF  30720
#define X_OFF   30976      // 4 warps x (hi 3072 + lo 3072)
#define SMEM_TOTAL (30976 + 4 * 6144)

static __device__ __forceinline__ uint32_t smem_u32(const void* p) {
    uint32_t a;
    asm("{ .reg .u64 t; cvta.to.shared.u64 t, %1; cvt.u32.u64 %0, t; }"
        : "=r"(a) : "l"(p));
    return a;
}
#define STS32(addr, v) \
    asm volatile("st.shared.b32 [%0], %1;" :: "r"(addr), "r"(v) : "memory")
#define LDS32(v, addr) \
    asm volatile("ld.shared.b32 %0, [%1];" : "=r"(v) : "r"(addr))

static __device__ __forceinline__ void ldsm4(uint32_t* r, uint32_t a) {
    asm volatile("ldmatrix.sync.aligned.m8n8.x4.shared.b16 {%0,%1,%2,%3}, [%4];"
                 : "=r"(r[0]), "=r"(r[1]), "=r"(r[2]), "=r"(r[3]) : "r"(a));
}
static __device__ __forceinline__ void ldsm2(uint32_t* r, uint32_t a) {
    asm volatile("ldmatrix.sync.aligned.m8n8.x2.shared.b16 {%0,%1}, [%2];"
                 : "=r"(r[0]), "=r"(r[1]) : "r"(a));
}
static __device__ __forceinline__ void mma_acc(float* d, const uint32_t* a,
                                               const uint32_t* b) {
    asm volatile("mma.sync.aligned.m16n8k16.row.col.f32.bf16.bf16.f32 "
                 "{%0,%1,%2,%3}, {%4,%5,%6,%7}, {%8,%9}, {%0,%1,%2,%3};"
                 : "+f"(d[0]), "+f"(d[1]), "+f"(d[2]), "+f"(d[3])
                 : "r"(a[0]), "r"(a[1]), "r"(a[2]), "r"(a[3]),
                   "r"(b[0]), "r"(b[1]));
}
static __device__ __forceinline__ void mma_zero(float* d, const uint32_t* a,
                                                const uint32_t* b) {
    asm volatile("mma.sync.aligned.m16n8k16.row.col.f32.bf16.bf16.f32 "
                 "{%0,%1,%2,%3}, {%4,%5,%6,%7}, {%8,%9}, {%10,%11,%12,%13};"
                 : "=f"(d[0]), "=f"(d[1]), "=f"(d[2]), "=f"(d[3])
                 : "r"(a[0]), "r"(a[1]), "r"(a[2]), "r"(a[3]),
                   "r"(b[0]), "r"(b[1]),
                   "f"(0.0f), "f"(0.0f), "f"(0.0f), "f"(0.0f));
}

static __device__ __forceinline__ float tanh_fast(float x) {
    float ax = fabsf(x);
    float u  = __expf(-2.0f * ax);
    float t  = __fdividef(1.0f - u, 1.0f + u);
    return copysignf(t, x);
}
static __device__ __forceinline__ float sigmoid_fast(float x) {
    return fmaf(tanh_fast(0.5f * x), 0.5f, 0.5f);
}
static __device__ __forceinline__ void split2(float x, __nv_bfloat16& hi,
                                              __nv_bfloat16& lo) {
    hi = __float2bfloat16(x);
    lo = __float2bfloat16(x - __bfloat162float(hi));
}
static __device__ __forceinline__ uint32_t packbf(__nv_bfloat16 a, __nv_bfloat16 b) {
    uint16_t ua = *(uint16_t*)&a, ub = *(uint16_t*)&b;
    return (uint32_t)ua | ((uint32_t)ub << 16);
}
static __device__ __forceinline__ float2 bf2f(uint32_t v) {
    __nv_bfloat162 b = *reinterpret_cast<__nv_bfloat162*>(&v);
    return __bfloat1622float2(b);
}

__global__ __launch_bounds__(TPB, 3)
void hedge_mma(const float* __restrict__ S,
               const float* __restrict__ W1,  const float* __restrict__ b1,
               const float* __restrict__ W2,  const float* __restrict__ b2,
               const float* __restrict__ Wih, const float* __restrict__ bih,
               const float* __restrict__ Whh, const float* __restrict__ bhh,
               float* __restrict__ out)
{
    extern __shared__ __align__(128) unsigned char sm[];
    const int tid = threadIdx.x;
    const uint32_t smb = smem_u32(sm);
    __nv_bfloat16* Whi = (__nv_bfloat16*)(sm + WHI_OFF);  // [160][48]
    __nv_bfloat16* Wlo = (__nv_bfloat16*)(sm + WLO_OFF);
    float* w2f = (float*)(sm + W2_OFF);

    // ---- build fused hi/lo weight matrix ----
    for (int i = tid; i < 160 * 48; i += TPB) {
        int n = i / 48, k = i - n * 48;
        float w = 0.0f;
        if (k < 32) {
            if (n < 32)       w = W1[n * 34 + 2 + k];
            else if (n < 96)  { int g = n - 32; w = Wih[g * 34 + 2 + k] + Whh[g * 32 + k]; }
            else if (n < 128) { int g = n - 32; w = Wih[g * 34 + 2 + k]; }
            else              w = Whh[(64 + (n - 128)) * 32 + k];
        } else if (k == 32) {
            if (n < 32)       w = W1[n * 34 + 0];
            else if (n < 128) w = Wih[(n - 32) * 34 + 0];
        } else if (k == 33) {
            if (n < 32)       w = W1[n * 34 + 1];
            else if (n < 128) w = Wih[(n - 32) * 34 + 1];
        } else if (k == 34) {
            if (n < 32)       w = b1[n];
            else if (n < 96)  { int g = n - 32; w = bih[g] + bhh[g]; }
            else if (n < 128) w = bih[n - 32];
            else              w = bhh[64 + (n - 128)];
        }
        __nv_bfloat16 hi, lo; split2(w, hi, lo);
        Whi[i] = hi; Wlo[i] = lo;
    }
    if (tid < 32) w2f[tid] = W2[tid];
    if (tid == 0) w2f[32] = b2[0];
    // zero X tiles
    {
        uint32_t* xz = (uint32_t*)(sm + X_OFF);
        for (int i = tid; i < (4 * 6144) / 4; i += TPB) xz[i] = 0u;
    }
    __syncthreads();

    const int warp = tid >> 5, lane = tid & 31;
    const int c = lane & 3, rq = lane >> 2;   // column-lane, row-quad
    const uint32_t xhiB = smb + X_OFF + warp * 6144;   // [32][48] bf16
    const uint32_t xloB = xhiB + 3072;
    const int gbase = blockIdx.x * RPC + warp * RPW;

    // per-lane W2 slice: group q covers cols 8q+2c+{0,1}
    float w2r[8];
    #pragma unroll
    for (int q = 0; q < 4; q++) {
        w2r[2 * q]     = w2f[8 * q + 2 * c];
        w2r[2 * q + 1] = w2f[8 * q + 2 * c + 1];
    }
    const float b2v = w2f[32];
    const __nv_bfloat16 bf0 = __float2bfloat16(0.0f);
    const __nv_bfloat16 one = __float2bfloat16(1.0f);

    // X init: row = lane, cols 32..35 = [s0, 0, 1, 0]
    {
        float s0 = S[(size_t)(gbase + lane) * SROW];
        __nv_bfloat16 h_, l_; split2(s0, h_, l_);
        uint32_t ra = (uint32_t)lane * 96u;
        STS32(xhiB + ra + 64, packbf(h_, bf0));
        STS32(xhiB + ra + 68, packbf(one, bf0));
        STS32(xloB + ra + 64, packbf(l_, bf0));
    }

    const uint32_t aOff = (uint32_t)((lane & 15) * 96 + (lane >> 4) * 16);
    const uint32_t bOff = (uint32_t)((lane & 7) * 96 + ((lane >> 3) & 1) * 16);
    const uint32_t whiB = smb + WHI_OFF, wloB = smb + WLO_OFF;

    #pragma unroll 1
    for (int t = 0; t < STEPS; t++) {
        __syncwarp();
        // A fragments: 2 rowblocks x 3 K-chunks, hi and lo
        uint32_t AH[2][3][4], AL[2][3][4];
        #pragma unroll
        for (int rb = 0; rb < 2; rb++) {
            #pragma unroll
            for (int kc = 0; kc < 3; kc++) {
                ldsm4(AH[rb][kc], xhiB + rb * 1536 + kc * 32 + aOff);
                ldsm4(AL[rb][kc], xloB + rb * 1536 + kc * 32 + aOff);
            }
        }

        float acc[4] = {0.0f, 0.0f, 0.0f, 0.0f};  // delta partials, 4 rows/lane

        #pragma unroll
        for (int q = 0; q < 4; q++) {
            float C[5][2][4];
            #pragma unroll
            for (int ti = 0; ti < 5; ti++) {
                uint32_t wrow = (uint32_t)((q + 4 * ti) * 768) + bOff;
                uint32_t bh[2], bl[2];
                ldsm2(bh, whiB + wrow);
                ldsm2(bl, wloB + wrow);
                #pragma unroll
                for (int rb = 0; rb < 2; rb++) {
                    mma_zero(C[ti][rb], AH[rb][0], bh);
                    mma_acc (C[ti][rb], AH[rb][0], bl);
                    mma_acc (C[ti][rb], AL[rb][0], bh);
                }
                ldsm2(bh, whiB + wrow + 32);
                ldsm2(bl, wloB + wrow + 32);
                #pragma unroll
                for (int rb = 0; rb < 2; rb++) {
                    mma_acc(C[ti][rb], AH[rb][1], bh);
                    mma_acc(C[ti][rb], AH[rb][1], bl);
                    mma_acc(C[ti][rb], AL[rb][1], bh);
                }
                ldsm2(bh, whiB + wrow + 64);
                ldsm2(bl, wloB + wrow + 64);
                #pragma unroll
                for (int rb = 0; rb < 2; rb++) {
                    mma_acc(C[ti][rb], AH[rb][2], bh);
                    mma_acc(C[ti][rb], AH[rb][2], bl);
                    mma_acc(C[ti][rb], AL[rb][2], bh);
                }
            }

            // epilogue for cols 8q+2c+{0,1}: C[0]=mlp, C[1]=r, C[2]=z,
            // C[3]=i_n, C[4]=h_n.  h_old re-read from the X tile (hi+lo).
            #pragma unroll
            for (int rb = 0; rb < 2; rb++) {
                #pragma unroll
                for (int hf = 0; hf < 2; hf++) {
                    float m0 = C[0][rb][hf * 2], m1 = C[0][rb][hf * 2 + 1];
                    acc[rb * 2 + hf] = fmaf(fmaxf(m0, 0.0f), w2r[2 * q],
                                       fmaf(fmaxf(m1, 0.0f), w2r[2 * q + 1],
                                            acc[rb * 2 + hf]));
                    uint32_t ra = (uint32_t)((rb * 16 + rq + hf * 8) * 96
                                             + q * 16 + c * 4);
                    uint32_t ohi, olo;
                    LDS32(ohi, xhiB + ra);
                    LDS32(olo, xloB + ra);
                    float2 fh = bf2f(ohi), fl = bf2f(olo);
                    float hold0 = fh.x + fl.x, hold1 = fh.y + fl.y;

                    float hv[2];
                    #pragma unroll
                    for (int e = 0; e < 2; e++) {
                        float rg = sigmoid_fast(C[1][rb][hf * 2 + e]);
                        float zg = sigmoid_fast(C[2][rb][hf * 2 + e]);
                        float nn = tanh_fast(fmaf(rg, C[4][rb][hf * 2 + e],
                                                  C[3][rb][hf * 2 + e]));
                        float ho = (e == 0) ? hold0 : hold1;
                        hv[e] = fmaf(zg, ho - nn, nn);
                    }
                    __nv_bfloat16 ah, al, bh_, bl_;
                    split2(hv[0], ah, al); split2(hv[1], bh_, bl_);
                    STS32(xhiB + ra, packbf(ah, bh_));
                    STS32(xloB + ra, packbf(al, bl_));
                }
            }
        }

        // delta: reduce over the 4-lane column group
        #pragma unroll
        for (int i = 0; i < 4; i++) {
            acc[i] += __shfl_xor_sync(0xffffffffu, acc[i], 1);
            acc[i] += __shfl_xor_sync(0xffffffffu, acc[i], 2);
            acc[i] += b2v;
        }

        if (c == 0) {
            #pragma unroll
            for (int rb = 0; rb < 2; rb++) {
                #pragma unroll
                for (int hf = 0; hf < 2; hf++) {
                    int r = rb * 16 + rq + hf * 8;
                    int grow = gbase + r;
                    float dl = acc[rb * 2 + hf];
                    out[(size_t)grow * STEPS + t] = dl;
                    float sn = S[(size_t)grow * SROW + t + 1];   // t+1 <= 30, valid
                    __nv_bfloat16 sh, sl, dh, dl_;
                    split2(sn, sh, sl); split2(dl, dh, dl_);
                    uint32_t ra = (uint32_t)(r * 96 + 64);
                    STS32(xhiB + ra, packbf(sh, dh));
                    STS32(xloB + ra, packbf(sl, dl_));
                }
            }
        }
    }
}

extern "C" void kernel_launch(void* const* d_in, const int* in_sizes, int n_in,
                              void* d_out, int out_size)
{
    (void)in_sizes; (void)n_in; (void)out_size;
    const float* S   = (const float*)d_in[0];
    const float* W1  = (const float*)d_in[1];
    const float* b1  = (const float*)d_in[2];
    const float* W2  = (const float*)d_in[3];
    const float* b2  = (const float*)d_in[4];
    const float* Wih = (const float*)d_in[5];
    const float* bih = (const float*)d_in[6];
    const float* Whh = (const float*)d_in[7];
    const float* bhh = (const float*)d_in[8];
    float* out = (float*)d_out;

    cudaFuncSetAttribute(hedge_mma,
                         cudaFuncAttributeMaxDynamicSharedMemorySize, SMEM_TOTAL);

    dim3 grid(BTOTAL / RPC);   // 8192 CTAs, 128 rows each
    hedge_mma<<<grid, TPB, SMEM_TOTAL>>>(S, W1, b1, W2, b2, Wih, bih, Whh, bhh, out);
}

// round 10
// speedup vs baseline: 4.1083x; 1.0579x over previous
#include <cuda_runtime.h>
#include <cuda_bf16.h>
#include <cstdint>

// RecurrentHedgeModel via mma.sync bf16 HMMA (family-common path).
// Round 10: the K=32..47 chunk of X is just [s, delta, 1] -> replace its
// 120 HMMA + 40 ldsm2 per warp-step (33% of tensor work) with an exact fp32
// rank-3 epilogue update C += s*ws + delta*wd + b from a float4 LUT in SMEM.
// X/W tiles shrink to K=32 (h only), 80B pitch (conflict-free ldsm).
// W rows: 0-31 W1 | 32-95 folded r,z (Wih+Whh) | 96-127 Wih_n | 128-159 Whh_n

#define STEPS  30
#define SROW   31
#define BTOTAL 1048576
#define TPB    128
#define RPW    32          // rows per warp
#define RPC    128         // rows per CTA (4 warps x 32)

// ---- smem map (bytes); W/X row pitch 80B = 40 bf16 (32 used) ----
#define WHI_OFF 0              // [160][40] bf16
#define WLO_OFF 12800
#define CST_OFF 25600          // [160] float4 {ws, wd, b, 0}
#define W2_OFF  28160          // 33 floats
#define SD_OFF  28304          // 4 warps x [32] float2 {s_t, delta_{t-1}}
#define X_OFF   29440          // 4 warps x (hi 2560 + lo 2560)
#define SMEM_TOTAL (29440 + 4 * 5120)

static __device__ __forceinline__ uint32_t smem_u32(const void* p) {
    uint32_t a;
    asm("{ .reg .u64 t; cvta.to.shared.u64 t, %1; cvt.u32.u64 %0, t; }"
        : "=r"(a) : "l"(p));
    return a;
}
#define STS32(addr, v) \
    asm volatile("st.shared.b32 [%0], %1;" :: "r"(addr), "r"(v) : "memory")
#define LDS32(v, addr) \
    asm volatile("ld.shared.b32 %0, [%1];" : "=r"(v) : "r"(addr))
#define LDS128F(f4, addr) \
    asm volatile("ld.shared.v4.f32 {%0,%1,%2,%3}, [%4];" \
                 : "=f"((f4).x), "=f"((f4).y), "=f"((f4).z), "=f"((f4).w) \
                 : "r"(addr))
#define LDS64F(f2, addr) \
    asm volatile("ld.shared.v2.f32 {%0,%1}, [%2];" \
                 : "=f"((f2).x), "=f"((f2).y) : "r"(addr))
#define STS64F(addr, a, b) \
    asm volatile("st.shared.v2.f32 [%0], {%1, %2};" \
                 :: "r"(addr), "f"(a), "f"(b) : "memory")

static __device__ __forceinline__ void ldsm4(uint32_t* r, uint32_t a) {
    asm volatile("ldmatrix.sync.aligned.m8n8.x4.shared.b16 {%0,%1,%2,%3}, [%4];"
                 : "=r"(r[0]), "=r"(r[1]), "=r"(r[2]), "=r"(r[3]) : "r"(a));
}
static __device__ __forceinline__ void ldsm2(uint32_t* r, uint32_t a) {
    asm volatile("ldmatrix.sync.aligned.m8n8.x2.shared.b16 {%0,%1}, [%2];"
                 : "=r"(r[0]), "=r"(r[1]) : "r"(a));
}
static __device__ __forceinline__ void mma_acc(float* d, const uint32_t* a,
                                               const uint32_t* b) {
    asm volatile("mma.sync.aligned.m16n8k16.row.col.f32.bf16.bf16.f32 "
                 "{%0,%1,%2,%3}, {%4,%5,%6,%7}, {%8,%9}, {%0,%1,%2,%3};"
                 : "+f"(d[0]), "+f"(d[1]), "+f"(d[2]), "+f"(d[3])
                 : "r"(a[0]), "r"(a[1]), "r"(a[2]), "r"(a[3]),
                   "r"(b[0]), "r"(b[1]));
}
static __device__ __forceinline__ void mma_zero(float* d, const uint32_t* a,
                                                const uint32_t* b) {
    asm volatile("mma.sync.aligned.m16n8k16.row.col.f32.bf16.bf16.f32 "
                 "{%0,%1,%2,%3}, {%4,%5,%6,%7}, {%8,%9}, {%10,%11,%12,%13};"
                 : "=f"(d[0]), "=f"(d[1]), "=f"(d[2]), "=f"(d[3])
                 : "r"(a[0]), "r"(a[1]), "r"(a[2]), "r"(a[3]),
                   "r"(b[0]), "r"(b[1]),
                   "f"(0.0f), "f"(0.0f), "f"(0.0f), "f"(0.0f));
}

static __device__ __forceinline__ float tanh_fast(float x) {
    float ax = fabsf(x);
    float u  = __expf(-2.0f * ax);
    float t  = __fdividef(1.0f - u, 1.0f + u);
    return copysignf(t, x);
}
static __device__ __forceinline__ float sigmoid_fast(float x) {
    return fmaf(tanh_fast(0.5f * x), 0.5f, 0.5f);
}
static __device__ __forceinline__ void split2(float x, __nv_bfloat16& hi,
                                              __nv_bfloat16& lo) {
    hi = __float2bfloat16(x);
    lo = __float2bfloat16(x - __bfloat162float(hi));
}
static __device__ __forceinline__ uint32_t packbf(__nv_bfloat16 a, __nv_bfloat16 b) {
    uint16_t ua = *(uint16_t*)&a, ub = *(uint16_t*)&b;
    return (uint32_t)ua | ((uint32_t)ub << 16);
}
static __device__ __forceinline__ float2 bf2f(uint32_t v) {
    __nv_bfloat162 b = *reinterpret_cast<__nv_bfloat162*>(&v);
    return __bfloat1622float2(b);
}

__global__ __launch_bounds__(TPB, 3)
void hedge_mma(const float* __restrict__ S,
               const float* __restrict__ W1,  const float* __restrict__ b1,
               const float* __restrict__ W2,  const float* __restrict__ b2,
               const float* __restrict__ Wih, const float* __restrict__ bih,
               const float* __restrict__ Whh, const float* __restrict__ bhh,
               float* __restrict__ out)
{
    extern __shared__ __align__(128) unsigned char sm[];
    const int tid = threadIdx.x;
    const uint32_t smb = smem_u32(sm);
    __nv_bfloat16* Whi = (__nv_bfloat16*)(sm + WHI_OFF);  // [160][40]
    __nv_bfloat16* Wlo = (__nv_bfloat16*)(sm + WLO_OFF);
    float4* cst = (float4*)(sm + CST_OFF);                // [160]
    float* w2f = (float*)(sm + W2_OFF);

    // ---- fused hi/lo weight matrix (h columns only, K=32, pitch 40) ----
    for (int i = tid; i < 160 * 32; i += TPB) {
        int n = i >> 5, k = i & 31;
        float w;
        if (n < 32)       w = W1[n * 34 + 2 + k];
        else if (n < 96)  { int g = n - 32; w = Wih[g * 34 + 2 + k] + Whh[g * 32 + k]; }
        else if (n < 128) { int g = n - 32; w = Wih[g * 34 + 2 + k]; }
        else              w = Whh[(64 + (n - 128)) * 32 + k];
        __nv_bfloat16 hi, lo; split2(w, hi, lo);
        Whi[n * 40 + k] = hi; Wlo[n * 40 + k] = lo;
    }
    // ---- rank-3 LUT: {ws, wd, b} per output col, exact fp32 ----
    for (int n = tid; n < 160; n += TPB) {
        float ws = 0.0f, wd = 0.0f, bb;
        if (n < 32)       { ws = W1[n * 34];  wd = W1[n * 34 + 1];  bb = b1[n]; }
        else if (n < 96)  { int g = n - 32; ws = Wih[g * 34]; wd = Wih[g * 34 + 1];
                            bb = bih[g] + bhh[g]; }
        else if (n < 128) { int g = n - 32; ws = Wih[g * 34]; wd = Wih[g * 34 + 1];
                            bb = bih[g]; }
        else              bb = bhh[64 + (n - 128)];
        cst[n] = make_float4(ws, wd, bb, 0.0f);
    }
    if (tid < 32) w2f[tid] = W2[tid];
    if (tid == 0) w2f[32] = b2[0];
    // zero X tiles
    {
        uint32_t* xz = (uint32_t*)(sm + X_OFF);
        for (int i = tid; i < (4 * 5120) / 4; i += TPB) xz[i] = 0u;
    }
    __syncthreads();

    const int warp = tid >> 5, lane = tid & 31;
    const int c = lane & 3, rq = lane >> 2;   // column-lane, row-quad
    const uint32_t xhiB = smb + X_OFF + warp * 5120;   // [32][40] bf16
    const uint32_t xloB = xhiB + 2560;
    const uint32_t sdB  = smb + SD_OFF + warp * 256;   // [32] float2
    const uint32_t cstB = smb + CST_OFF;
    const int gbase = blockIdx.x * RPC + warp * RPW;

    // per-lane W2 slice: group q covers cols 8q+2c+{0,1}
    float w2r[8];
    #pragma unroll
    for (int q = 0; q < 4; q++) {
        w2r[2 * q]     = w2f[8 * q + 2 * c];
        w2r[2 * q + 1] = w2f[8 * q + 2 * c + 1];
    }
    const float b2v = w2f[32];

    // sd init: (s_0, delta=0) per row (row = lane)
    STS64F(sdB + lane * 8, S[(size_t)(gbase + lane) * SROW], 0.0f);

    const uint32_t aOff = (uint32_t)((lane & 15) * 80 + (lane >> 4) * 16);
    const uint32_t bOff = (uint32_t)((lane & 7) * 80 + ((lane >> 3) & 1) * 16);
    const uint32_t whiB = smb + WHI_OFF, wloB = smb + WLO_OFF;

    #pragma unroll 1
    for (int t = 0; t < STEPS; t++) {
        __syncwarp();
        // (s_t, delta_{t-1}) for my 4 rows
        float2 sdv[4];
        #pragma unroll
        for (int rb = 0; rb < 2; rb++)
            #pragma unroll
            for (int hf = 0; hf < 2; hf++)
                LDS64F(sdv[rb * 2 + hf], sdB + (uint32_t)(rb * 16 + rq + hf * 8) * 8);

        // A fragments: 2 rowblocks x 2 K-chunks, hi and lo
        uint32_t AH[2][2][4], AL[2][2][4];
        #pragma unroll
        for (int rb = 0; rb < 2; rb++) {
            #pragma unroll
            for (int kc = 0; kc < 2; kc++) {
                ldsm4(AH[rb][kc], xhiB + rb * 1280 + kc * 32 + aOff);
                ldsm4(AL[rb][kc], xloB + rb * 1280 + kc * 32 + aOff);
            }
        }

        float acc[4] = {0.0f, 0.0f, 0.0f, 0.0f};  // delta partials, 4 rows/lane

        #pragma unroll
        for (int q = 0; q < 4; q++) {
            float C[5][2][4];
            #pragma unroll
            for (int ti = 0; ti < 5; ti++) {
                uint32_t wrow = (uint32_t)((q + 4 * ti) * 640) + bOff;
                uint32_t bh[2], bl[2];
                ldsm2(bh, whiB + wrow);
                ldsm2(bl, wloB + wrow);
                #pragma unroll
                for (int rb = 0; rb < 2; rb++) {
                    mma_zero(C[ti][rb], AH[rb][0], bh);
                    mma_acc (C[ti][rb], AH[rb][0], bl);
                    mma_acc (C[ti][rb], AL[rb][0], bh);
                }
                ldsm2(bh, whiB + wrow + 32);
                ldsm2(bl, wloB + wrow + 32);
                #pragma unroll
                for (int rb = 0; rb < 2; rb++) {
                    mma_acc(C[ti][rb], AH[rb][1], bh);
                    mma_acc(C[ti][rb], AH[rb][1], bl);
                    mma_acc(C[ti][rb], AL[rb][1], bh);
                }
            }

            // rank-3 update: C += s*ws + delta*wd + b  (exact fp32)
            #pragma unroll
            for (int ti = 0; ti < 5; ti++) {
                uint32_t ca = cstB + (uint32_t)(((q + 4 * ti) * 8 + 2 * c) * 16);
                float4 f0, f1;
                LDS128F(f0, ca);
                LDS128F(f1, ca + 16);
                #pragma unroll
                for (int rb = 0; rb < 2; rb++) {
                    #pragma unroll
                    for (int hf = 0; hf < 2; hf++) {
                        float s_ = sdv[rb * 2 + hf].x, d_ = sdv[rb * 2 + hf].y;
                        C[ti][rb][hf * 2]     += fmaf(s_, f0.x, fmaf(d_, f0.y, f0.z));
                        C[ti][rb][hf * 2 + 1] += fmaf(s_, f1.x, fmaf(d_, f1.y, f1.z));
                    }
                }
            }

            // epilogue: C[0]=mlp, C[1]=r, C[2]=z, C[3]=i_n, C[4]=h_n
            #pragma unroll
            for (int rb = 0; rb < 2; rb++) {
                #pragma unroll
                for (int hf = 0; hf < 2; hf++) {
                    float m0 = C[0][rb][hf * 2], m1 = C[0][rb][hf * 2 + 1];
                    acc[rb * 2 + hf] = fmaf(fmaxf(m0, 0.0f), w2r[2 * q],
                                       fmaf(fmaxf(m1, 0.0f), w2r[2 * q + 1],
                                            acc[rb * 2 + hf]));
                    uint32_t ra = (uint32_t)((rb * 16 + rq + hf * 8) * 80
                                             + q * 16 + c * 4);
                    uint32_t ohi, olo;
                    LDS32(ohi, xhiB + ra);
                    LDS32(olo, xloB + ra);
                    float2 fh = bf2f(ohi), fl = bf2f(olo);
                    float hold0 = fh.x + fl.x, hold1 = fh.y + fl.y;

                    float hv[2];
                    #pragma unroll
                    for (int e = 0; e < 2; e++) {
                        float rg = sigmoid_fast(C[1][rb][hf * 2 + e]);
                        float zg = sigmoid_fast(C[2][rb][hf * 2 + e]);
                        float nn = tanh_fast(fmaf(rg, C[4][rb][hf * 2 + e],
                                                  C[3][rb][hf * 2 + e]));
                        float ho = (e == 0) ? hold0 : hold1;
                        hv[e] = fmaf(zg, ho - nn, nn);
                    }
                    __nv_bfloat16 ah, al, bh_, bl_;
                    split2(hv[0], ah, al); split2(hv[1], bh_, bl_);
                    STS32(xhiB + ra, packbf(ah, bh_));
                    STS32(xloB + ra, packbf(al, bl_));
                }
            }
        }

        // delta: reduce over the 4-lane column group
        #pragma unroll
        for (int i = 0; i < 4; i++) {
            acc[i] += __shfl_xor_sync(0xffffffffu, acc[i], 1);
            acc[i] += __shfl_xor_sync(0xffffffffu, acc[i], 2);
            acc[i] += b2v;
        }

        if (c == 0) {
            #pragma unroll
            for (int rb = 0; rb < 2; rb++) {
                #pragma unroll
                for (int hf = 0; hf < 2; hf++) {
                    int r = rb * 16 + rq + hf * 8;
                    int grow = gbase + r;
                    float dl = acc[rb * 2 + hf];
                    out[(size_t)grow * STEPS + t] = dl;
                    float sn = S[(size_t)grow * SROW + t + 1];   // t+1 <= 30, valid
                    STS64F(sdB + (uint32_t)r * 8, sn, dl);
                }
            }
        }
    }
}

extern "C" void kernel_launch(void* const* d_in, const int* in_sizes, int n_in,
                              void* d_out, int out_size)
{
    (void)in_sizes; (void)n_in; (void)out_size;
    const float* S   = (const float*)d_in[0];
    const float* W1  = (const float*)d_in[1];
    const float* b1  = (const float*)d_in[2];
    const float* W2  = (const float*)d_in[3];
    const float* b2  = (const float*)d_in[4];
    const float* Wih = (const float*)d_in[5];
    const float* bih = (const float*)d_in[6];
    const float* Whh = (const float*)d_in[7];
    const float* bhh = (const float*)d_in[8];
    float* out = (float*)d_out;

    cudaFuncSetAttribute(hedge_mma,
                         cudaFuncAttributeMaxDynamicSharedMemorySize, SMEM_TOTAL);

    dim3 grid(BTOTAL / RPC);   // 8192 CTAs, 128 rows each
    hedge_mma<<<grid, TPB, SMEM_TOTAL>>>(S, W1, b1, W2, b2, Wih, bih, Whh, bhh, out);
}

// round 11
// speedup vs baseline: 6.2537x; 1.5222x over previous
#include <cuda_runtime.h>
#include <cuda_bf16.h>
#include <cstdint>

// RecurrentHedgeModel via mma.sync bf16 HMMA (family-common path).
// Round 11: issue-bound (57%) on scalar epilogue work -> cut instructions:
//  (1) tanh.approx.f32 (MUFU.TANH) for all activations (~900 -> ~320 instr)
//  (2) rank-3 (s,delta,bias) folded into the mma accumulator INIT (no adds)
//  (3) h_old as exact fp32 float2 in conflict-free per-lane SMEM
//  (4) packed cvt.rn.bf16x2.f32 for X-tile hi/lo writes
// W rows: 0-31 W1 | 32-95 folded r,z (Wih+Whh) | 96-127 Wih_n | 128-159 Whh_n

#define STEPS  30
#define SROW   31
#define BTOTAL 1048576
#define TPB    128
#define RPW    32          // rows per warp
#define RPC    128         // rows per CTA (4 warps x 32)

// ---- smem map (bytes); W/X row pitch 80B = 40 bf16 (32 used) ----
#define WHI_OFF  0             // [160][40] bf16
#define WLO_OFF  12800
#define CST_OFF  25600         // [160] float4 {ws, wd, b, 0}
#define W2_OFF   28160         // 33 floats
#define SD_OFF   28304         // 4 warps x [32] float2 {s_t, delta_{t-1}}
#define HOLD_OFF 29440         // [16 slots][TPB] float2 (fp32 h state)
#define X_OFF    45824         // 4 warps x (hi 2560 + lo 2560)
#define SMEM_TOTAL (45824 + 4 * 5120)

static __device__ __forceinline__ uint32_t smem_u32(const void* p) {
    uint32_t a;
    asm("{ .reg .u64 t; cvta.to.shared.u64 t, %1; cvt.u32.u64 %0, t; }"
        : "=r"(a) : "l"(p));
    return a;
}
#define STS32(addr, v) \
    asm volatile("st.shared.b32 [%0], %1;" :: "r"(addr), "r"(v) : "memory")
#define LDS128F(f4, addr) \
    asm volatile("ld.shared.v4.f32 {%0,%1,%2,%3}, [%4];" \
                 : "=f"((f4).x), "=f"((f4).y), "=f"((f4).z), "=f"((f4).w) \
                 : "r"(addr))
#define LDS64F(f2, addr) \
    asm volatile("ld.shared.v2.f32 {%0,%1}, [%2];" \
                 : "=f"((f2).x), "=f"((f2).y) : "r"(addr))
#define STS64F(addr, a, b) \
    asm volatile("st.shared.v2.f32 [%0], {%1, %2};" \
                 :: "r"(addr), "f"(a), "f"(b) : "memory")

static __device__ __forceinline__ void ldsm4(uint32_t* r, uint32_t a) {
    asm volatile("ldmatrix.sync.aligned.m8n8.x4.shared.b16 {%0,%1,%2,%3}, [%4];"
                 : "=r"(r[0]), "=r"(r[1]), "=r"(r[2]), "=r"(r[3]) : "r"(a));
}
static __device__ __forceinline__ void ldsm2(uint32_t* r, uint32_t a) {
    asm volatile("ldmatrix.sync.aligned.m8n8.x2.shared.b16 {%0,%1}, [%2];"
                 : "=r"(r[0]), "=r"(r[1]) : "r"(a));
}
static __device__ __forceinline__ void mma_acc(float* d, const uint32_t* a,
                                               const uint32_t* b) {
    asm volatile("mma.sync.aligned.m16n8k16.row.col.f32.bf16.bf16.f32 "
                 "{%0,%1,%2,%3}, {%4,%5,%6,%7}, {%8,%9}, {%0,%1,%2,%3};"
                 : "+f"(d[0]), "+f"(d[1]), "+f"(d[2]), "+f"(d[3])
                 : "r"(a[0]), "r"(a[1]), "r"(a[2]), "r"(a[3]),
                   "r"(b[0]), "r"(b[1]));
}

static __device__ __forceinline__ float tanh_hw(float x) {
    float y; asm("tanh.approx.f32 %0, %1;" : "=f"(y) : "f"(x)); return y;
}
static __device__ __forceinline__ float sigmoid_hw(float x) {
    return fmaf(tanh_hw(0.5f * x), 0.5f, 0.5f);
}
// packed bf16x2 conversion: lower16 = bf16(x0), upper16 = bf16(x1)
static __device__ __forceinline__ uint32_t cvt2bf(float x1, float x0) {
    uint32_t r;
    asm("cvt.rn.bf16x2.f32 %0, %1, %2;" : "=r"(r) : "f"(x1), "f"(x0));
    return r;
}
static __device__ __forceinline__ void split2(float x, __nv_bfloat16& hi,
                                              __nv_bfloat16& lo) {
    hi = __float2bfloat16(x);
    lo = __float2bfloat16(x - __bfloat162float(hi));
}

__global__ __launch_bounds__(TPB, 3)
void hedge_mma(const float* __restrict__ S,
               const float* __restrict__ W1,  const float* __restrict__ b1,
               const float* __restrict__ W2,  const float* __restrict__ b2,
               const float* __restrict__ Wih, const float* __restrict__ bih,
               const float* __restrict__ Whh, const float* __restrict__ bhh,
               float* __restrict__ out)
{
    extern __shared__ __align__(128) unsigned char sm[];
    const int tid = threadIdx.x;
    const uint32_t smb = smem_u32(sm);
    __nv_bfloat16* Whi = (__nv_bfloat16*)(sm + WHI_OFF);  // [160][40]
    __nv_bfloat16* Wlo = (__nv_bfloat16*)(sm + WLO_OFF);
    float4* cst = (float4*)(sm + CST_OFF);                // [160]
    float* w2f = (float*)(sm + W2_OFF);

    // ---- fused hi/lo weight matrix (h columns only, K=32, pitch 40) ----
    for (int i = tid; i < 160 * 32; i += TPB) {
        int n = i >> 5, k = i & 31;
        float w;
        if (n < 32)       w = W1[n * 34 + 2 + k];
        else if (n < 96)  { int g = n - 32; w = Wih[g * 34 + 2 + k] + Whh[g * 32 + k]; }
        else if (n < 128) { int g = n - 32; w = Wih[g * 34 + 2 + k]; }
        else              w = Whh[(64 + (n - 128)) * 32 + k];
        __nv_bfloat16 hi, lo; split2(w, hi, lo);
        Whi[n * 40 + k] = hi; Wlo[n * 40 + k] = lo;
    }
    // ---- rank-3 LUT: {ws, wd, b} per output col, exact fp32 ----
    for (int n = tid; n < 160; n += TPB) {
        float ws = 0.0f, wd = 0.0f, bb;
        if (n < 32)       { ws = W1[n * 34];  wd = W1[n * 34 + 1];  bb = b1[n]; }
        else if (n < 96)  { int g = n - 32; ws = Wih[g * 34]; wd = Wih[g * 34 + 1];
                            bb = bih[g] + bhh[g]; }
        else if (n < 128) { int g = n - 32; ws = Wih[g * 34]; wd = Wih[g * 34 + 1];
                            bb = bih[g]; }
        else              bb = bhh[64 + (n - 128)];
        cst[n] = make_float4(ws, wd, bb, 0.0f);
    }
    if (tid < 32) w2f[tid] = W2[tid];
    if (tid == 0) w2f[32] = b2[0];
    // zero X tiles + hold state
    {
        uint32_t* xz = (uint32_t*)(sm + X_OFF);
        for (int i = tid; i < (4 * 5120) / 4; i += TPB) xz[i] = 0u;
        uint32_t* hz = (uint32_t*)(sm + HOLD_OFF);
        for (int i = tid; i < 16384 / 4; i += TPB) hz[i] = 0u;
    }
    __syncthreads();

    const int warp = tid >> 5, lane = tid & 31;
    const int c = lane & 3, rq = lane >> 2;   // column-lane, row-quad
    const uint32_t xhiB = smb + X_OFF + warp * 5120;   // [32][40] bf16
    const uint32_t xloB = xhiB + 2560;
    const uint32_t sdB  = smb + SD_OFF + warp * 256;   // [32] float2
    const uint32_t cstB = smb + CST_OFF;
    const uint32_t holdB = smb + HOLD_OFF + (uint32_t)tid * 8;  // [slot][tid] f2
    const int gbase = blockIdx.x * RPC + warp * RPW;

    // per-lane W2 slice: group q covers cols 8q+2c+{0,1}
    float w2r[8];
    #pragma unroll
    for (int q = 0; q < 4; q++) {
        w2r[2 * q]     = w2f[8 * q + 2 * c];
        w2r[2 * q + 1] = w2f[8 * q + 2 * c + 1];
    }
    const float b2v = w2f[32];

    // sd init: (s_0, delta=0) per row (row = lane)
    STS64F(sdB + lane * 8, S[(size_t)(gbase + lane) * SROW], 0.0f);

    const uint32_t aOff = (uint32_t)((lane & 15) * 80 + (lane >> 4) * 16);
    const uint32_t bOff = (uint32_t)((lane & 7) * 80 + ((lane >> 3) & 1) * 16);
    const uint32_t whiB = smb + WHI_OFF, wloB = smb + WLO_OFF;

    #pragma unroll 1
    for (int t = 0; t < STEPS; t++) {
        __syncwarp();
        // (s_t, delta_{t-1}) for my 4 row-positions
        float2 sdv[4];
        #pragma unroll
        for (int rb = 0; rb < 2; rb++)
            #pragma unroll
            for (int hf = 0; hf < 2; hf++)
                LDS64F(sdv[rb * 2 + hf], sdB + (uint32_t)(rb * 16 + rq + hf * 8) * 8);

        // A fragments: 2 rowblocks x 2 K-chunks, hi and lo
        uint32_t AH[2][2][4], AL[2][2][4];
        #pragma unroll
        for (int rb = 0; rb < 2; rb++) {
            #pragma unroll
            for (int kc = 0; kc < 2; kc++) {
                ldsm4(AH[rb][kc], xhiB + rb * 1280 + kc * 32 + aOff);
                ldsm4(AL[rb][kc], xloB + rb * 1280 + kc * 32 + aOff);
            }
        }

        float acc[4] = {0.0f, 0.0f, 0.0f, 0.0f};  // delta partials, 4 rows/lane

        #pragma unroll
        for (int q = 0; q < 4; q++) {
            float C[5][2][4];
            // ---- accumulator init = rank-3 term (exact fp32) ----
            #pragma unroll
            for (int ti = 0; ti < 5; ti++) {
                uint32_t ca = cstB + (uint32_t)(((q + 4 * ti) * 8 + 2 * c) * 16);
                float4 f0, f1;
                LDS128F(f0, ca);
                LDS128F(f1, ca + 16);
                #pragma unroll
                for (int rb = 0; rb < 2; rb++) {
                    #pragma unroll
                    for (int hf = 0; hf < 2; hf++) {
                        float s_ = sdv[rb * 2 + hf].x, d_ = sdv[rb * 2 + hf].y;
                        C[ti][rb][hf * 2]     = fmaf(s_, f0.x, fmaf(d_, f0.y, f0.z));
                        C[ti][rb][hf * 2 + 1] = fmaf(s_, f1.x, fmaf(d_, f1.y, f1.z));
                    }
                }
            }
            // ---- mma accumulation (hi*hi + hi*lo + lo*hi) ----
            #pragma unroll
            for (int ti = 0; ti < 5; ti++) {
                uint32_t wrow = (uint32_t)((q + 4 * ti) * 640) + bOff;
                uint32_t bh[2], bl[2];
                ldsm2(bh, whiB + wrow);
                ldsm2(bl, wloB + wrow);
                #pragma unroll
                for (int rb = 0; rb < 2; rb++) {
                    mma_acc(C[ti][rb], AH[rb][0], bh);
                    mma_acc(C[ti][rb], AH[rb][0], bl);
                    mma_acc(C[ti][rb], AL[rb][0], bh);
                }
                ldsm2(bh, whiB + wrow + 32);
                ldsm2(bl, wloB + wrow + 32);
                #pragma unroll
                for (int rb = 0; rb < 2; rb++) {
                    mma_acc(C[ti][rb], AH[rb][1], bh);
                    mma_acc(C[ti][rb], AH[rb][1], bl);
                    mma_acc(C[ti][rb], AL[rb][1], bh);
                }
            }

            // ---- epilogue: C[0]=mlp, C[1]=r, C[2]=z, C[3]=i_n, C[4]=h_n ----
            #pragma unroll
            for (int rb = 0; rb < 2; rb++) {
                #pragma unroll
                for (int hf = 0; hf < 2; hf++) {
                    float m0 = C[0][rb][hf * 2], m1 = C[0][rb][hf * 2 + 1];
                    acc[rb * 2 + hf] = fmaf(fmaxf(m0, 0.0f), w2r[2 * q],
                                       fmaf(fmaxf(m1, 0.0f), w2r[2 * q + 1],
                                            acc[rb * 2 + hf]));
                    uint32_t hsl = holdB + (uint32_t)((q * 4 + rb * 2 + hf) * TPB) * 8;
                    float2 ho; LDS64F(ho, hsl);

                    float hv[2];
                    #pragma unroll
                    for (int e = 0; e < 2; e++) {
                        float rg = sigmoid_hw(C[1][rb][hf * 2 + e]);
                        float zg = sigmoid_hw(C[2][rb][hf * 2 + e]);
                        float nn = tanh_hw(fmaf(rg, C[4][rb][hf * 2 + e],
                                                C[3][rb][hf * 2 + e]));
                        float hop = (e == 0) ? ho.x : ho.y;
                        hv[e] = fmaf(zg, hop - nn, nn);
                    }
                    STS64F(hsl, hv[0], hv[1]);

                    // X tile write (bf16 hi/lo), packed conversions
                    uint32_t ra = (uint32_t)((rb * 16 + rq + hf * 8) * 80
                                             + q * 16 + c * 4);
                    uint32_t ph = cvt2bf(hv[1], hv[0]);
                    float h0f = __uint_as_float(ph << 16);
                    float h1f = __uint_as_float(ph & 0xffff0000u);
                    uint32_t pl = cvt2bf(hv[1] - h1f, hv[0] - h0f);
                    STS32(xhiB + ra, ph);
                    STS32(xloB + ra, pl);
                }
            }
        }

        // delta: reduce over the 4-lane column group
        #pragma unroll
        for (int i = 0; i < 4; i++) {
            acc[i] += __shfl_xor_sync(0xffffffffu, acc[i], 1);
            acc[i] += __shfl_xor_sync(0xffffffffu, acc[i], 2);
            acc[i] += b2v;
        }

        if (c == 0) {
            #pragma unroll
            for (int rb = 0; rb < 2; rb++) {
                #pragma unroll
                for (int hf = 0; hf < 2; hf++) {
                    int r = rb * 16 + rq + hf * 8;
                    int grow = gbase + r;
                    float dl = acc[rb * 2 + hf];
                    out[(size_t)grow * STEPS + t] = dl;
                    float sn = S[(size_t)grow * SROW + t + 1];   // t+1 <= 30, valid
                    STS64F(sdB + (uint32_t)r * 8, sn, dl);
                }
            }
        }
    }
}

extern "C" void kernel_launch(void* const* d_in, const int* in_sizes, int n_in,
                              void* d_out, int out_size)
{
    (void)in_sizes; (void)n_in; (void)out_size;
    const float* S   = (const float*)d_in[0];
    const float* W1  = (const float*)d_in[1];
    const float* b1  = (const float*)d_in[2];
    const float* W2  = (const float*)d_in[3];
    const float* b2  = (const float*)d_in[4];
    const float* Wih = (const float*)d_in[5];
    const float* bih = (const float*)d_in[6];
    const float* Whh = (const float*)d_in[7];
    const float* bhh = (const float*)d_in[8];
    float* out = (float*)d_out;

    cudaFuncSetAttribute(hedge_mma,
                         cudaFuncAttributeMaxDynamicSharedMemorySize, SMEM_TOTAL);

    dim3 grid(BTOTAL / RPC);   // 8192 CTAs, 128 rows each
    hedge_mma<<<grid, TPB, SMEM_TOTAL>>>(S, W1, b1, W2, b2, Wih, bih, Whh, bhh, out);
}

// round 12
// speedup vs baseline: 8.3060x; 1.3282x over previous
#include <cuda_runtime.h>
#include <cuda_fp16.h>
#include <cstdint>

// RecurrentHedgeModel via mma.sync HMMA (family-common path).
// Round 12: asymmetric fp16 scheme cuts the tensor floor 33%:
//   W in fp16 hi/lo (22-bit exact, 2 passes), X in SINGLE fp16 (2^-12 noise;
//   h state kept exact in fp32 SMEM so noise never compounds).
//   240 -> 160 HMMA/warp-step; B hi+lo in one mixed-address ldsm4;
//   X tile halves (4 A-ldsm4, 16 X-writes).
// W rows: 0-31 W1 | 32-95 folded r,z (Wih+Whh) | 96-127 Wih_n | 128-159 Whh_n

#define STEPS  30
#define SROW   31
#define BTOTAL 1048576
#define TPB    128
#define RPW    32          // rows per warp
#define RPC    128         // rows per CTA (4 warps x 32)

// ---- smem map (bytes); W/X row pitch 80B = 40 fp16 (32 used) ----
#define WHI_OFF  0             // [160][40] fp16
#define WLO_OFF  12800
#define CST_OFF  25600         // [160] float4 {ws, wd, b, 0}
#define W2_OFF   28160         // 33 floats
#define SD_OFF   28304         // 4 warps x [32] float2 {s_t, delta_{t-1}}
#define HOLD_OFF 29440         // [16 slots][TPB] float2 (fp32 h state)
#define X_OFF    45824         // 4 warps x 2560 (single fp16 tile)
#define SMEM_TOTAL (45824 + 4 * 2560)

static __device__ __forceinline__ uint32_t smem_u32(const void* p) {
    uint32_t a;
    asm("{ .reg .u64 t; cvta.to.shared.u64 t, %1; cvt.u32.u64 %0, t; }"
        : "=r"(a) : "l"(p));
    return a;
}
#define STS32(addr, v) \
    asm volatile("st.shared.b32 [%0], %1;" :: "r"(addr), "r"(v) : "memory")
#define LDS128F(f4, addr) \
    asm volatile("ld.shared.v4.f32 {%0,%1,%2,%3}, [%4];" \
                 : "=f"((f4).x), "=f"((f4).y), "=f"((f4).z), "=f"((f4).w) \
                 : "r"(addr))
#define LDS64F(f2, addr) \
    asm volatile("ld.shared.v2.f32 {%0,%1}, [%2];" \
                 : "=f"((f2).x), "=f"((f2).y) : "r"(addr))
#define STS64F(addr, a, b) \
    asm volatile("st.shared.v2.f32 [%0], {%1, %2};" \
                 :: "r"(addr), "f"(a), "f"(b) : "memory")

static __device__ __forceinline__ void ldsm4(uint32_t* r, uint32_t a) {
    asm volatile("ldmatrix.sync.aligned.m8n8.x4.shared.b16 {%0,%1,%2,%3}, [%4];"
                 : "=r"(r[0]), "=r"(r[1]), "=r"(r[2]), "=r"(r[3]) : "r"(a));
}
static __device__ __forceinline__ void mma_acc(float* d, const uint32_t* a,
                                               const uint32_t* b) {
    asm volatile("mma.sync.aligned.m16n8k16.row.col.f32.f16.f16.f32 "
                 "{%0,%1,%2,%3}, {%4,%5,%6,%7}, {%8,%9}, {%0,%1,%2,%3};"
                 : "+f"(d[0]), "+f"(d[1]), "+f"(d[2]), "+f"(d[3])
                 : "r"(a[0]), "r"(a[1]), "r"(a[2]), "r"(a[3]),
                   "r"(b[0]), "r"(b[1]));
}

static __device__ __forceinline__ float tanh_hw(float x) {
    float y; asm("tanh.approx.f32 %0, %1;" : "=f"(y) : "f"(x)); return y;
}
static __device__ __forceinline__ float sigmoid_hw(float x) {
    return fmaf(tanh_hw(0.5f * x), 0.5f, 0.5f);
}
// packed fp16x2: lower16 = f16(x0), upper16 = f16(x1)
static __device__ __forceinline__ uint32_t cvt2h(float x1, float x0) {
    uint32_t r;
    asm("cvt.rn.f16x2.f32 %0, %1, %2;" : "=r"(r) : "f"(x1), "f"(x0));
    return r;
}

__global__ __launch_bounds__(TPB, 3)
void hedge_mma(const float* __restrict__ S,
               const float* __restrict__ W1,  const float* __restrict__ b1,
               const float* __restrict__ W2,  const float* __restrict__ b2,
               const float* __restrict__ Wih, const float* __restrict__ bih,
               const float* __restrict__ Whh, const float* __restrict__ bhh,
               float* __restrict__ out)
{
    extern __shared__ __align__(128) unsigned char sm[];
    const int tid = threadIdx.x;
    const uint32_t smb = smem_u32(sm);
    __half* Whi = (__half*)(sm + WHI_OFF);   // [160][40]
    __half* Wlo = (__half*)(sm + WLO_OFF);
    float4* cst = (float4*)(sm + CST_OFF);   // [160]
    float* w2f = (float*)(sm + W2_OFF);

    // ---- fused hi/lo fp16 weight matrix (h columns only, K=32, pitch 40) ----
    for (int i = tid; i < 160 * 32; i += TPB) {
        int n = i >> 5, k = i & 31;
        float w;
        if (n < 32)       w = W1[n * 34 + 2 + k];
        else if (n < 96)  { int g = n - 32; w = Wih[g * 34 + 2 + k] + Whh[g * 32 + k]; }
        else if (n < 128) { int g = n - 32; w = Wih[g * 34 + 2 + k]; }
        else              w = Whh[(64 + (n - 128)) * 32 + k];
        __half hi = __float2half_rn(w);
        __half lo = __float2half_rn(w - __half2float(hi));
        Whi[n * 40 + k] = hi; Wlo[n * 40 + k] = lo;
    }
    // ---- rank-3 LUT: {ws, wd, b} per output col, exact fp32 ----
    for (int n = tid; n < 160; n += TPB) {
        float ws = 0.0f, wd = 0.0f, bb;
        if (n < 32)       { ws = W1[n * 34];  wd = W1[n * 34 + 1];  bb = b1[n]; }
        else if (n < 96)  { int g = n - 32; ws = Wih[g * 34]; wd = Wih[g * 34 + 1];
                            bb = bih[g] + bhh[g]; }
        else if (n < 128) { int g = n - 32; ws = Wih[g * 34]; wd = Wih[g * 34 + 1];
                            bb = bih[g]; }
        else              bb = bhh[64 + (n - 128)];
        cst[n] = make_float4(ws, wd, bb, 0.0f);
    }
    if (tid < 32) w2f[tid] = W2[tid];
    if (tid == 0) w2f[32] = b2[0];
    // zero X tiles + hold state
    {
        uint32_t* xz = (uint32_t*)(sm + X_OFF);
        for (int i = tid; i < (4 * 2560) / 4; i += TPB) xz[i] = 0u;
        uint32_t* hz = (uint32_t*)(sm + HOLD_OFF);
        for (int i = tid; i < 16384 / 4; i += TPB) hz[i] = 0u;
    }
    __syncthreads();

    const int warp = tid >> 5, lane = tid & 31;
    const int c = lane & 3, rq = lane >> 2;   // column-lane, row-quad
    const uint32_t xB  = smb + X_OFF + warp * 2560;    // [32][40] fp16
    const uint32_t sdB = smb + SD_OFF + warp * 256;    // [32] float2
    const uint32_t cstB = smb + CST_OFF;
    const uint32_t holdB = smb + HOLD_OFF + (uint32_t)tid * 8;  // [slot][tid] f2
    const int gbase = blockIdx.x * RPC + warp * RPW;

    // per-lane W2 slice: group q covers cols 8q+2c+{0,1}
    float w2r[8];
    #pragma unroll
    for (int q = 0; q < 4; q++) {
        w2r[2 * q]     = w2f[8 * q + 2 * c];
        w2r[2 * q + 1] = w2f[8 * q + 2 * c + 1];
    }
    const float b2v = w2f[32];

    // sd init: (s_0, delta=0) per row (row = lane)
    STS64F(sdB + lane * 8, S[(size_t)(gbase + lane) * SROW], 0.0f);

    const uint32_t aOff = (uint32_t)((lane & 15) * 80 + (lane >> 4) * 16);
    // mixed-address ldsm4 B base: mats {hi k0-7, hi k8-15, lo k0-7, lo k8-15}
    const uint32_t bsel = (uint32_t)(lane >> 3);      // 0..3
    const uint32_t bBase4 = ((bsel >> 1) ? (smb + WLO_OFF) : (smb + WHI_OFF))
                            + (uint32_t)(lane & 7) * 80 + (bsel & 1) * 16;

    #pragma unroll 1
    for (int t = 0; t < STEPS; t++) {
        __syncwarp();
        // (s_t, delta_{t-1}) for my 4 row-positions
        float2 sdv[4];
        #pragma unroll
        for (int rb = 0; rb < 2; rb++)
            #pragma unroll
            for (int hf = 0; hf < 2; hf++)
                LDS64F(sdv[rb * 2 + hf], sdB + (uint32_t)(rb * 16 + rq + hf * 8) * 8);

        // A fragments: 2 rowblocks x 2 K-chunks (single fp16)
        uint32_t A[2][2][4];
        #pragma unroll
        for (int rb = 0; rb < 2; rb++)
            #pragma unroll
            for (int kc = 0; kc < 2; kc++)
                ldsm4(A[rb][kc], xB + rb * 1280 + kc * 32 + aOff);

        float acc[4] = {0.0f, 0.0f, 0.0f, 0.0f};  // delta partials, 4 rows/lane

        #pragma unroll
        for (int q = 0; q < 4; q++) {
            float C[5][2][4];
            // ---- accumulator init = rank-3 term (exact fp32) ----
            #pragma unroll
            for (int ti = 0; ti < 5; ti++) {
                uint32_t ca = cstB + (uint32_t)(((q + 4 * ti) * 8 + 2 * c) * 16);
                float4 f0, f1;
                LDS128F(f0, ca);
                LDS128F(f1, ca + 16);
                #pragma unroll
                for (int rb = 0; rb < 2; rb++) {
                    #pragma unroll
                    for (int hf = 0; hf < 2; hf++) {
                        float s_ = sdv[rb * 2 + hf].x, d_ = sdv[rb * 2 + hf].y;
                        C[ti][rb][hf * 2]     = fmaf(s_, f0.x, fmaf(d_, f0.y, f0.z));
                        C[ti][rb][hf * 2 + 1] = fmaf(s_, f1.x, fmaf(d_, f1.y, f1.z));
                    }
                }
            }
            // ---- mma: X_f16 * (W_hi + W_lo), 2 passes ----
            #pragma unroll
            for (int ti = 0; ti < 5; ti++) {
                uint32_t wrow = (uint32_t)((q + 4 * ti) * 640);
                #pragma unroll
                for (int kc = 0; kc < 2; kc++) {
                    uint32_t bb[4];                    // {bh0, bh1, bl0, bl1}
                    ldsm4(bb, bBase4 + wrow + (uint32_t)kc * 32);
                    #pragma unroll
                    for (int rb = 0; rb < 2; rb++) {
                        mma_acc(C[ti][rb], A[rb][kc], bb);      // hi pass
                        mma_acc(C[ti][rb], A[rb][kc], bb + 2);  // lo pass
                    }
                }
            }

            // ---- epilogue: C[0]=mlp, C[1]=r, C[2]=z, C[3]=i_n, C[4]=h_n ----
            #pragma unroll
            for (int rb = 0; rb < 2; rb++) {
                #pragma unroll
                for (int hf = 0; hf < 2; hf++) {
                    float m0 = C[0][rb][hf * 2], m1 = C[0][rb][hf * 2 + 1];
                    acc[rb * 2 + hf] = fmaf(fmaxf(m0, 0.0f), w2r[2 * q],
                                       fmaf(fmaxf(m1, 0.0f), w2r[2 * q + 1],
                                            acc[rb * 2 + hf]));
                    uint32_t hsl = holdB + (uint32_t)((q * 4 + rb * 2 + hf) * TPB) * 8;
                    float2 ho; LDS64F(ho, hsl);

                    float hv[2];
                    #pragma unroll
                    for (int e = 0; e < 2; e++) {
                        float rg = sigmoid_hw(C[1][rb][hf * 2 + e]);
                        float zg = sigmoid_hw(C[2][rb][hf * 2 + e]);
                        float nn = tanh_hw(fmaf(rg, C[4][rb][hf * 2 + e],
                                                C[3][rb][hf * 2 + e]));
                        float hop = (e == 0) ? ho.x : ho.y;
                        hv[e] = fmaf(zg, hop - nn, nn);
                    }
                    STS64F(hsl, hv[0], hv[1]);

                    // X tile write: single packed fp16x2
                    uint32_t ra = (uint32_t)((rb * 16 + rq + hf * 8) * 80
                                             + q * 16 + c * 4);
                    STS32(xB + ra, cvt2h(hv[1], hv[0]));
                }
            }
        }

        // delta: reduce over the 4-lane column group
        #pragma unroll
        for (int i = 0; i < 4; i++) {
            acc[i] += __shfl_xor_sync(0xffffffffu, acc[i], 1);
            acc[i] += __shfl_xor_sync(0xffffffffu, acc[i], 2);
            acc[i] += b2v;
        }

        if (c == 0) {
            #pragma unroll
            for (int rb = 0; rb < 2; rb++) {
                #pragma unroll
                for (int hf = 0; hf < 2; hf++) {
                    int r = rb * 16 + rq + hf * 8;
                    int grow = gbase + r;
                    float dl = acc[rb * 2 + hf];
                    out[(size_t)grow * STEPS + t] = dl;
                    float sn = S[(size_t)grow * SROW + t + 1];   // t+1 <= 30, valid
                    STS64F(sdB + (uint32_t)r * 8, sn, dl);
                }
            }
        }
    }
}

extern "C" void kernel_launch(void* const* d_in, const int* in_sizes, int n_in,
                              void* d_out, int out_size)
{
    (void)in_sizes; (void)n_in; (void)out_size;
    const float* S   = (const float*)d_in[0];
    const float* W1  = (const float*)d_in[1];
    const float* b1  = (const float*)d_in[2];
    const float* W2  = (const float*)d_in[3];
    const float* b2  = (const float*)d_in[4];
    const float* Wih = (const float*)d_in[5];
    const float* bih = (const float*)d_in[6];
    const float* Whh = (const float*)d_in[7];
    const float* bhh = (const float*)d_in[8];
    float* out = (float*)d_out;

    cudaFuncSetAttribute(hedge_mma,
                         cudaFuncAttributeMaxDynamicSharedMemorySize, SMEM_TOTAL);

    dim3 grid(BTOTAL / RPC);   // 8192 CTAs, 128 rows each
    hedge_mma<<<grid, TPB, SMEM_TOTAL>>>(S, W1, b1, W2, b2, Wih, bih, Whh, bhh, out);
}

// round 13
// speedup vs baseline: 10.8504x; 1.3063x over previous
#include <cuda_runtime.h>
#include <cuda_fp16.h>
#include <cstdint>

// RecurrentHedgeModel via mma.sync HMMA (family-common path).
// Round 13: spend precision margin (6.5e-5 of 1e-3) on throughput:
//   (1) W single fp16 (1 pass): HMMA 160->80, and one ldsm4 per tile now
//       covers ALL of B (K=32 = 64 contiguous bytes = 4 mats) -> B wf halved
//   (2) hold[] eliminated: h_old re-read as fp16 from the X tile (bounded
//       geometric error; mma already sees fp16 h) -> -64 wf, -16KB smem
// W rows: 0-31 W1 | 32-95 folded r,z (Wih+Whh) | 96-127 Wih_n | 128-159 Whh_n

#define STEPS  30
#define SROW   31
#define BTOTAL 1048576
#define TPB    128
#define RPW    32          // rows per warp
#define RPC    128         // rows per CTA (4 warps x 32)

// ---- smem map (bytes); W/X row pitch 80B = 40 fp16 (32 used) ----
#define WHI_OFF  0             // [160][40] fp16
#define CST_OFF  12800         // [160] float4 {ws, wd, b, 0}
#define W2_OFF   15360         // 33 floats
#define SD_OFF   15552         // 4 warps x [32] float2 {s_t, delta_{t-1}}
#define X_OFF    16640         // 4 warps x 2560 (single fp16 tile)
#define SMEM_TOTAL (16640 + 4 * 2560)

static __device__ __forceinline__ uint32_t smem_u32(const void* p) {
    uint32_t a;
    asm("{ .reg .u64 t; cvta.to.shared.u64 t, %1; cvt.u32.u64 %0, t; }"
        : "=r"(a) : "l"(p));
    return a;
}
#define STS32(addr, v) \
    asm volatile("st.shared.b32 [%0], %1;" :: "r"(addr), "r"(v) : "memory")
#define LDS32(v, addr) \
    asm volatile("ld.shared.b32 %0, [%1];" : "=r"(v) : "r"(addr))
#define LDS128F(f4, addr) \
    asm volatile("ld.shared.v4.f32 {%0,%1,%2,%3}, [%4];" \
                 : "=f"((f4).x), "=f"((f4).y), "=f"((f4).z), "=f"((f4).w) \
                 : "r"(addr))
#define LDS64F(f2, addr) \
    asm volatile("ld.shared.v2.f32 {%0,%1}, [%2];" \
                 : "=f"((f2).x), "=f"((f2).y) : "r"(addr))
#define STS64F(addr, a, b) \
    asm volatile("st.shared.v2.f32 [%0], {%1, %2};" \
                 :: "r"(addr), "f"(a), "f"(b) : "memory")

static __device__ __forceinline__ void ldsm4(uint32_t* r, uint32_t a) {
    asm volatile("ldmatrix.sync.aligned.m8n8.x4.shared.b16 {%0,%1,%2,%3}, [%4];"
                 : "=r"(r[0]), "=r"(r[1]), "=r"(r[2]), "=r"(r[3]) : "r"(a));
}
static __device__ __forceinline__ void mma_acc(float* d, const uint32_t* a,
                                               const uint32_t* b) {
    asm volatile("mma.sync.aligned.m16n8k16.row.col.f32.f16.f16.f32 "
                 "{%0,%1,%2,%3}, {%4,%5,%6,%7}, {%8,%9}, {%0,%1,%2,%3};"
                 : "+f"(d[0]), "+f"(d[1]), "+f"(d[2]), "+f"(d[3])
                 : "r"(a[0]), "r"(a[1]), "r"(a[2]), "r"(a[3]),
                   "r"(b[0]), "r"(b[1]));
}

static __device__ __forceinline__ float tanh_hw(float x) {
    float y; asm("tanh.approx.f32 %0, %1;" : "=f"(y) : "f"(x)); return y;
}
static __device__ __forceinline__ float sigmoid_hw(float x) {
    return fmaf(tanh_hw(0.5f * x), 0.5f, 0.5f);
}
// packed fp16x2: lower16 = f16(x0), upper16 = f16(x1)
static __device__ __forceinline__ uint32_t cvt2h(float x1, float x0) {
    uint32_t r;
    asm("cvt.rn.f16x2.f32 %0, %1, %2;" : "=r"(r) : "f"(x1), "f"(x0));
    return r;
}
static __device__ __forceinline__ float2 h2f(uint32_t v) {
    __half2 h = *reinterpret_cast<__half2*>(&v);
    return __half22float2(h);
}

__global__ __launch_bounds__(TPB, 3)
void hedge_mma(const float* __restrict__ S,
               const float* __restrict__ W1,  const float* __restrict__ b1,
               const float* __restrict__ W2,  const float* __restrict__ b2,
               const float* __restrict__ Wih, const float* __restrict__ bih,
               const float* __restrict__ Whh, const float* __restrict__ bhh,
               float* __restrict__ out)
{
    extern __shared__ __align__(128) unsigned char sm[];
    const int tid = threadIdx.x;
    const uint32_t smb = smem_u32(sm);
    __half* Whi = (__half*)(sm + WHI_OFF);   // [160][40]
    float4* cst = (float4*)(sm + CST_OFF);   // [160]
    float* w2f = (float*)(sm + W2_OFF);

    // ---- fused fp16 weight matrix (h columns only, K=32, pitch 40) ----
    for (int i = tid; i < 160 * 32; i += TPB) {
        int n = i >> 5, k = i & 31;
        float w;
        if (n < 32)       w = W1[n * 34 + 2 + k];
        else if (n < 96)  { int g = n - 32; w = Wih[g * 34 + 2 + k] + Whh[g * 32 + k]; }
        else if (n < 128) { int g = n - 32; w = Wih[g * 34 + 2 + k]; }
        else              w = Whh[(64 + (n - 128)) * 32 + k];
        Whi[n * 40 + k] = __float2half_rn(w);
    }
    // ---- rank-3 LUT: {ws, wd, b} per output col, exact fp32 ----
    for (int n = tid; n < 160; n += TPB) {
        float ws = 0.0f, wd = 0.0f, bb;
        if (n < 32)       { ws = W1[n * 34];  wd = W1[n * 34 + 1];  bb = b1[n]; }
        else if (n < 96)  { int g = n - 32; ws = Wih[g * 34]; wd = Wih[g * 34 + 1];
                            bb = bih[g] + bhh[g]; }
        else if (n < 128) { int g = n - 32; ws = Wih[g * 34]; wd = Wih[g * 34 + 1];
                            bb = bih[g]; }
        else              bb = bhh[64 + (n - 128)];
        cst[n] = make_float4(ws, wd, bb, 0.0f);
    }
    if (tid < 32) w2f[tid] = W2[tid];
    if (tid == 0) w2f[32] = b2[0];
    // zero X tiles
    {
        uint32_t* xz = (uint32_t*)(sm + X_OFF);
        for (int i = tid; i < (4 * 2560) / 4; i += TPB) xz[i] = 0u;
    }
    __syncthreads();

    const int warp = tid >> 5, lane = tid & 31;
    const int c = lane & 3, rq = lane >> 2;   // column-lane, row-quad
    const uint32_t xB  = smb + X_OFF + warp * 2560;    // [32][40] fp16
    const uint32_t sdB = smb + SD_OFF + warp * 256;    // [32] float2
    const uint32_t cstB = smb + CST_OFF;
    const int gbase = blockIdx.x * RPC + warp * RPW;

    // per-lane W2 slice: group q covers cols 8q+2c+{0,1}
    float w2r[8];
    #pragma unroll
    for (int q = 0; q < 4; q++) {
        w2r[2 * q]     = w2f[8 * q + 2 * c];
        w2r[2 * q + 1] = w2f[8 * q + 2 * c + 1];
    }
    const float b2v = w2f[32];

    // sd init: (s_0, delta=0) per row (row = lane)
    STS64F(sdB + lane * 8, S[(size_t)(gbase + lane) * SROW], 0.0f);

    const uint32_t aOff = (uint32_t)((lane & 15) * 80 + (lane >> 4) * 16);
    // B ldsm4: all K=32 of one tile (4 mats at +0,+16,+32,+48 in the 64B row)
    const uint32_t bOff4 = (uint32_t)((lane & 7) * 80 + (lane >> 3) * 16);
    const uint32_t whiB = smb + WHI_OFF;

    #pragma unroll 1
    for (int t = 0; t < STEPS; t++) {
        __syncwarp();
        // (s_t, delta_{t-1}) for my 4 row-positions
        float2 sdv[4];
        #pragma unroll
        for (int rb = 0; rb < 2; rb++)
            #pragma unroll
            for (int hf = 0; hf < 2; hf++)
                LDS64F(sdv[rb * 2 + hf], sdB + (uint32_t)(rb * 16 + rq + hf * 8) * 8);

        // A fragments: 2 rowblocks x 2 K-chunks (single fp16)
        uint32_t A[2][2][4];
        #pragma unroll
        for (int rb = 0; rb < 2; rb++)
            #pragma unroll
            for (int kc = 0; kc < 2; kc++)
                ldsm4(A[rb][kc], xB + rb * 1280 + kc * 32 + aOff);

        float acc[4] = {0.0f, 0.0f, 0.0f, 0.0f};  // delta partials, 4 rows/lane

        #pragma unroll
        for (int q = 0; q < 4; q++) {
            float C[5][2][4];
            // ---- accumulator init = rank-3 term (exact fp32) ----
            #pragma unroll
            for (int ti = 0; ti < 5; ti++) {
                uint32_t ca = cstB + (uint32_t)(((q + 4 * ti) * 8 + 2 * c) * 16);
                float4 f0, f1;
                LDS128F(f0, ca);
                LDS128F(f1, ca + 16);
                #pragma unroll
                for (int rb = 0; rb < 2; rb++) {
                    #pragma unroll
                    for (int hf = 0; hf < 2; hf++) {
                        float s_ = sdv[rb * 2 + hf].x, d_ = sdv[rb * 2 + hf].y;
                        C[ti][rb][hf * 2]     = fmaf(s_, f0.x, fmaf(d_, f0.y, f0.z));
                        C[ti][rb][hf * 2 + 1] = fmaf(s_, f1.x, fmaf(d_, f1.y, f1.z));
                    }
                }
            }
            // ---- mma: single fp16 pass, one ldsm4 per tile (all K) ----
            #pragma unroll
            for (int ti = 0; ti < 5; ti++) {
                uint32_t bb[4];      // {kc0 k0-7, kc0 k8-15, kc1 k0-7, kc1 k8-15}
                ldsm4(bb, whiB + (uint32_t)((q + 4 * ti) * 640) + bOff4);
                #pragma unroll
                for (int rb = 0; rb < 2; rb++) {
                    mma_acc(C[ti][rb], A[rb][0], bb);
                    mma_acc(C[ti][rb], A[rb][1], bb + 2);
                }
            }

            // ---- epilogue: C[0]=mlp, C[1]=r, C[2]=z, C[3]=i_n, C[4]=h_n ----
            #pragma unroll
            for (int rb = 0; rb < 2; rb++) {
                #pragma unroll
                for (int hf = 0; hf < 2; hf++) {
                    float m0 = C[0][rb][hf * 2], m1 = C[0][rb][hf * 2 + 1];
                    acc[rb * 2 + hf] = fmaf(fmaxf(m0, 0.0f), w2r[2 * q],
                                       fmaf(fmaxf(m1, 0.0f), w2r[2 * q + 1],
                                            acc[rb * 2 + hf]));
                    // h_old: fp16 from the X tile (same address we overwrite)
                    uint32_t ra = (uint32_t)((rb * 16 + rq + hf * 8) * 80
                                             + q * 16 + c * 4);
                    uint32_t hraw; LDS32(hraw, xB + ra);
                    float2 ho = h2f(hraw);

                    float hv[2];
                    #pragma unroll
                    for (int e = 0; e < 2; e++) {
                        float rg = sigmoid_hw(C[1][rb][hf * 2 + e]);
                        float zg = sigmoid_hw(C[2][rb][hf * 2 + e]);
                        float nn = tanh_hw(fmaf(rg, C[4][rb][hf * 2 + e],
                                                C[3][rb][hf * 2 + e]));
                        float hop = (e == 0) ? ho.x : ho.y;
                        hv[e] = fmaf(zg, hop - nn, nn);
                    }
                    STS32(xB + ra, cvt2h(hv[1], hv[0]));
                }
            }
        }

        // delta: reduce over the 4-lane column group
        #pragma unroll
        for (int i = 0; i < 4; i++) {
            acc[i] += __shfl_xor_sync(0xffffffffu, acc[i], 1);
            acc[i] += __shfl_xor_sync(0xffffffffu, acc[i], 2);
            acc[i] += b2v;
        }

        if (c == 0) {
            #pragma unroll
            for (int rb = 0; rb < 2; rb++) {
                #pragma unroll
                for (int hf = 0; hf < 2; hf++) {
                    int r = rb * 16 + rq + hf * 8;
                    int grow = gbase + r;
                    float dl = acc[rb * 2 + hf];
                    out[(size_t)grow * STEPS + t] = dl;
                    float sn = S[(size_t)grow * SROW + t + 1];   // t+1 <= 30, valid
                    STS64F(sdB + (uint32_t)r * 8, sn, dl);
                }
            }
        }
    }
}

extern "C" void kernel_launch(void* const* d_in, const int* in_sizes, int n_in,
                              void* d_out, int out_size)
{
    (void)in_sizes; (void)n_in; (void)out_size;
    const float* S   = (const float*)d_in[0];
    const float* W1  = (const float*)d_in[1];
    const float* b1  = (const float*)d_in[2];
    const float* W2  = (const float*)d_in[3];
    const float* b2  = (const float*)d_in[4];
    const float* Wih = (const float*)d_in[5];
    const float* bih = (const float*)d_in[6];
    const float* Whh = (const float*)d_in[7];
    const float* bhh = (const float*)d_in[8];
    float* out = (float*)d_out;

    cudaFuncSetAttribute(hedge_mma,
                         cudaFuncAttributeMaxDynamicSharedMemorySize, SMEM_TOTAL);

    dim3 grid(BTOTAL / RPC);   // 8192 CTAs, 128 rows each
    hedge_mma<<<grid, TPB, SMEM_TOTAL>>>(S, W1, b1, W2, b2, Wih, bih, Whh, bhh, out);
}

// round 14
// speedup vs baseline: 11.9931x; 1.1053x over previous
#include <cuda_runtime.h>
#include <cuda_fp16.h>
#include <cstdint>

// RecurrentHedgeModel via mma.sync HMMA (family-common path).
// Round 14: rank-3 term (s, delta, bias) moved back into the tensor core as a
// cheap m16n8k8 third chunk: X2=[s_hi,s_lo,d_hi,d_lo,1], W2=[ws,ws,wd,wd,b].
// Chunk-2 B fragments are loop-invariant -> hoisted into 20 registers (zero
// per-step L1). Removes the 40 LDS.128 + 320 FMA rank-3 stream that round-13
// ncu showed as the top L1 (72.7%) and fma (35.4%) consumer.
// W rows: 0-31 W1 | 32-95 folded r,z (Wih+Whh) | 96-127 Wih_n | 128-159 Whh_n

#define STEPS  30
#define SROW   31
#define BTOTAL 1048576
#define TPB    128
#define RPW    32          // rows per warp
#define RPC    128         // rows per CTA (4 warps x 32)

// ---- smem map (bytes) ----
#define WHI_OFF  0             // [160][40] fp16, pitch 80B (K=32 h-cols)
#define W2C_OFF  12800         // 20 tiles x 128B (k8 B mats, ldsm4-grouped)
#define W2F_OFF  15360         // 33 floats
#define X_OFF    15552         // 4 warps x 2560 (fp16 h tile, pitch 80B)
#define X2_OFF   25792         // 4 warps x 512 ([32 rows][16B] chunk2)
#define SMEM_TOTAL 27840

static __device__ __forceinline__ uint32_t smem_u32(const void* p) {
    uint32_t a;
    asm("{ .reg .u64 t; cvta.to.shared.u64 t, %1; cvt.u32.u64 %0, t; }"
        : "=r"(a) : "l"(p));
    return a;
}
#define STS32(addr, v) \
    asm volatile("st.shared.b32 [%0], %1;" :: "r"(addr), "r"(v) : "memory")
#define LDS32(v, addr) \
    asm volatile("ld.shared.b32 %0, [%1];" : "=r"(v) : "r"(addr))
#define STS64U(addr, r0, r1) \
    asm volatile("st.shared.v2.b32 [%0], {%1, %2};" \
                 :: "r"(addr), "r"(r0), "r"(r1) : "memory")
#define STS128U(addr, r0, r1, r2, r3) \
    asm volatile("st.shared.v4.b32 [%0], {%1, %2, %3, %4};" \
                 :: "r"(addr), "r"(r0), "r"(r1), "r"(r2), "r"(r3) : "memory")

static __device__ __forceinline__ void ldsm4(uint32_t* r, uint32_t a) {
    asm volatile("ldmatrix.sync.aligned.m8n8.x4.shared.b16 {%0,%1,%2,%3}, [%4];"
                 : "=r"(r[0]), "=r"(r[1]), "=r"(r[2]), "=r"(r[3]) : "r"(a));
}
static __device__ __forceinline__ void ldsm2(uint32_t* r, uint32_t a) {
    asm volatile("ldmatrix.sync.aligned.m8n8.x2.shared.b16 {%0,%1}, [%2];"
                 : "=r"(r[0]), "=r"(r[1]) : "r"(a));
}
static __device__ __forceinline__ void mma_acc(float* d, const uint32_t* a,
                                               const uint32_t* b) {
    asm volatile("mma.sync.aligned.m16n8k16.row.col.f32.f16.f16.f32 "
                 "{%0,%1,%2,%3}, {%4,%5,%6,%7}, {%8,%9}, {%0,%1,%2,%3};"
                 : "+f"(d[0]), "+f"(d[1]), "+f"(d[2]), "+f"(d[3])
                 : "r"(a[0]), "r"(a[1]), "r"(a[2]), "r"(a[3]),
                   "r"(b[0]), "r"(b[1]));
}
static __device__ __forceinline__ void mma_zero(float* d, const uint32_t* a,
                                                const uint32_t* b) {
    asm volatile("mma.sync.aligned.m16n8k16.row.col.f32.f16.f16.f32 "
                 "{%0,%1,%2,%3}, {%4,%5,%6,%7}, {%8,%9}, {%10,%11,%12,%13};"
                 : "=f"(d[0]), "=f"(d[1]), "=f"(d[2]), "=f"(d[3])
                 : "r"(a[0]), "r"(a[1]), "r"(a[2]), "r"(a[3]),
                   "r"(b[0]), "r"(b[1]),
                   "f"(0.0f), "f"(0.0f), "f"(0.0f), "f"(0.0f));
}
static __device__ __forceinline__ void mma_k8(float* d, const uint32_t* a,
                                              uint32_t b0) {
    asm volatile("mma.sync.aligned.m16n8k8.row.col.f32.f16.f16.f32 "
                 "{%0,%1,%2,%3}, {%4,%5}, {%6}, {%0,%1,%2,%3};"
                 : "+f"(d[0]), "+f"(d[1]), "+f"(d[2]), "+f"(d[3])
                 : "r"(a[0]), "r"(a[1]), "r"(b0));
}

static __device__ __forceinline__ float tanh_hw(float x) {
    float y; asm("tanh.approx.f32 %0, %1;" : "=f"(y) : "f"(x)); return y;
}
static __device__ __forceinline__ float sigmoid_hw(float x) {
    return fmaf(tanh_hw(0.5f * x), 0.5f, 0.5f);
}
// packed fp16x2: lower16 = f16(x0), upper16 = f16(x1)
static __device__ __forceinline__ uint32_t cvt2h(float x1, float x0) {
    uint32_t r;
    asm("cvt.rn.f16x2.f32 %0, %1, %2;" : "=r"(r) : "f"(x1), "f"(x0));
    return r;
}
static __device__ __forceinline__ float2 h2f(uint32_t v) {
    __half2 h = *reinterpret_cast<__half2*>(&v);
    return __half22float2(h);
}
// hi/lo fp16 split packed: lower = f16(x), upper = f16(x - f16(x))
static __device__ __forceinline__ uint32_t split_pack(float x) {
    float hi = __half2float(__float2half_rn(x));
    return cvt2h(x - hi, x);
}

// per-column rank-3 coefficients {ws, wd, b}
static __device__ __forceinline__ void col_coef(int n,
    const float* W1, const float* b1, const float* Wih,
    const float* bih, const float* bhh, float& ws, float& wd, float& bb)
{
    ws = 0.0f; wd = 0.0f;
    if (n < 32)       { ws = W1[n * 34];  wd = W1[n * 34 + 1];  bb = b1[n]; }
    else if (n < 96)  { int g = n - 32; ws = Wih[g * 34]; wd = Wih[g * 34 + 1];
                        bb = bih[g] + bhh[g]; }
    else if (n < 128) { int g = n - 32; ws = Wih[g * 34]; wd = Wih[g * 34 + 1];
                        bb = bih[g]; }
    else              bb = bhh[64 + (n - 128)];
}

__global__ __launch_bounds__(TPB, 3)
void hedge_mma(const float* __restrict__ S,
               const float* __restrict__ W1,  const float* __restrict__ b1,
               const float* __restrict__ W2,  const float* __restrict__ b2,
               const float* __restrict__ Wih, const float* __restrict__ bih,
               const float* __restrict__ Whh, const float* __restrict__ bhh,
               float* __restrict__ out)
{
    extern __shared__ __align__(128) unsigned char sm[];
    const int tid = threadIdx.x;
    const uint32_t smb = smem_u32(sm);
    __half* Whi = (__half*)(sm + WHI_OFF);   // [160][40]
    __half* W2c = (__half*)(sm + W2C_OFF);   // [20][8][8]
    float* w2f = (float*)(sm + W2F_OFF);

    // ---- fused fp16 weight matrix (h columns only, K=32, pitch 40) ----
    for (int i = tid; i < 160 * 32; i += TPB) {
        int n = i >> 5, k = i & 31;
        float w;
        if (n < 32)       w = W1[n * 34 + 2 + k];
        else if (n < 96)  { int g = n - 32; w = Wih[g * 34 + 2 + k] + Whh[g * 32 + k]; }
        else if (n < 128) { int g = n - 32; w = Wih[g * 34 + 2 + k]; }
        else              w = Whh[(64 + (n - 128)) * 32 + k];
        Whi[n * 40 + k] = __float2half_rn(w);
    }
    // ---- chunk-2 B mats: tile tt rows n=8tt+nl, k: 0,1=ws 2,3=wd 4=b ----
    for (int i = tid; i < 20 * 64; i += TPB) {
        int tt = i >> 6, loc = i & 63, nl = loc >> 3, k = loc & 7;
        int n = tt * 8 + nl;
        float ws, wd, bb;
        col_coef(n, W1, b1, Wih, bih, bhh, ws, wd, bb);
        float v = (k < 2) ? ws : (k < 4) ? wd : (k == 4) ? bb : 0.0f;
        W2c[tt * 64 + nl * 8 + k] = __float2half_rn(v);
    }
    if (tid < 32) w2f[tid] = W2[tid];
    if (tid == 0) w2f[32] = b2[0];
    // zero X tiles
    {
        uint32_t* xz = (uint32_t*)(sm + X_OFF);
        for (int i = tid; i < (4 * 2560) / 4; i += TPB) xz[i] = 0u;
    }
    // X2 init: one 16B row per thread: [s_hi,s_lo | 0,0 | 1,0 | 0,0]
    {
        int grow0 = blockIdx.x * RPC + tid;
        float s0 = S[(size_t)grow0 * SROW];
        uint32_t a = smb + X2_OFF + (uint32_t)tid * 16;
        STS128U(a, split_pack(s0), 0u, 0x00003C00u, 0u);
    }
    __syncthreads();

    const int warp = tid >> 5, lane = tid & 31;
    const int c = lane & 3, rq = lane >> 2;   // column-lane, row-quad
    const uint32_t xB  = smb + X_OFF + warp * 2560;    // [32][40] fp16
    const uint32_t x2B = smb + X2_OFF + warp * 512;    // [32][16B]
    const int gbase = blockIdx.x * RPC + warp * RPW;

    // per-lane W2 slice: group q covers cols 8q+2c+{0,1}
    float w2r[8];
    #pragma unroll
    for (int q = 0; q < 4; q++) {
        w2r[2 * q]     = w2f[8 * q + 2 * c];
        w2r[2 * q + 1] = w2f[8 * q + 2 * c + 1];
    }
    const float b2v = w2f[32];

    // hoist chunk-2 B fragments (loop-invariant): 20 regs
    uint32_t b2r[20];
    #pragma unroll
    for (int g = 0; g < 5; g++) {
        uint32_t tmp[4];
        ldsm4(tmp, smb + W2C_OFF + (uint32_t)g * 512
                   + (uint32_t)(lane >> 3) * 128 + (uint32_t)(lane & 7) * 16);
        #pragma unroll
        for (int j = 0; j < 4; j++) b2r[4 * g + j] = tmp[j];
    }

    const uint32_t aOff  = (uint32_t)((lane & 15) * 80 + (lane >> 4) * 16);
    const uint32_t a2Off = (uint32_t)((lane & 15) * 16);
    const uint32_t bOff4 = (uint32_t)((lane & 7) * 80 + (lane >> 3) * 16);
    const uint32_t whiB = smb + WHI_OFF;

    #pragma unroll 1
    for (int t = 0; t < STEPS; t++) {
        __syncwarp();
        // A fragments: h (2 kc) + chunk2 (k8), per rowblock
        uint32_t A[2][2][4], A2[2][2];
        #pragma unroll
        for (int rb = 0; rb < 2; rb++) {
            #pragma unroll
            for (int kc = 0; kc < 2; kc++)
                ldsm4(A[rb][kc], xB + rb * 1280 + kc * 32 + aOff);
            ldsm2(A2[rb], x2B + rb * 256 + a2Off);
        }

        float acc[4] = {0.0f, 0.0f, 0.0f, 0.0f};  // delta partials, 4 rows/lane

        #pragma unroll
        for (int q = 0; q < 4; q++) {
            float C[5][2][4];
            #pragma unroll
            for (int ti = 0; ti < 5; ti++) {
                const int tile = q + 4 * ti;
                uint32_t bb[4];      // main B: all K=32 of this tile
                ldsm4(bb, whiB + (uint32_t)(tile * 640) + bOff4);
                #pragma unroll
                for (int rb = 0; rb < 2; rb++) {
                    mma_zero(C[ti][rb], A[rb][0], bb);
                    mma_acc (C[ti][rb], A[rb][1], bb + 2);
                    mma_k8  (C[ti][rb], A2[rb], b2r[tile]);
                }
            }

            // ---- epilogue: C[0]=mlp, C[1]=r, C[2]=z, C[3]=i_n, C[4]=h_n ----
            #pragma unroll
            for (int rb = 0; rb < 2; rb++) {
                #pragma unroll
                for (int hf = 0; hf < 2; hf++) {
                    float m0 = C[0][rb][hf * 2], m1 = C[0][rb][hf * 2 + 1];
                    acc[rb * 2 + hf] = fmaf(fmaxf(m0, 0.0f), w2r[2 * q],
                                       fmaf(fmaxf(m1, 0.0f), w2r[2 * q + 1],
                                            acc[rb * 2 + hf]));
                    // h_old: fp16 from the X tile (same address we overwrite)
                    uint32_t ra = (uint32_t)((rb * 16 + rq + hf * 8) * 80
                                             + q * 16 + c * 4);
                    uint32_t hraw; LDS32(hraw, xB + ra);
                    float2 ho = h2f(hraw);

                    float hv[2];
                    #pragma unroll
                    for (int e = 0; e < 2; e++) {
                        float rg = sigmoid_hw(C[1][rb][hf * 2 + e]);
                        float zg = sigmoid_hw(C[2][rb][hf * 2 + e]);
                        float nn = tanh_hw(fmaf(rg, C[4][rb][hf * 2 + e],
                                                C[3][rb][hf * 2 + e]));
                        float hop = (e == 0) ? ho.x : ho.y;
                        hv[e] = fmaf(zg, hop - nn, nn);
                    }
                    STS32(xB + ra, cvt2h(hv[1], hv[0]));
                }
            }
        }

        // delta: reduce over the 4-lane column group
        #pragma unroll
        for (int i = 0; i < 4; i++) {
            acc[i] += __shfl_xor_sync(0xffffffffu, acc[i], 1);
            acc[i] += __shfl_xor_sync(0xffffffffu, acc[i], 2);
            acc[i] += b2v;
        }

        if (c == 0) {
            #pragma unroll
            for (int rb = 0; rb < 2; rb++) {
                #pragma unroll
                for (int hf = 0; hf < 2; hf++) {
                    int r = rb * 16 + rq + hf * 8;
                    int grow = gbase + r;
                    float dl = acc[rb * 2 + hf];
                    out[(size_t)grow * STEPS + t] = dl;
                    float sn = S[(size_t)grow * SROW + t + 1];   // t+1 <= 30, valid
                    STS64U(x2B + (uint32_t)r * 16, split_pack(sn), split_pack(dl));
                }
            }
        }
    }
}

extern "C" void kernel_launch(void* const* d_in, const int* in_sizes, int n_in,
                              void* d_out, int out_size)
{
    (void)in_sizes; (void)n_in; (void)out_size;
    const float* S   = (const float*)d_in[0];
    const float* W1  = (const float*)d_in[1];
    const float* b1  = (const float*)d_in[2];
    const float* W2  = (const float*)d_in[3];
    const float* b2  = (const float*)d_in[4];
    const float* Wih = (const float*)d_in[5];
    const float* bih = (const float*)d_in[6];
    const float* Whh = (const float*)d_in[7];
    const float* bhh = (const float*)d_in[8];
    float* out = (float*)d_out;

    cudaFuncSetAttribute(hedge_mma,
                         cudaFuncAttributeMaxDynamicSharedMemorySize, SMEM_TOTAL);

    dim3 grid(BTOTAL / RPC);   // 8192 CTAs, 128 rows each
    hedge_mma<<<grid, TPB, SMEM_TOTAL>>>(S, W1, b1, W2, b2, Wih, bih, Whh, bhh, out);
}

// round 15
// speedup vs baseline: 13.1772x; 1.0987x over previous
#include <cuda_runtime.h>
#include <cuda_fp16.h>
#include <cstdint>

// RecurrentHedgeModel via mma.sync HMMA (family-common path).
// Round 15: (a) half2 epilogue — all gate math in packed fp16 (tanh.approx.
// f16x2 / fma.rn.f16x2), r/z weight rows pre-scaled 0.5 so sigmoid needs no
// pre-multiply, h_old consumed raw; (b) 4th CTA/SM via __launch_bounds__(128,4)
// (regs freed by the half2 path + w2 moved to smem reads).
// W rows: 0-31 W1 | 32-95 folded r,z x0.5 | 96-127 Wih_n | 128-159 Whh_n

#define STEPS  30
#define SROW   31
#define BTOTAL 1048576
#define TPB    128
#define RPW    32          // rows per warp
#define RPC    128         // rows per CTA (4 warps x 32)

// ---- smem map (bytes) ----
#define WHI_OFF  0             // [160][40] fp16, pitch 80B (K=32 h-cols)
#define W2C_OFF  12800         // 20 tiles x 128B (k8 B mats, ldsm4-grouped)
#define W2F_OFF  15360         // 33 floats
#define X_OFF    15552         // 4 warps x 2560 (fp16 h tile, pitch 80B)
#define X2_OFF   25792         // 4 warps x 512 ([32 rows][16B] chunk2)
#define SMEM_TOTAL 27840

static __device__ __forceinline__ uint32_t smem_u32(const void* p) {
    uint32_t a;
    asm("{ .reg .u64 t; cvta.to.shared.u64 t, %1; cvt.u32.u64 %0, t; }"
        : "=r"(a) : "l"(p));
    return a;
}
#define STS32(addr, v) \
    asm volatile("st.shared.b32 [%0], %1;" :: "r"(addr), "r"(v) : "memory")
#define LDS32(v, addr) \
    asm volatile("ld.shared.b32 %0, [%1];" : "=r"(v) : "r"(addr))
#define STS64U(addr, r0, r1) \
    asm volatile("st.shared.v2.b32 [%0], {%1, %2};" \
                 :: "r"(addr), "r"(r0), "r"(r1) : "memory")
#define STS128U(addr, r0, r1, r2, r3) \
    asm volatile("st.shared.v4.b32 [%0], {%1, %2, %3, %4};" \
                 :: "r"(addr), "r"(r0), "r"(r1), "r"(r2), "r"(r3) : "memory")

static __device__ __forceinline__ void ldsm4(uint32_t* r, uint32_t a) {
    asm volatile("ldmatrix.sync.aligned.m8n8.x4.shared.b16 {%0,%1,%2,%3}, [%4];"
                 : "=r"(r[0]), "=r"(r[1]), "=r"(r[2]), "=r"(r[3]) : "r"(a));
}
static __device__ __forceinline__ void ldsm2(uint32_t* r, uint32_t a) {
    asm volatile("ldmatrix.sync.aligned.m8n8.x2.shared.b16 {%0,%1}, [%2];"
                 : "=r"(r[0]), "=r"(r[1]) : "r"(a));
}
static __device__ __forceinline__ void mma_acc(float* d, const uint32_t* a,
                                               const uint32_t* b) {
    asm volatile("mma.sync.aligned.m16n8k16.row.col.f32.f16.f16.f32 "
                 "{%0,%1,%2,%3}, {%4,%5,%6,%7}, {%8,%9}, {%0,%1,%2,%3};"
                 : "+f"(d[0]), "+f"(d[1]), "+f"(d[2]), "+f"(d[3])
                 : "r"(a[0]), "r"(a[1]), "r"(a[2]), "r"(a[3]),
                   "r"(b[0]), "r"(b[1]));
}
static __device__ __forceinline__ void mma_zero(float* d, const uint32_t* a,
                                                const uint32_t* b) {
    asm volatile("mma.sync.aligned.m16n8k16.row.col.f32.f16.f16.f32 "
                 "{%0,%1,%2,%3}, {%4,%5,%6,%7}, {%8,%9}, {%10,%11,%12,%13};"
                 : "=f"(d[0]), "=f"(d[1]), "=f"(d[2]), "=f"(d[3])
                 : "r"(a[0]), "r"(a[1]), "r"(a[2]), "r"(a[3]),
                   "r"(b[0]), "r"(b[1]),
                   "f"(0.0f), "f"(0.0f), "f"(0.0f), "f"(0.0f));
}
static __device__ __forceinline__ void mma_k8(float* d, const uint32_t* a,
                                              uint32_t b0) {
    asm volatile("mma.sync.aligned.m16n8k8.row.col.f32.f16.f16.f32 "
                 "{%0,%1,%2,%3}, {%4,%5}, {%6}, {%0,%1,%2,%3};"
                 : "+f"(d[0]), "+f"(d[1]), "+f"(d[2]), "+f"(d[3])
                 : "r"(a[0]), "r"(a[1]), "r"(b0));
}

// ---- packed fp16 helpers ----
static __device__ __forceinline__ uint32_t tanh2(uint32_t x) {
    uint32_t y; asm("tanh.approx.f16x2 %0, %1;" : "=r"(y) : "r"(x)); return y;
}
static __device__ __forceinline__ uint32_t hfma2u(uint32_t a, uint32_t b, uint32_t c) {
    uint32_t d; asm("fma.rn.f16x2 %0, %1, %2, %3;" : "=r"(d) : "r"(a), "r"(b), "r"(c)); return d;
}
static __device__ __forceinline__ uint32_t hsub2u(uint32_t a, uint32_t b) {
    uint32_t d; asm("sub.rn.f16x2 %0, %1, %2;" : "=r"(d) : "r"(a), "r"(b)); return d;
}
// packed fp16x2: lower16 = f16(x0), upper16 = f16(x1)
static __device__ __forceinline__ uint32_t cvt2h(float x1, float x0) {
    uint32_t r;
    asm("cvt.rn.f16x2.f32 %0, %1, %2;" : "=r"(r) : "f"(x1), "f"(x0));
    return r;
}
// hi/lo fp16 split packed: lower = f16(x), upper = f16(x - f16(x))
static __device__ __forceinline__ uint32_t split_pack(float x) {
    float hi = __half2float(__float2half_rn(x));
    return cvt2h(x - hi, x);
}

// per-column rank-3 coefficients {ws, wd, b}
static __device__ __forceinline__ void col_coef(int n,
    const float* W1, const float* b1, const float* Wih,
    const float* bih, const float* bhh, float& ws, float& wd, float& bb)
{
    ws = 0.0f; wd = 0.0f;
    if (n < 32)       { ws = W1[n * 34];  wd = W1[n * 34 + 1];  bb = b1[n]; }
    else if (n < 96)  { int g = n - 32; ws = Wih[g * 34]; wd = Wih[g * 34 + 1];
                        bb = bih[g] + bhh[g]; }
    else if (n < 128) { int g = n - 32; ws = Wih[g * 34]; wd = Wih[g * 34 + 1];
                        bb = bih[g]; }
    else              bb = bhh[64 + (n - 128)];
}

__global__ __launch_bounds__(TPB, 4)
void hedge_mma(const float* __restrict__ S,
               const float* __restrict__ W1,  const float* __restrict__ b1,
               const float* __restrict__ W2,  const float* __restrict__ b2,
               const float* __restrict__ Wih, const float* __restrict__ bih,
               const float* __restrict__ Whh, const float* __restrict__ bhh,
               float* __restrict__ out)
{
    extern __shared__ __align__(128) unsigned char sm[];
    const int tid = threadIdx.x;
    const uint32_t smb = smem_u32(sm);
    __half* Whi = (__half*)(sm + WHI_OFF);   // [160][40]
    __half* W2c = (__half*)(sm + W2C_OFF);   // [20][8][8]
    float* w2f = (float*)(sm + W2F_OFF);

    // ---- fused fp16 weight matrix; r/z rows (32..95) pre-scaled by 0.5 ----
    for (int i = tid; i < 160 * 32; i += TPB) {
        int n = i >> 5, k = i & 31;
        float w;
        if (n < 32)       w = W1[n * 34 + 2 + k];
        else if (n < 96)  { int g = n - 32;
                            w = 0.5f * (Wih[g * 34 + 2 + k] + Whh[g * 32 + k]); }
        else if (n < 128) { int g = n - 32; w = Wih[g * 34 + 2 + k]; }
        else              w = Whh[(64 + (n - 128)) * 32 + k];
        Whi[n * 40 + k] = __float2half_rn(w);
    }
    // ---- chunk-2 B mats (rank-3), r/z tiles (4..11) pre-scaled by 0.5 ----
    for (int i = tid; i < 20 * 64; i += TPB) {
        int tt = i >> 6, loc = i & 63, nl = loc >> 3, k = loc & 7;
        int n = tt * 8 + nl;
        float ws, wd, bb;
        col_coef(n, W1, b1, Wih, bih, bhh, ws, wd, bb);
        float v = (k < 2) ? ws : (k < 4) ? wd : (k == 4) ? bb : 0.0f;
        if (tt >= 4 && tt < 12) v *= 0.5f;
        W2c[tt * 64 + nl * 8 + k] = __float2half_rn(v);
    }
    if (tid < 32) w2f[tid] = W2[tid];
    if (tid == 0) w2f[32] = b2[0];
    // zero X tiles
    {
        uint32_t* xz = (uint32_t*)(sm + X_OFF);
        for (int i = tid; i < (4 * 2560) / 4; i += TPB) xz[i] = 0u;
    }
    // X2 init: one 16B row per thread: [s_hi,s_lo | 0,0 | 1,0 | 0,0]
    {
        int grow0 = blockIdx.x * RPC + tid;
        float s0 = S[(size_t)grow0 * SROW];
        uint32_t a = smb + X2_OFF + (uint32_t)tid * 16;
        STS128U(a, split_pack(s0), 0u, 0x00003C00u, 0u);
    }
    __syncthreads();

    const int warp = tid >> 5, lane = tid & 31;
    const int c = lane & 3, rq = lane >> 2;   // column-lane, row-quad
    const uint32_t xB  = smb + X_OFF + warp * 2560;    // [32][40] fp16
    const uint32_t x2B = smb + X2_OFF + warp * 512;    // [32][16B]
    const int gbase = blockIdx.x * RPC + warp * RPW;
    const float b2v = w2f[32];
    const uint32_t H05 = 0x38003800u;   // half2(0.5, 0.5)

    // hoist chunk-2 B fragments (loop-invariant): 20 regs
    uint32_t b2r[20];
    #pragma unroll
    for (int g = 0; g < 5; g++) {
        uint32_t tmp[4];
        ldsm4(tmp, smb + W2C_OFF + (uint32_t)g * 512
                   + (uint32_t)(lane >> 3) * 128 + (uint32_t)(lane & 7) * 16);
        #pragma unroll
        for (int j = 0; j < 4; j++) b2r[4 * g + j] = tmp[j];
    }

    const uint32_t aOff  = (uint32_t)((lane & 15) * 80 + (lane >> 4) * 16);
    const uint32_t a2Off = (uint32_t)((lane & 15) * 16);
    const uint32_t bOff4 = (uint32_t)((lane & 7) * 80 + (lane >> 3) * 16);
    const uint32_t whiB = smb + WHI_OFF;

    #pragma unroll 1
    for (int t = 0; t < STEPS; t++) {
        __syncwarp();
        // A fragments: h (2 kc) + chunk2 (k8), per rowblock
        uint32_t A[2][2][4], A2[2][2];
        #pragma unroll
        for (int rb = 0; rb < 2; rb++) {
            #pragma unroll
            for (int kc = 0; kc < 2; kc++)
                ldsm4(A[rb][kc], xB + rb * 1280 + kc * 32 + aOff);
            ldsm2(A2[rb], x2B + rb * 256 + a2Off);
        }

        float acc[4] = {0.0f, 0.0f, 0.0f, 0.0f};  // delta partials, 4 rows/lane

        #pragma unroll
        for (int q = 0; q < 4; q++) {
            float C[5][2][4];
            #pragma unroll
            for (int ti = 0; ti < 5; ti++) {
                const int tile = q + 4 * ti;
                uint32_t bb[4];      // main B: all K=32 of this tile
                ldsm4(bb, whiB + (uint32_t)(tile * 640) + bOff4);
                #pragma unroll
                for (int rb = 0; rb < 2; rb++) {
                    mma_zero(C[ti][rb], A[rb][0], bb);
                    mma_acc (C[ti][rb], A[rb][1], bb + 2);
                    mma_k8  (C[ti][rb], A2[rb], b2r[tile]);
                }
            }

            const float w2a = w2f[8 * q + 2 * c];
            const float w2b = w2f[8 * q + 2 * c + 1];

            // ---- half2 epilogue: C[0]=mlp, C[1]=0.5r, C[2]=0.5z,
            //                      C[3]=i_n, C[4]=h_n ----
            #pragma unroll
            for (int rb = 0; rb < 2; rb++) {
                #pragma unroll
                for (int hf = 0; hf < 2; hf++) {
                    float m0 = C[0][rb][hf * 2], m1 = C[0][rb][hf * 2 + 1];
                    acc[rb * 2 + hf] = fmaf(fmaxf(m0, 0.0f), w2a,
                                       fmaf(fmaxf(m1, 0.0f), w2b,
                                            acc[rb * 2 + hf]));
                    uint32_t rp = cvt2h(C[1][rb][hf * 2 + 1], C[1][rb][hf * 2]);
                    uint32_t zp = cvt2h(C[2][rb][hf * 2 + 1], C[2][rb][hf * 2]);
                    uint32_t ip = cvt2h(C[3][rb][hf * 2 + 1], C[3][rb][hf * 2]);
                    uint32_t hp = cvt2h(C[4][rb][hf * 2 + 1], C[4][rb][hf * 2]);
                    uint32_t rs = hfma2u(tanh2(rp), H05, H05);  // sigma(r)
                    uint32_t zs = hfma2u(tanh2(zp), H05, H05);  // sigma(z)
                    uint32_t nt = tanh2(hfma2u(rs, hp, ip));    // n
                    uint32_t ra = (uint32_t)((rb * 16 + rq + hf * 8) * 80
                                             + q * 16 + c * 4);
                    uint32_t hold; LDS32(hold, xB + ra);
                    // h' = n + z*(h_old - n)
                    uint32_t hnew = hfma2u(zs, hsub2u(hold, nt), nt);
                    STS32(xB + ra, hnew);
                }
            }
        }

        // delta: reduce over the 4-lane column group
        #pragma unroll
        for (int i = 0; i < 4; i++) {
            acc[i] += __shfl_xor_sync(0xffffffffu, acc[i], 1);
            acc[i] += __shfl_xor_sync(0xffffffffu, acc[i], 2);
            acc[i] += b2v;
        }

        if (c == 0) {
            #pragma unroll
            for (int rb = 0; rb < 2; rb++) {
                #pragma unroll
                for (int hf = 0; hf < 2; hf++) {
                    int r = rb * 16 + rq + hf * 8;
                    int grow = gbase + r;
                    float dl = acc[rb * 2 + hf];
                    out[(size_t)grow * STEPS + t] = dl;
                    float sn = S[(size_t)grow * SROW + t + 1];   // t+1 <= 30, valid
                    STS64U(x2B + (uint32_t)r * 16, split_pack(sn), split_pack(dl));
                }
            }
        }
    }
}

extern "C" void kernel_launch(void* const* d_in, const int* in_sizes, int n_in,
                              void* d_out, int out_size)
{
    (void)in_sizes; (void)n_in; (void)out_size;
    const float* S   = (const float*)d_in[0];
    const float* W1  = (const float*)d_in[1];
    const float* b1  = (const float*)d_in[2];
    const float* W2  = (const float*)d_in[3];
    const float* b2  = (const float*)d_in[4];
    const float* Wih = (const float*)d_in[5];
    const float* bih = (const float*)d_in[6];
    const float* Whh = (const float*)d_in[7];
    const float* bhh = (const float*)d_in[8];
    float* out = (float*)d_out;

    cudaFuncSetAttribute(hedge_mma,
                         cudaFuncAttributeMaxDynamicSharedMemorySize, SMEM_TOTAL);

    dim3 grid(BTOTAL / RPC);   // 8192 CTAs, 128 rows each
    hedge_mma<<<grid, TPB, SMEM_TOTAL>>>(S, W1, b1, W2, b2, Wih, bih, Whh, bhh, out);
}

// round 16
// speedup vs baseline: 13.5528x; 1.0285x over previous
#include <cuda_runtime.h>
#include <cuda_fp16.h>
#include <cstdint>

// RecurrentHedgeModel via mma.sync HMMA (family-common path).
// Round 16: fp16 accumulators for the 4 gate tiles (r,z,i_n,h_n) — C comes out
// of the mma already packed half2 for tanh.approx.f16x2 (kills the cvt2h
// stream) and C regs/group drop 40->24, freeing the 128-reg ceiling so ptxas
// can overlap group-q epilogue with group-q+1 mma. The mlp tile (delta path,
// the checked output) keeps full fp32 accumulation.
// W rows: 0-31 W1 | 32-95 folded r,z x0.5 | 96-127 Wih_n | 128-159 Whh_n

#define STEPS  30
#define SROW   31
#define BTOTAL 1048576
#define TPB    128
#define RPW    32          // rows per warp
#define RPC    128         // rows per CTA (4 warps x 32)

// ---- smem map (bytes) ----
#define WHI_OFF  0             // [160][40] fp16, pitch 80B (K=32 h-cols)
#define W2C_OFF  12800         // 20 tiles x 128B (k8 B mats, ldsm4-grouped)
#define W2F_OFF  15360         // 33 floats
#define X_OFF    15552         // 4 warps x 2560 (fp16 h tile, pitch 80B)
#define X2_OFF   25792         // 4 warps x 512 ([32 rows][16B] chunk2)
#define SMEM_TOTAL 27840

static __device__ __forceinline__ uint32_t smem_u32(const void* p) {
    uint32_t a;
    asm("{ .reg .u64 t; cvta.to.shared.u64 t, %1; cvt.u32.u64 %0, t; }"
        : "=r"(a) : "l"(p));
    return a;
}
#define STS32(addr, v) \
    asm volatile("st.shared.b32 [%0], %1;" :: "r"(addr), "r"(v) : "memory")
#define LDS32(v, addr) \
    asm volatile("ld.shared.b32 %0, [%1];" : "=r"(v) : "r"(addr))
#define STS64U(addr, r0, r1) \
    asm volatile("st.shared.v2.b32 [%0], {%1, %2};" \
                 :: "r"(addr), "r"(r0), "r"(r1) : "memory")
#define STS128U(addr, r0, r1, r2, r3) \
    asm volatile("st.shared.v4.b32 [%0], {%1, %2, %3, %4};" \
                 :: "r"(addr), "r"(r0), "r"(r1), "r"(r2), "r"(r3) : "memory")

static __device__ __forceinline__ void ldsm4(uint32_t* r, uint32_t a) {
    asm volatile("ldmatrix.sync.aligned.m8n8.x4.shared.b16 {%0,%1,%2,%3}, [%4];"
                 : "=r"(r[0]), "=r"(r[1]), "=r"(r[2]), "=r"(r[3]) : "r"(a));
}
static __device__ __forceinline__ void ldsm2(uint32_t* r, uint32_t a) {
    asm volatile("ldmatrix.sync.aligned.m8n8.x2.shared.b16 {%0,%1}, [%2];"
                 : "=r"(r[0]), "=r"(r[1]) : "r"(a));
}
// ---- fp32-accum mma (mlp/delta tile) ----
static __device__ __forceinline__ void mma_acc(float* d, const uint32_t* a,
                                               const uint32_t* b) {
    asm volatile("mma.sync.aligned.m16n8k16.row.col.f32.f16.f16.f32 "
                 "{%0,%1,%2,%3}, {%4,%5,%6,%7}, {%8,%9}, {%0,%1,%2,%3};"
                 : "+f"(d[0]), "+f"(d[1]), "+f"(d[2]), "+f"(d[3])
                 : "r"(a[0]), "r"(a[1]), "r"(a[2]), "r"(a[3]),
                   "r"(b[0]), "r"(b[1]));
}
static __device__ __forceinline__ void mma_zero(float* d, const uint32_t* a,
                                                const uint32_t* b) {
    asm volatile("mma.sync.aligned.m16n8k16.row.col.f32.f16.f16.f32 "
                 "{%0,%1,%2,%3}, {%4,%5,%6,%7}, {%8,%9}, {%10,%11,%12,%13};"
                 : "=f"(d[0]), "=f"(d[1]), "=f"(d[2]), "=f"(d[3])
                 : "r"(a[0]), "r"(a[1]), "r"(a[2]), "r"(a[3]),
                   "r"(b[0]), "r"(b[1]),
                   "f"(0.0f), "f"(0.0f), "f"(0.0f), "f"(0.0f));
}
static __device__ __forceinline__ void mma_k8(float* d, const uint32_t* a,
                                              uint32_t b0) {
    asm volatile("mma.sync.aligned.m16n8k8.row.col.f32.f16.f16.f32 "
                 "{%0,%1,%2,%3}, {%4,%5}, {%6}, {%0,%1,%2,%3};"
                 : "+f"(d[0]), "+f"(d[1]), "+f"(d[2]), "+f"(d[3])
                 : "r"(a[0]), "r"(a[1]), "r"(b0));
}
// ---- fp16-accum mma (gate tiles) ----
static __device__ __forceinline__ void mma_h_zero(uint32_t* d, const uint32_t* a,
                                                  const uint32_t* b) {
    asm volatile("mma.sync.aligned.m16n8k16.row.col.f16.f16.f16.f16 "
                 "{%0,%1}, {%2,%3,%4,%5}, {%6,%7}, {%8,%9};"
                 : "=r"(d[0]), "=r"(d[1])
                 : "r"(a[0]), "r"(a[1]), "r"(a[2]), "r"(a[3]),
                   "r"(b[0]), "r"(b[1]), "r"(0u), "r"(0u));
}
static __device__ __forceinline__ void mma_h_acc(uint32_t* d, const uint32_t* a,
                                                 const uint32_t* b) {
    asm volatile("mma.sync.aligned.m16n8k16.row.col.f16.f16.f16.f16 "
                 "{%0,%1}, {%2,%3,%4,%5}, {%6,%7}, {%0,%1};"
                 : "+r"(d[0]), "+r"(d[1])
                 : "r"(a[0]), "r"(a[1]), "r"(a[2]), "r"(a[3]),
                   "r"(b[0]), "r"(b[1]));
}
static __device__ __forceinline__ void mma_h_k8(uint32_t* d, const uint32_t* a,
                                                uint32_t b0) {
    asm volatile("mma.sync.aligned.m16n8k8.row.col.f16.f16.f16.f16 "
                 "{%0,%1}, {%2,%3}, {%4}, {%0,%1};"
                 : "+r"(d[0]), "+r"(d[1])
                 : "r"(a[0]), "r"(a[1]), "r"(b0));
}

// ---- packed fp16 helpers ----
static __device__ __forceinline__ uint32_t tanh2(uint32_t x) {
    uint32_t y; asm("tanh.approx.f16x2 %0, %1;" : "=r"(y) : "r"(x)); return y;
}
static __device__ __forceinline__ uint32_t hfma2u(uint32_t a, uint32_t b, uint32_t c) {
    uint32_t d; asm("fma.rn.f16x2 %0, %1, %2, %3;" : "=r"(d) : "r"(a), "r"(b), "r"(c)); return d;
}
static __device__ __forceinline__ uint32_t hsub2u(uint32_t a, uint32_t b) {
    uint32_t d; asm("sub.rn.f16x2 %0, %1, %2;" : "=r"(d) : "r"(a), "r"(b)); return d;
}
// packed fp16x2: lower16 = f16(x0), upper16 = f16(x1)
static __device__ __forceinline__ uint32_t cvt2h(float x1, float x0) {
    uint32_t r;
    asm("cvt.rn.f16x2.f32 %0, %1, %2;" : "=r"(r) : "f"(x1), "f"(x0));
    return r;
}
// hi/lo fp16 split packed: lower = f16(x), upper = f16(x - f16(x))
static __device__ __forceinline__ uint32_t split_pack(float x) {
    float hi = __half2float(__float2half_rn(x));
    return cvt2h(x - hi, x);
}

// per-column rank-3 coefficients {ws, wd, b}
static __device__ __forceinline__ void col_coef(int n,
    const float* W1, const float* b1, const float* Wih,
    const float* bih, const float* bhh, float& ws, float& wd, float& bb)
{
    ws = 0.0f; wd = 0.0f;
    if (n < 32)       { ws = W1[n * 34];  wd = W1[n * 34 + 1];  bb = b1[n]; }
    else if (n < 96)  { int g = n - 32; ws = Wih[g * 34]; wd = Wih[g * 34 + 1];
                        bb = bih[g] + bhh[g]; }
    else if (n < 128) { int g = n - 32; ws = Wih[g * 34]; wd = Wih[g * 34 + 1];
                        bb = bih[g]; }
    else              bb = bhh[64 + (n - 128)];
}

__global__ __launch_bounds__(TPB, 4)
void hedge_mma(const float* __restrict__ S,
               const float* __restrict__ W1,  const float* __restrict__ b1,
               const float* __restrict__ W2,  const float* __restrict__ b2,
               const float* __restrict__ Wih, const float* __restrict__ bih,
               const float* __restrict__ Whh, const float* __restrict__ bhh,
               float* __restrict__ out)
{
    extern __shared__ __align__(128) unsigned char sm[];
    const int tid = threadIdx.x;
    const uint32_t smb = smem_u32(sm);
    __half* Whi = (__half*)(sm + WHI_OFF);   // [160][40]
    __half* W2c = (__half*)(sm + W2C_OFF);   // [20][8][8]
    float* w2f = (float*)(sm + W2F_OFF);

    // ---- fused fp16 weight matrix; r/z rows (32..95) pre-scaled by 0.5 ----
    for (int i = tid; i < 160 * 32; i += TPB) {
        int n = i >> 5, k = i & 31;
        float w;
        if (n < 32)       w = W1[n * 34 + 2 + k];
        else if (n < 96)  { int g = n - 32;
                            w = 0.5f * (Wih[g * 34 + 2 + k] + Whh[g * 32 + k]); }
        else if (n < 128) { int g = n - 32; w = Wih[g * 34 + 2 + k]; }
        else              w = Whh[(64 + (n - 128)) * 32 + k];
        Whi[n * 40 + k] = __float2half_rn(w);
    }
    // ---- chunk-2 B mats (rank-3), r/z tiles (4..11) pre-scaled by 0.5 ----
    for (int i = tid; i < 20 * 64; i += TPB) {
        int tt = i >> 6, loc = i & 63, nl = loc >> 3, k = loc & 7;
        int n = tt * 8 + nl;
        float ws, wd, bb;
        col_coef(n, W1, b1, Wih, bih, bhh, ws, wd, bb);
        float v = (k < 2) ? ws : (k < 4) ? wd : (k == 4) ? bb : 0.0f;
        if (tt >= 4 && tt < 12) v *= 0.5f;
        W2c[tt * 64 + nl * 8 + k] = __float2half_rn(v);
    }
    if (tid < 32) w2f[tid] = W2[tid];
    if (tid == 0) w2f[32] = b2[0];
    // zero X tiles
    {
        uint32_t* xz = (uint32_t*)(sm + X_OFF);
        for (int i = tid; i < (4 * 2560) / 4; i += TPB) xz[i] = 0u;
    }
    // X2 init: one 16B row per thread: [s_hi,s_lo | 0,0 | 1,0 | 0,0]
    {
        int grow0 = blockIdx.x * RPC + tid;
        float s0 = S[(size_t)grow0 * SROW];
        uint32_t a = smb + X2_OFF + (uint32_t)tid * 16;
        STS128U(a, split_pack(s0), 0u, 0x00003C00u, 0u);
    }
    __syncthreads();

    const int warp = tid >> 5, lane = tid & 31;
    const int c = lane & 3, rq = lane >> 2;   // column-lane, row-quad
    const uint32_t xB  = smb + X_OFF + warp * 2560;    // [32][40] fp16
    const uint32_t x2B = smb + X2_OFF + warp * 512;    // [32][16B]
    const int gbase = blockIdx.x * RPC + warp * RPW;
    const float b2v = w2f[32];
    const uint32_t H05 = 0x38003800u;   // half2(0.5, 0.5)

    // hoist chunk-2 B fragments (loop-invariant): 20 regs
    uint32_t b2r[20];
    #pragma unroll
    for (int g = 0; g < 5; g++) {
        uint32_t tmp[4];
        ldsm4(tmp, smb + W2C_OFF + (uint32_t)g * 512
                   + (uint32_t)(lane >> 3) * 128 + (uint32_t)(lane & 7) * 16);
        #pragma unroll
        for (int j = 0; j < 4; j++) b2r[4 * g + j] = tmp[j];
    }

    const uint32_t aOff  = (uint32_t)((lane & 15) * 80 + (lane >> 4) * 16);
    const uint32_t a2Off = (uint32_t)((lane & 15) * 16);
    const uint32_t bOff4 = (uint32_t)((lane & 7) * 80 + (lane >> 3) * 16);
    const uint32_t whiB = smb + WHI_OFF;

    #pragma unroll 1
    for (int t = 0; t < STEPS; t++) {
        __syncwarp();
        // A fragments: h (2 kc) + chunk2 (k8), per rowblock
        uint32_t A[2][2][4], A2[2][2];
        #pragma unroll
        for (int rb = 0; rb < 2; rb++) {
            #pragma unroll
            for (int kc = 0; kc < 2; kc++)
                ldsm4(A[rb][kc], xB + rb * 1280 + kc * 32 + aOff);
            ldsm2(A2[rb], x2B + rb * 256 + a2Off);
        }

        float acc[4] = {0.0f, 0.0f, 0.0f, 0.0f};  // delta partials, 4 rows/lane

        #pragma unroll
        for (int q = 0; q < 4; q++) {
            float    Cm[2][4];        // mlp tile, fp32 accum
            uint32_t Cg[4][2][2];     // gate tiles r,z,i_n,h_n: packed fp16

            // ---- mlp tile (ti=0): fp32 path ----
            {
                uint32_t bb[4];
                ldsm4(bb, whiB + (uint32_t)(q * 640) + bOff4);
                #pragma unroll
                for (int rb = 0; rb < 2; rb++) {
                    mma_zero(Cm[rb], A[rb][0], bb);
                    mma_acc (Cm[rb], A[rb][1], bb + 2);
                    mma_k8  (Cm[rb], A2[rb], b2r[q]);
                }
            }
            // ---- gate tiles (ti=1..4): fp16-accum path ----
            #pragma unroll
            for (int gi = 0; gi < 4; gi++) {
                const int tile = q + 4 * (gi + 1);
                uint32_t bb[4];
                ldsm4(bb, whiB + (uint32_t)(tile * 640) + bOff4);
                #pragma unroll
                for (int rb = 0; rb < 2; rb++) {
                    mma_h_zero(Cg[gi][rb], A[rb][0], bb);
                    mma_h_acc (Cg[gi][rb], A[rb][1], bb + 2);
                    mma_h_k8  (Cg[gi][rb], A2[rb], b2r[tile]);
                }
            }

            const float w2a = w2f[8 * q + 2 * c];
            const float w2b = w2f[8 * q + 2 * c + 1];

            // ---- epilogue: delta partial (fp32) + packed-fp16 gates ----
            #pragma unroll
            for (int rb = 0; rb < 2; rb++) {
                #pragma unroll
                for (int hf = 0; hf < 2; hf++) {
                    float m0 = Cm[rb][hf * 2], m1 = Cm[rb][hf * 2 + 1];
                    acc[rb * 2 + hf] = fmaf(fmaxf(m0, 0.0f), w2a,
                                       fmaf(fmaxf(m1, 0.0f), w2b,
                                            acc[rb * 2 + hf]));
                    // gates come out of the mma already packed half2
                    uint32_t rs = hfma2u(tanh2(Cg[0][rb][hf]), H05, H05);
                    uint32_t zs = hfma2u(tanh2(Cg[1][rb][hf]), H05, H05);
                    uint32_t nt = tanh2(hfma2u(rs, Cg[3][rb][hf], Cg[2][rb][hf]));
                    uint32_t ra = (uint32_t)((rb * 16 + rq + hf * 8) * 80
                                             + q * 16 + c * 4);
                    uint32_t hold; LDS32(hold, xB + ra);
                    // h' = n + z*(h_old - n)
                    uint32_t hnew = hfma2u(zs, hsub2u(hold, nt), nt);
                    STS32(xB + ra, hnew);
                }
            }
        }

        // delta: reduce over the 4-lane column group
        #pragma unroll
        for (int i = 0; i < 4; i++) {
            acc[i] += __shfl_xor_sync(0xffffffffu, acc[i], 1);
            acc[i] += __shfl_xor_sync(0xffffffffu, acc[i], 2);
            acc[i] += b2v;
        }

        if (c == 0) {
            #pragma unroll
            for (int rb = 0; rb < 2; rb++) {
                #pragma unroll
                for (int hf = 0; hf < 2; hf++) {
                    int r = rb * 16 + rq + hf * 8;
                    int grow = gbase + r;
                    float dl = acc[rb * 2 + hf];
                    out[(size_t)grow * STEPS + t] = dl;
                    float sn = S[(size_t)grow * SROW + t + 1];   // t+1 <= 30, valid
                    STS64U(x2B + (uint32_t)r * 16, split_pack(sn), split_pack(dl));
                }
            }
        }
    }
}

extern "C" void kernel_launch(void* const* d_in, const int* in_sizes, int n_in,
                              void* d_out, int out_size)
{
    (void)in_sizes; (void)n_in; (void)out_size;
    const float* S   = (const float*)d_in[0];
    const float* W1  = (const float*)d_in[1];
    const float* b1  = (const float*)d_in[2];
    const float* W2  = (const float*)d_in[3];
    const float* b2  = (const float*)d_in[4];
    const float* Wih = (const float*)d_in[5];
    const float* bih = (const float*)d_in[6];
    const float* Whh = (const float*)d_in[7];
    const float* bhh = (const float*)d_in[8];
    float* out = (float*)d_out;

    cudaFuncSetAttribute(hedge_mma,
                         cudaFuncAttributeMaxDynamicSharedMemorySize, SMEM_TOTAL);

    dim3 grid(BTOTAL / RPC);   // 8192 CTAs, 128 rows each
    hedge_mma<<<grid, TPB, SMEM_TOTAL>>>(S, W1, b1, W2, b2, Wih, bih, Whh, bhh, out);
}

// round 17
// speedup vs baseline: 13.7823x; 1.0169x over previous
#include <cuda_runtime.h>
#include <cuda_fp16.h>
#include <cstdint>

// RecurrentHedgeModel via mma.sync HMMA (family-common path).
// Round 17: the 40 k8 rank-3 mmas were 33% of the tensor floor doing 5 useful
// K-slots — evicted to a packed-half2 scalar accumulator INIT (C = s*ws + d*wd
// + b via hfma2, coefs from a 16B-entry SMEM LUT = 1 wavefront/load). Gate
// tiles: init + 2 accumulate-into k16 mma. mlp tile keeps fp32 init/accum.
// Tensor busor 0.79 -> 0.53 ms; X2 tile and ldsm2s removed.
// W rows: 0-31 W1 | 32-95 folded r,z x0.5 | 96-127 Wih_n | 128-159 Whh_n

#define STEPS  30
#define SROW   31
#define BTOTAL 1048576
#define TPB    128
#define RPW    32          // rows per warp
#define RPC    128         // rows per CTA (4 warps x 32)

// ---- smem map (bytes) ----
#define WHI_OFF  0             // [160][40] fp16, pitch 80B (K=32 h-cols)
#define GLUT_OFF 12800         // [20 tiles][4 c] x 16B {ws2, wd2, b2, pad}
#define CSTM_OFF 14080         // [32] float4 {ws, wd, b, 0} (mlp cols)
#define W2F_OFF  14592         // 33 floats
#define SD_OFF   14848         // 4 warps x [32] float2 {s_t, delta_{t-1}}
#define X_OFF    15872         // 4 warps x 2560 (fp16 h tile, pitch 80B)
#define SMEM_TOTAL (15872 + 4 * 2560)

static __device__ __forceinline__ uint32_t smem_u32(const void* p) {
    uint32_t a;
    asm("{ .reg .u64 t; cvta.to.shared.u64 t, %1; cvt.u32.u64 %0, t; }"
        : "=r"(a) : "l"(p));
    return a;
}
#define STS32(addr, v) \
    asm volatile("st.shared.b32 [%0], %1;" :: "r"(addr), "r"(v) : "memory")
#define LDS32(v, addr) \
    asm volatile("ld.shared.b32 %0, [%1];" : "=r"(v) : "r"(addr))
#define LDS128F(f4, addr) \
    asm volatile("ld.shared.v4.f32 {%0,%1,%2,%3}, [%4];" \
                 : "=f"((f4).x), "=f"((f4).y), "=f"((f4).z), "=f"((f4).w) \
                 : "r"(addr))
#define LDS128U(r0, r1, r2, r3, addr) \
    asm volatile("ld.shared.v4.b32 {%0,%1,%2,%3}, [%4];" \
                 : "=r"(r0), "=r"(r1), "=r"(r2), "=r"(r3) : "r"(addr))
#define LDS64F(f2, addr) \
    asm volatile("ld.shared.v2.f32 {%0,%1}, [%2];" \
                 : "=f"((f2).x), "=f"((f2).y) : "r"(addr))
#define STS64F(addr, a, b) \
    asm volatile("st.shared.v2.f32 [%0], {%1, %2};" \
                 :: "r"(addr), "f"(a), "f"(b) : "memory")
#define STS128U(addr, r0, r1, r2, r3) \
    asm volatile("st.shared.v4.b32 [%0], {%1, %2, %3, %4};" \
                 :: "r"(addr), "r"(r0), "r"(r1), "r"(r2), "r"(r3) : "memory")

static __device__ __forceinline__ void ldsm4(uint32_t* r, uint32_t a) {
    asm volatile("ldmatrix.sync.aligned.m8n8.x4.shared.b16 {%0,%1,%2,%3}, [%4];"
                 : "=r"(r[0]), "=r"(r[1]), "=r"(r[2]), "=r"(r[3]) : "r"(a));
}
// ---- fp32-accum mma (mlp/delta tile) ----
static __device__ __forceinline__ void mma_acc(float* d, const uint32_t* a,
                                               const uint32_t* b) {
    asm volatile("mma.sync.aligned.m16n8k16.row.col.f32.f16.f16.f32 "
                 "{%0,%1,%2,%3}, {%4,%5,%6,%7}, {%8,%9}, {%0,%1,%2,%3};"
                 : "+f"(d[0]), "+f"(d[1]), "+f"(d[2]), "+f"(d[3])
                 : "r"(a[0]), "r"(a[1]), "r"(a[2]), "r"(a[3]),
                   "r"(b[0]), "r"(b[1]));
}
// ---- fp16-accum mma (gate tiles), accumulate-into ----
static __device__ __forceinline__ void mma_h_acc(uint32_t* d, const uint32_t* a,
                                                 const uint32_t* b) {
    asm volatile("mma.sync.aligned.m16n8k16.row.col.f16.f16.f16.f16 "
                 "{%0,%1}, {%2,%3,%4,%5}, {%6,%7}, {%0,%1};"
                 : "+r"(d[0]), "+r"(d[1])
                 : "r"(a[0]), "r"(a[1]), "r"(a[2]), "r"(a[3]),
                   "r"(b[0]), "r"(b[1]));
}

// ---- packed fp16 helpers ----
static __device__ __forceinline__ uint32_t tanh2(uint32_t x) {
    uint32_t y; asm("tanh.approx.f16x2 %0, %1;" : "=r"(y) : "r"(x)); return y;
}
static __device__ __forceinline__ uint32_t hfma2u(uint32_t a, uint32_t b, uint32_t c) {
    uint32_t d; asm("fma.rn.f16x2 %0, %1, %2, %3;" : "=r"(d) : "r"(a), "r"(b), "r"(c)); return d;
}
static __device__ __forceinline__ uint32_t hsub2u(uint32_t a, uint32_t b) {
    uint32_t d; asm("sub.rn.f16x2 %0, %1, %2;" : "=r"(d) : "r"(a), "r"(b)); return d;
}
// packed fp16x2: lower16 = f16(x0), upper16 = f16(x1)
static __device__ __forceinline__ uint32_t cvt2h(float x1, float x0) {
    uint32_t r;
    asm("cvt.rn.f16x2.f32 %0, %1, %2;" : "=r"(r) : "f"(x1), "f"(x0));
    return r;
}

// per-column rank-3 coefficients {ws, wd, b}
static __device__ __forceinline__ void col_coef(int n,
    const float* W1, const float* b1, const float* Wih,
    const float* bih, const float* bhh, float& ws, float& wd, float& bb)
{
    ws = 0.0f; wd = 0.0f;
    if (n < 32)       { ws = W1[n * 34];  wd = W1[n * 34 + 1];  bb = b1[n]; }
    else if (n < 96)  { int g = n - 32; ws = Wih[g * 34]; wd = Wih[g * 34 + 1];
                        bb = bih[g] + bhh[g]; }
    else if (n < 128) { int g = n - 32; ws = Wih[g * 34]; wd = Wih[g * 34 + 1];
                        bb = bih[g]; }
    else              bb = bhh[64 + (n - 128)];
}

__global__ __launch_bounds__(TPB, 4)
void hedge_mma(const float* __restrict__ S,
               const float* __restrict__ W1,  const float* __restrict__ b1,
               const float* __restrict__ W2,  const float* __restrict__ b2,
               const float* __restrict__ Wih, const float* __restrict__ bih,
               const float* __restrict__ Whh, const float* __restrict__ bhh,
               float* __restrict__ out)
{
    extern __shared__ __align__(128) unsigned char sm[];
    const int tid = threadIdx.x;
    const uint32_t smb = smem_u32(sm);
    __half* Whi = (__half*)(sm + WHI_OFF);   // [160][40]
    float4* cstm = (float4*)(sm + CSTM_OFF); // [32]
    float* w2f = (float*)(sm + W2F_OFF);

    // ---- fused fp16 weight matrix; r/z rows (32..95) pre-scaled by 0.5 ----
    for (int i = tid; i < 160 * 32; i += TPB) {
        int n = i >> 5, k = i & 31;
        float w;
        if (n < 32)       w = W1[n * 34 + 2 + k];
        else if (n < 96)  { int g = n - 32;
                            w = 0.5f * (Wih[g * 34 + 2 + k] + Whh[g * 32 + k]); }
        else if (n < 128) { int g = n - 32; w = Wih[g * 34 + 2 + k]; }
        else              w = Whh[(64 + (n - 128)) * 32 + k];
        Whi[n * 40 + k] = __float2half_rn(w);
    }
    // ---- gate rank-3 LUT: [tile][c] = {half2 ws, half2 wd, half2 b, pad} ----
    for (int i = tid; i < 20 * 4; i += TPB) {
        int tt = i >> 2, c = i & 3;
        int n0 = tt * 8 + 2 * c;
        float ws0, wd0, b0, ws1, wd1, b1c;
        col_coef(n0,     W1, b1, Wih, bih, bhh, ws0, wd0, b0);
        col_coef(n0 + 1, W1, b1, Wih, bih, bhh, ws1, wd1, b1c);
        float sc = (tt >= 4 && tt < 12) ? 0.5f : 1.0f;   // r,z tiles pre-scaled
        STS128U(smb + GLUT_OFF + (uint32_t)i * 16,
                cvt2h(ws1 * sc, ws0 * sc),
                cvt2h(wd1 * sc, wd0 * sc),
                cvt2h(b1c * sc, b0 * sc), 0u);
    }
    // ---- mlp rank-3 LUT (fp32, cols 0..31) ----
    for (int n = tid; n < 32; n += TPB) {
        float ws, wd, bb;
        col_coef(n, W1, b1, Wih, bih, bhh, ws, wd, bb);
        cstm[n] = make_float4(ws, wd, bb, 0.0f);
    }
    if (tid < 32) w2f[tid] = W2[tid];
    if (tid == 0) w2f[32] = b2[0];
    // zero X tiles
    {
        uint32_t* xz = (uint32_t*)(sm + X_OFF);
        for (int i = tid; i < (4 * 2560) / 4; i += TPB) xz[i] = 0u;
    }
    // sd init: (s_0, delta=0) per row
    {
        int grow0 = blockIdx.x * RPC + tid;
        int w_ = tid >> 5, r_ = tid & 31;
        STS64F(smb + SD_OFF + (uint32_t)(w_ * 256 + r_ * 8),
               S[(size_t)grow0 * SROW], 0.0f);
    }
    __syncthreads();

    const int warp = tid >> 5, lane = tid & 31;
    const int c = lane & 3, rq = lane >> 2;   // column-lane, row-quad
    const uint32_t xB  = smb + X_OFF + warp * 2560;    // [32][40] fp16
    const uint32_t sdB = smb + SD_OFF + warp * 256;    // [32] float2
    const int gbase = blockIdx.x * RPC + warp * RPW;
    const float b2v = w2f[32];
    const uint32_t H05 = 0x38003800u;   // half2(0.5, 0.5)

    const uint32_t aOff  = (uint32_t)((lane & 15) * 80 + (lane >> 4) * 16);
    const uint32_t bOff4 = (uint32_t)((lane & 7) * 80 + (lane >> 3) * 16);
    const uint32_t whiB = smb + WHI_OFF;
    const uint32_t glutC = smb + GLUT_OFF + (uint32_t)c * 16;

    #pragma unroll 1
    for (int t = 0; t < STEPS; t++) {
        __syncwarp();
        // (s_t, delta_{t-1}) for my 4 row-positions + half2 broadcasts
        float2 sdv[4];
        uint32_t ss2[4], dd2[4];
        #pragma unroll
        for (int rb = 0; rb < 2; rb++)
            #pragma unroll
            for (int hf = 0; hf < 2; hf++) {
                int i = rb * 2 + hf;
                LDS64F(sdv[i], sdB + (uint32_t)(rb * 16 + rq + hf * 8) * 8);
                ss2[i] = cvt2h(sdv[i].x, sdv[i].x);
                dd2[i] = cvt2h(sdv[i].y, sdv[i].y);
            }

        // A fragments: h tile, 2 rowblocks x 2 K-chunks
        uint32_t A[2][2][4];
        #pragma unroll
        for (int rb = 0; rb < 2; rb++)
            #pragma unroll
            for (int kc = 0; kc < 2; kc++)
                ldsm4(A[rb][kc], xB + rb * 1280 + kc * 32 + aOff);

        float acc[4] = {0.0f, 0.0f, 0.0f, 0.0f};  // delta partials, 4 rows/lane

        #pragma unroll
        for (int q = 0; q < 4; q++) {
            float    Cm[2][4];        // mlp tile, fp32
            uint32_t Cg[4][2][2];     // gate tiles r,z,i_n,h_n: packed fp16

            // ---- mlp tile: fp32 rank-3 init + 2 accum mma ----
            {
                float4 f0, f1;
                uint32_t ca = smb + CSTM_OFF + (uint32_t)((8 * q + 2 * c) * 16);
                LDS128F(f0, ca);
                LDS128F(f1, ca + 16);
                #pragma unroll
                for (int rb = 0; rb < 2; rb++)
                    #pragma unroll
                    for (int hf = 0; hf < 2; hf++) {
                        float s_ = sdv[rb * 2 + hf].x, d_ = sdv[rb * 2 + hf].y;
                        Cm[rb][hf * 2]     = fmaf(s_, f0.x, fmaf(d_, f0.y, f0.z));
                        Cm[rb][hf * 2 + 1] = fmaf(s_, f1.x, fmaf(d_, f1.y, f1.z));
                    }
                uint32_t bb[4];
                ldsm4(bb, whiB + (uint32_t)(q * 640) + bOff4);
                #pragma unroll
                for (int rb = 0; rb < 2; rb++) {
                    mma_acc(Cm[rb], A[rb][0], bb);
                    mma_acc(Cm[rb], A[rb][1], bb + 2);
                }
            }
            // ---- gate tiles: half2 rank-3 init + 2 accum mma ----
            #pragma unroll
            for (int gi = 0; gi < 4; gi++) {
                const int tile = q + 4 * (gi + 1);
                uint32_t wsp, wdp, bp, pad;
                LDS128U(wsp, wdp, bp, pad, glutC + (uint32_t)(tile * 64));
                #pragma unroll
                for (int rb = 0; rb < 2; rb++)
                    #pragma unroll
                    for (int hf = 0; hf < 2; hf++)
                        Cg[gi][rb][hf] = hfma2u(ss2[rb * 2 + hf], wsp,
                                          hfma2u(dd2[rb * 2 + hf], wdp, bp));
                uint32_t bb[4];
                ldsm4(bb, whiB + (uint32_t)(tile * 640) + bOff4);
                #pragma unroll
                for (int rb = 0; rb < 2; rb++) {
                    mma_h_acc(Cg[gi][rb], A[rb][0], bb);
                    mma_h_acc(Cg[gi][rb], A[rb][1], bb + 2);
                }
            }

            const float w2a = w2f[8 * q + 2 * c];
            const float w2b = w2f[8 * q + 2 * c + 1];

            // ---- epilogue: delta partial (fp32) + packed-fp16 gates ----
            #pragma unroll
            for (int rb = 0; rb < 2; rb++) {
                #pragma unroll
                for (int hf = 0; hf < 2; hf++) {
                    float m0 = Cm[rb][hf * 2], m1 = Cm[rb][hf * 2 + 1];
                    acc[rb * 2 + hf] = fmaf(fmaxf(m0, 0.0f), w2a,
                                       fmaf(fmaxf(m1, 0.0f), w2b,
                                            acc[rb * 2 + hf]));
                    uint32_t rs = hfma2u(tanh2(Cg[0][rb][hf]), H05, H05);
                    uint32_t zs = hfma2u(tanh2(Cg[1][rb][hf]), H05, H05);
                    uint32_t nt = tanh2(hfma2u(rs, Cg[3][rb][hf], Cg[2][rb][hf]));
                    uint32_t ra = (uint32_t)((rb * 16 + rq + hf * 8) * 80
                                             + q * 16 + c * 4);
                    uint32_t hold; LDS32(hold, xB + ra);
                    // h' = n + z*(h_old - n)
                    uint32_t hnew = hfma2u(zs, hsub2u(hold, nt), nt);
                    STS32(xB + ra, hnew);
                }
            }
        }

        // delta: reduce over the 4-lane column group
        #pragma unroll
        for (int i = 0; i < 4; i++) {
            acc[i] += __shfl_xor_sync(0xffffffffu, acc[i], 1);
            acc[i] += __shfl_xor_sync(0xffffffffu, acc[i], 2);
            acc[i] += b2v;
        }

        if (c == 0) {
            #pragma unroll
            for (int rb = 0; rb < 2; rb++) {
                #pragma unroll
                for (int hf = 0; hf < 2; hf++) {
                    int r = rb * 16 + rq + hf * 8;
                    int grow = gbase + r;
                    float dl = acc[rb * 2 + hf];
                    out[(size_t)grow * STEPS + t] = dl;
                    float sn = S[(size_t)grow * SROW + t + 1];   // t+1 <= 30, valid
                    STS64F(sdB + (uint32_t)r * 8, sn, dl);
                }
            }
        }
    }
}

extern "C" void kernel_launch(void* const* d_in, const int* in_sizes, int n_in,
                              void* d_out, int out_size)
{
    (void)in_sizes; (void)n_in; (void)out_size;
    const float* S   = (const float*)d_in[0];
    const float* W1  = (const float*)d_in[1];
    const float* b1  = (const float*)d_in[2];
    const float* W2  = (const float*)d_in[3];
    const float* b2  = (const float*)d_in[4];
    const float* Wih = (const float*)d_in[5];
    const float* bih = (const float*)d_in[6];
    const float* Whh = (const float*)d_in[7];
    const float* bhh = (const float*)d_in[8];
    float* out = (float*)d_out;

    cudaFuncSetAttribute(hedge_mma,
                         cudaFuncAttributeMaxDynamicSharedMemorySize, SMEM_TOTAL);

    dim3 grid(BTOTAL / RPC);   // 8192 CTAs, 128 rows each
    hedge_mma<<<grid, TPB, SMEM_TOTAL>>>(S, W1, b1, W2, b2, Wih, bih, Whh, bhh, out);
}